// round 5
// baseline (speedup 1.0000x reference)
#include <cuda_runtime.h>
#include <math.h>
#include <stdint.h>

#define WSZ 8
#define NHEAD 4
#define DIM 128
#define NTOK 64
#define HD 32
#define BATCH 32
#define HW 64
#define LSEQ 4096
#define RPE_HID 512
#define APAD 132
#define SBP 67
#define VTP 68
#define HP 68

__device__ float g_bias[NHEAD * NTOK * NTOK];
__device__ float g_ttab[225 * NHEAD];
__device__ float g_ybuf[(size_t)BATCH * LSEQ * DIM];

// ---------------- tf32 MMA helpers ----------------
__device__ __forceinline__ uint32_t f2tf32(float f) {
    uint32_t u;
    asm("cvt.rna.tf32.f32 %0, %1;" : "=r"(u) : "f"(f));
    return u;
}
__device__ __forceinline__ float rtf32(float f) { return __uint_as_float(f2tf32(f)); }

__device__ __forceinline__ void mma_tf32(float* c, const uint32_t* a, uint32_t b0, uint32_t b1) {
    asm volatile(
        "mma.sync.aligned.m16n8k8.row.col.f32.tf32.tf32.f32 "
        "{%0,%1,%2,%3}, {%4,%5,%6,%7}, {%8,%9}, {%0,%1,%2,%3};"
        : "+f"(c[0]), "+f"(c[1]), "+f"(c[2]), "+f"(c[3])
        : "r"(a[0]), "r"(a[1]), "r"(a[2]), "r"(a[3]), "r"(b0), "r"(b1));
}

template<int MT, int NT, int KS>
__device__ __forceinline__ void wgemm(const float* __restrict__ Asm, int lda, int aoff,
                                      const float* __restrict__ Bsm, int ldb, int boff,
                                      float (&acc)[MT][NT][4], int rbase, int nbase,
                                      int g, int i)
{
    #pragma unroll
    for (int ks = 0; ks < KS; ks++) {
        int kc = i + ks * 8;
        uint32_t a[MT][4];
        #pragma unroll
        for (int m = 0; m < MT; m++) {
            int r0 = rbase + m * 16 + g;
            a[m][0] = __float_as_uint(Asm[r0 * lda + aoff + kc]);
            a[m][1] = __float_as_uint(Asm[(r0 + 8) * lda + aoff + kc]);
            a[m][2] = __float_as_uint(Asm[r0 * lda + aoff + kc + 4]);
            a[m][3] = __float_as_uint(Asm[(r0 + 8) * lda + aoff + kc + 4]);
        }
        #pragma unroll
        for (int n = 0; n < NT; n++) {
            int nc = nbase + n * 8 + g;
            uint32_t b0 = __float_as_uint(Bsm[nc * ldb + boff + kc]);
            uint32_t b1 = __float_as_uint(Bsm[nc * ldb + boff + kc + 4]);
            #pragma unroll
            for (int m = 0; m < MT; m++) mma_tf32(acc[m][n], a[m], b0, b1);
        }
    }
}

// ---------------- RPE bias ----------------
__global__ void bias_table_kernel(const float* __restrict__ w1, const float* __restrict__ b1,
                                  const float* __restrict__ w2) {
    __shared__ float4 red[128];
    int p = blockIdx.x;
    int tid = threadIdx.x;
    int i = p / 15, j = p % 15;
    float v0 = (float)(i - 7) / 7.0f * 8.0f;
    float v1 = (float)(j - 7) / 7.0f * 8.0f;
    float inv_l8 = 1.0f / log2f(8.0f);
    float s0 = (v0 > 0.f) ? 1.f : ((v0 < 0.f) ? -1.f : 0.f);
    float s1 = (v1 > 0.f) ? 1.f : ((v1 < 0.f) ? -1.f : 0.f);
    float x0 = s0 * log2f(fabsf(v0) + 1.0f) * inv_l8;
    float x1 = s1 * log2f(fabsf(v1) + 1.0f) * inv_l8;
    float a0 = 0.f, a1 = 0.f, a2 = 0.f, a3 = 0.f;
    #pragma unroll
    for (int r = 0; r < 4; r++) {
        int h = tid + 128 * r;
        float hid = x0 * w1[2 * h] + x1 * w1[2 * h + 1] + b1[h];
        hid = fmaxf(hid, 0.f);
        a0 += hid * w2[0 * RPE_HID + h];
        a1 += hid * w2[1 * RPE_HID + h];
        a2 += hid * w2[2 * RPE_HID + h];
        a3 += hid * w2[3 * RPE_HID + h];
    }
    red[tid] = make_float4(a0, a1, a2, a3);
    __syncthreads();
    for (int s = 64; s > 0; s >>= 1) {
        if (tid < s) {
            float4 o = red[tid + s];
            red[tid].x += o.x; red[tid].y += o.y; red[tid].z += o.z; red[tid].w += o.w;
        }
        __syncthreads();
    }
    if (tid == 0) {
        g_ttab[p * 4 + 0] = red[0].x; g_ttab[p * 4 + 1] = red[0].y;
        g_ttab[p * 4 + 2] = red[0].z; g_ttab[p * 4 + 3] = red[0].w;
    }
}

__global__ void bias_scatter_kernel() {
    int e = blockIdx.x * 256 + threadIdx.x;
    int h = e >> 12;
    int rem = e & 4095;
    int i = rem >> 6, j = rem & 63;
    int yi = i >> 3, xi = i & 7, yj = j >> 3, xj = j & 7;
    int idx = (yi - yj + 7) * 15 + (xi - xj + 7);
    g_bias[e] = g_ttab[idx * 4 + h];
}

// ---------------- Kernel 2: attention + LN1 + residual (tf32, 512 threads) ----------------
// smem floats:
//  xw @0 [64][132]; sb4 overlay @0 (4*64*67=17152); wb @8448 [128][132];
//  qb/ow @25344 [64][132]; kb @33792 [64][132]; vt @42240 [128][68];
//  rsum4 @50944 [256]; p512 @51200 [512]; psum @51712 [512]; regid/mu/rstd after.
__global__ __launch_bounds__(512) void attn_kernel(
    const float* __restrict__ x, const float* __restrict__ qkv_w, const float* __restrict__ qkv_b,
    const float* __restrict__ proj_w, const float* __restrict__ proj_b,
    const float* __restrict__ n1w, const float* __restrict__ n1b)
{
    extern __shared__ float sm[];
    float* xw = sm;
    float* sb4 = sm;
    float* wb = sm + 8448;
    float* qb = sm + 25344;
    float* ow = qb;
    float* kb = sm + 33792;
    float* vt = sm + 42240;
    float* rsum4 = sm + 50944;
    float* p512 = sm + 51200;
    float* psum = sm + 51712;
    int* regid = (int*)(sm + 52224);
    float* mu = sm + 52288;
    float* rstd = sm + 52352;

    int tid = threadIdx.x;
    int wid = tid >> 5;
    int lane = tid & 31;
    int g = lane >> 2;
    int i = lane & 3;

    int bx = blockIdx.x;
    int bimg = bx >> 6;
    int wh = (bx >> 3) & 7, ww = bx & 7;
    const float* xbase = x + (size_t)bimg * (LSEQ * DIM);

    // window load (rolled -4), tf32-rounded
    #pragma unroll
    for (int it = 0; it < 4; it++) {
        int e4 = tid + 512 * it;
        int t = e4 >> 5;
        int c = (e4 & 31) << 2;
        int ti = t >> 3, tj = t & 7;
        int hh = (wh * 8 + ti + 4) & 63;
        int wwp = (ww * 8 + tj + 4) & 63;
        float4 v = *(const float4*)(xbase + (size_t)((hh << 6) + wwp) * DIM + c);
        float* d = xw + t * APAD + c;
        d[0] = rtf32(v.x); d[1] = rtf32(v.y); d[2] = rtf32(v.z); d[3] = rtf32(v.w);
    }
    if (tid < 64) {
        int ti = tid >> 3, tj = tid & 7;
        int ah = wh * 8 + ti, aw = ww * 8 + tj;
        int rh = ah < 56 ? 0 : (ah < 60 ? 1 : 2);
        int rw = aw < 56 ? 0 : (aw < 60 ? 1 : 2);
        regid[tid] = rh * 3 + rw;
    }

    const float scale = 0.17677669529663687f;

    // ---- QKV: 3 GEMMs 64x128x128, 16 warps as 2(M)x8(N) ----
    for (int cidx = 0; cidx < 3; cidx++) {
        const float* wsrc = qkv_w + cidx * DIM * DIM;
        #pragma unroll
        for (int it = 0; it < 8; it++) {
            int e4 = tid + 512 * it;
            int r = e4 >> 5;
            int c = (e4 & 31) << 2;
            float4 v = *(const float4*)(wsrc + r * DIM + c);
            float* d = wb + r * APAD + c;
            d[0] = rtf32(v.x); d[1] = rtf32(v.y); d[2] = rtf32(v.z); d[3] = rtf32(v.w);
        }
        __syncthreads();

        float acc[2][2][4];
        #pragma unroll
        for (int m = 0; m < 2; m++)
            #pragma unroll
            for (int n = 0; n < 2; n++)
                #pragma unroll
                for (int q = 0; q < 4; q++) acc[m][n][q] = 0.f;
        int rbase = (wid >> 3) * 32;
        int nbase = (wid & 7) * 16;
        wgemm<2, 2, 16>(xw, APAD, 0, wb, APAD, 0, acc, rbase, nbase, g, i);

        #pragma unroll
        for (int n = 0; n < 2; n++) {
            int col = nbase + n * 8 + 2 * i;
            float b0f = qkv_b[cidx * DIM + col];
            float b1f = qkv_b[cidx * DIM + col + 1];
            #pragma unroll
            for (int m = 0; m < 2; m++) {
                int row = rbase + m * 16 + g;
                float v0 = acc[m][n][0] + b0f;
                float v1 = acc[m][n][1] + b1f;
                float v2 = acc[m][n][2] + b0f;
                float v3 = acc[m][n][3] + b1f;
                if (cidx == 0) {
                    qb[row * APAD + col]           = rtf32(v0 * scale);
                    qb[row * APAD + col + 1]       = rtf32(v1 * scale);
                    qb[(row + 8) * APAD + col]     = rtf32(v2 * scale);
                    qb[(row + 8) * APAD + col + 1] = rtf32(v3 * scale);
                } else if (cidx == 1) {
                    kb[row * APAD + col]           = rtf32(v0);
                    kb[row * APAD + col + 1]       = rtf32(v1);
                    kb[(row + 8) * APAD + col]     = rtf32(v2);
                    kb[(row + 8) * APAD + col + 1] = rtf32(v3);
                } else {
                    vt[col * VTP + row]           = rtf32(v0);
                    vt[(col + 1) * VTP + row]     = rtf32(v1);
                    vt[col * VTP + row + 8]       = rtf32(v2);
                    vt[(col + 1) * VTP + row + 8] = rtf32(v3);
                }
            }
        }
        __syncthreads();
    }

    // ---- scores: 4 heads x 4 warps/head; warp does 16 rows x 64 cols, k=32 ----
    {
        int h = wid >> 2;
        int hoff = h * HD;
        int rbase = (wid & 3) * 16;
        float acc[1][8][4];
        #pragma unroll
        for (int n = 0; n < 8; n++)
            #pragma unroll
            for (int q = 0; q < 4; q++) acc[0][n][q] = 0.f;
        wgemm<1, 8, 4>(qb, APAD, hoff, kb, APAD, hoff, acc, rbase, 0, g, i);

        float* sbh = sb4 + h * (64 * SBP);
        const float* gb = g_bias + h * 4096;
        int row0 = rbase + g;
        int r0 = regid[row0];
        int r1 = regid[row0 + 8];
        #pragma unroll
        for (int n = 0; n < 8; n++) {
            int col = n * 8 + 2 * i;
            int c0 = regid[col], c1 = regid[col + 1];
            float m00 = (r0 != c0) ? -100.f : 0.f;
            float m01 = (r0 != c1) ? -100.f : 0.f;
            float m10 = (r1 != c0) ? -100.f : 0.f;
            float m11 = (r1 != c1) ? -100.f : 0.f;
            sbh[row0 * SBP + col]           = acc[0][n][0] + gb[row0 * 64 + col] + m00;
            sbh[row0 * SBP + col + 1]       = acc[0][n][1] + gb[row0 * 64 + col + 1] + m01;
            sbh[(row0 + 8) * SBP + col]     = acc[0][n][2] + gb[(row0 + 8) * 64 + col] + m10;
            sbh[(row0 + 8) * SBP + col + 1] = acc[0][n][3] + gb[(row0 + 8) * 64 + col + 1] + m11;
        }
    }
    __syncthreads();

    // ---- softmax: 2 threads per (head,row) ----
    {
        int row = tid >> 1;
        int half = tid & 1;
        float* rowp = sb4 + (row >> 6) * (64 * SBP) + (row & 63) * SBP + half * 32;
        float mx = -1e30f;
        #pragma unroll 8
        for (int j = 0; j < 32; j++) mx = fmaxf(mx, rowp[j]);
        p512[tid] = mx;
        __syncthreads();
        float M = fmaxf(p512[tid], p512[tid ^ 1]);
        float s = 0.f;
        #pragma unroll 8
        for (int j = 0; j < 32; j++) {
            float e = __expf(rowp[j] - M);
            s += e;
            rowp[j] = rtf32(e);
        }
        psum[tid] = s;
        __syncthreads();
        if (tid < 256) rsum4[tid] = 1.0f / (psum[2 * tid] + psum[2 * tid + 1]);
    }
    __syncthreads();

    // ---- PV: 4 heads x 4 warps; warp 16 rows x 32 cols, k=64 ----
    {
        int h = wid >> 2;
        int hoff = h * HD;
        int rbase = (wid & 3) * 16;
        float acc[1][4][4];
        #pragma unroll
        for (int n = 0; n < 4; n++)
            #pragma unroll
            for (int q = 0; q < 4; q++) acc[0][n][q] = 0.f;
        wgemm<1, 4, 8>(sb4 + h * (64 * SBP), SBP, 0, vt, VTP, 0, acc, rbase, hoff, g, i);

        int row = rbase + g;
        float rs0 = rsum4[h * 64 + row];
        float rs1 = rsum4[h * 64 + row + 8];
        #pragma unroll
        for (int n = 0; n < 4; n++) {
            int col = hoff + n * 8 + 2 * i;
            ow[row * APAD + col]           = rtf32(acc[0][n][0] * rs0);
            ow[row * APAD + col + 1]       = rtf32(acc[0][n][1] * rs0);
            ow[(row + 8) * APAD + col]     = rtf32(acc[0][n][2] * rs1);
            ow[(row + 8) * APAD + col + 1] = rtf32(acc[0][n][3] * rs1);
        }
    }
    __syncthreads();

    // ---- stage proj_w ----
    #pragma unroll
    for (int it = 0; it < 8; it++) {
        int e4 = tid + 512 * it;
        int r = e4 >> 5;
        int c = (e4 & 31) << 2;
        float4 v = *(const float4*)(proj_w + r * DIM + c);
        float* d = wb + r * APAD + c;
        d[0] = rtf32(v.x); d[1] = rtf32(v.y); d[2] = rtf32(v.z); d[3] = rtf32(v.w);
    }
    __syncthreads();

    // ---- proj GEMM 64x128x128 -> kb (fp32) ----
    {
        float acc[2][2][4];
        #pragma unroll
        for (int m = 0; m < 2; m++)
            #pragma unroll
            for (int n = 0; n < 2; n++)
                #pragma unroll
                for (int q = 0; q < 4; q++) acc[m][n][q] = 0.f;
        int rbase = (wid >> 3) * 32;
        int nbase = (wid & 7) * 16;
        wgemm<2, 2, 16>(ow, APAD, 0, wb, APAD, 0, acc, rbase, nbase, g, i);
        #pragma unroll
        for (int n = 0; n < 2; n++) {
            int col = nbase + n * 8 + 2 * i;
            float b0f = proj_b[col];
            float b1f = proj_b[col + 1];
            #pragma unroll
            for (int m = 0; m < 2; m++) {
                int row = rbase + m * 16 + g;
                kb[row * APAD + col]           = acc[m][n][0] + b0f;
                kb[row * APAD + col + 1]       = acc[m][n][1] + b1f;
                kb[(row + 8) * APAD + col]     = acc[m][n][2] + b0f;
                kb[(row + 8) * APAD + col + 1] = acc[m][n][3] + b1f;
            }
        }
    }
    __syncthreads();

    // ---- LN1 stats: 8 threads/row ----
    {
        int row = tid >> 3;
        int cb = (tid & 7) * 16;
        float s = 0.f;
        #pragma unroll 8
        for (int c = 0; c < 16; c++) s += kb[row * APAD + cb + c];
        p512[tid] = s;
    }
    __syncthreads();
    if (tid < 64) {
        float s = 0.f;
        #pragma unroll
        for (int q = 0; q < 8; q++) s += p512[8 * tid + q];
        mu[tid] = s * (1.0f / DIM);
    }
    __syncthreads();
    {
        int row = tid >> 3;
        int cb = (tid & 7) * 16;
        float m = mu[row];
        float v = 0.f;
        #pragma unroll 8
        for (int c = 0; c < 16; c++) {
            float d = kb[row * APAD + cb + c] - m;
            v += d * d;
        }
        p512[tid] = v;
    }
    __syncthreads();
    if (tid < 64) {
        float v = 0.f;
        #pragma unroll
        for (int q = 0; q < 8; q++) v += p512[8 * tid + q];
        rstd[tid] = rsqrtf(v * (1.0f / DIM) + 1e-5f);
    }
    __syncthreads();

    // ---- y = x + LN(proj) ----
    float* yb = g_ybuf + (size_t)bimg * (LSEQ * DIM);
    #pragma unroll
    for (int it = 0; it < 4; it++) {
        int e4 = tid + 512 * it;
        int t = e4 >> 5;
        int c = (e4 & 31) << 2;
        int ti = t >> 3, tj = t & 7;
        int hh = (wh * 8 + ti + 4) & 63;
        int wwp = (ww * 8 + tj + 4) & 63;
        size_t goff = (size_t)((hh << 6) + wwp) * DIM + c;
        float4 xv = *(const float4*)(xbase + goff);
        float m = mu[t], r = rstd[t];
        float4 o;
        o.x = xv.x + (kb[t * APAD + c + 0] - m) * r * n1w[c + 0] + n1b[c + 0];
        o.y = xv.y + (kb[t * APAD + c + 1] - m) * r * n1w[c + 1] + n1b[c + 1];
        o.z = xv.z + (kb[t * APAD + c + 2] - m) * r * n1w[c + 2] + n1b[c + 2];
        o.w = xv.w + (kb[t * APAD + c + 3] - m) * r * n1w[c + 3] + n1b[c + 3];
        *(float4*)(yb + goff) = o;
    }
}

// ---------------- Kernel 3: MLP + LN2 + residual (64 tok/CTA, 2 CTAs/SM) ----------------
// smem: Ysm [64][132] (rounded; h2 at end) | Wsm [max 128*68=8704] | Hsm [64][68] | p256, mu, rstd
__global__ __launch_bounds__(256, 2) void mlp_kernel(
    const float* __restrict__ fc1w, const float* __restrict__ fc1b,
    const float* __restrict__ fc2w, const float* __restrict__ fc2b,
    const float* __restrict__ n2w, const float* __restrict__ n2b,
    float* __restrict__ out)
{
    extern __shared__ float sm[];
    float* Ysm = sm;                      // 8448
    float* Wsm = Ysm + 64 * APAD;         // 8704
    float* Hsm = Wsm + 8704;              // 4352
    float* ps  = Hsm + 64 * HP;           // 256
    float* muv = ps + 256;                // 64
    float* rsv = muv + 64;                // 64

    int tid = threadIdx.x;
    int wid = tid >> 5;
    int lane = tid & 31;
    int g = lane >> 2;
    int i = lane & 3;
    int rbase = (wid >> 2) * 32;          // {0,32}
    int nbase1 = (wid & 3) * 16;          // GEMM1 N (hidden)
    int nbase2 = (wid & 3) * 32;          // GEMM2 N (out dims)

    size_t tok0 = (size_t)blockIdx.x * 64;
    const float* ysrc = g_ybuf + tok0 * DIM;

    // load Y (tf32-rounded; residual re-read from gmem at the end)
    #pragma unroll
    for (int it = 0; it < 8; it++) {
        int e4 = tid + 256 * it;
        int t = e4 >> 5;
        int c = (e4 & 31) << 2;
        float4 v = *(const float4*)(ysrc + (size_t)t * DIM + c);
        float* d = Ysm + t * APAD + c;
        d[0] = rtf32(v.x); d[1] = rtf32(v.y); d[2] = rtf32(v.z); d[3] = rtf32(v.w);
    }

    float acc2[2][4][4];
    #pragma unroll
    for (int m = 0; m < 2; m++)
        #pragma unroll
        for (int n = 0; n < 4; n++)
            #pragma unroll
            for (int q = 0; q < 4; q++) acc2[m][n][q] = 0.f;

    const float is2 = 0.70710678118654752f;

    for (int hc = 0; hc < 8; hc++) {
        __syncthreads();
        // stage fc1 chunk: rows [hc*64, +64) x 128 -> Wsm [64][APAD]
        const float* w1 = fc1w + (size_t)hc * 64 * DIM;
        #pragma unroll
        for (int it = 0; it < 8; it++) {
            int e4 = tid + 256 * it;
            int r = e4 >> 5;
            int c = (e4 & 31) << 2;
            float4 v = *(const float4*)(w1 + r * DIM + c);
            float* d = Wsm + r * APAD + c;
            d[0] = rtf32(v.x); d[1] = rtf32(v.y); d[2] = rtf32(v.z); d[3] = rtf32(v.w);
        }
        __syncthreads();

        // GEMM1: H = gelu(Y @ W1c^T + b1)  (64x64, k=128)
        float acc1[2][2][4];
        #pragma unroll
        for (int m = 0; m < 2; m++)
            #pragma unroll
            for (int n = 0; n < 2; n++)
                #pragma unroll
                for (int q = 0; q < 4; q++) acc1[m][n][q] = 0.f;
        wgemm<2, 2, 16>(Ysm, APAD, 0, Wsm, APAD, 0, acc1, rbase, nbase1, g, i);

        #pragma unroll
        for (int n = 0; n < 2; n++) {
            int col = nbase1 + n * 8 + 2 * i;
            float b0f = fc1b[hc * 64 + col];
            float b1f = fc1b[hc * 64 + col + 1];
            #pragma unroll
            for (int m = 0; m < 2; m++) {
                int row = rbase + m * 16 + g;
                float v0 = acc1[m][n][0] + b0f;
                float v1 = acc1[m][n][1] + b1f;
                float v2 = acc1[m][n][2] + b0f;
                float v3 = acc1[m][n][3] + b1f;
                v0 = 0.5f * v0 * (1.0f + erff(v0 * is2));
                v1 = 0.5f * v1 * (1.0f + erff(v1 * is2));
                v2 = 0.5f * v2 * (1.0f + erff(v2 * is2));
                v3 = 0.5f * v3 * (1.0f + erff(v3 * is2));
                Hsm[row * HP + col]           = rtf32(v0);
                Hsm[row * HP + col + 1]       = rtf32(v1);
                Hsm[(row + 8) * HP + col]     = rtf32(v2);
                Hsm[(row + 8) * HP + col + 1] = rtf32(v3);
            }
        }
        __syncthreads();

        // stage fc2 chunk: [128 out][64 k] -> Wsm [128][HP]
        #pragma unroll
        for (int it = 0; it < 8; it++) {
            int e4 = tid + 256 * it;
            int r = e4 >> 4;
            int c = (e4 & 15) << 2;
            float4 v = *(const float4*)(fc2w + (size_t)r * 512 + hc * 64 + c);
            float* d = Wsm + r * HP + c;
            d[0] = rtf32(v.x); d[1] = rtf32(v.y); d[2] = rtf32(v.z); d[3] = rtf32(v.w);
        }
        __syncthreads();

        // GEMM2: acc2 += H @ W2c^T  (64x128, k=64)
        wgemm<2, 4, 8>(Hsm, HP, 0, Wsm, HP, 0, acc2, rbase, nbase2, g, i);
    }

    __syncthreads();
    // h2 (+bias) -> Ysm (fp32)
    #pragma unroll
    for (int n = 0; n < 4; n++) {
        int col = nbase2 + n * 8 + 2 * i;
        float b0f = fc2b[col];
        float b1f = fc2b[col + 1];
        #pragma unroll
        for (int m = 0; m < 2; m++) {
            int row = rbase + m * 16 + g;
            Ysm[row * APAD + col]           = acc2[m][n][0] + b0f;
            Ysm[row * APAD + col + 1]       = acc2[m][n][1] + b1f;
            Ysm[(row + 8) * APAD + col]     = acc2[m][n][2] + b0f;
            Ysm[(row + 8) * APAD + col + 1] = acc2[m][n][3] + b1f;
        }
    }
    __syncthreads();

    // LN2 stats: 4 threads/row
    {
        int row = tid >> 2;
        int cb = (tid & 3) * 32;
        float s = 0.f;
        #pragma unroll 8
        for (int c = 0; c < 32; c++) s += Ysm[row * APAD + cb + c];
        ps[tid] = s;
    }
    __syncthreads();
    if (tid < 64) {
        float s = ps[4 * tid] + ps[4 * tid + 1] + ps[4 * tid + 2] + ps[4 * tid + 3];
        muv[tid] = s * (1.0f / DIM);
    }
    __syncthreads();
    {
        int row = tid >> 2;
        int cb = (tid & 3) * 32;
        float m = muv[row];
        float v = 0.f;
        #pragma unroll 8
        for (int c = 0; c < 32; c++) {
            float d = Ysm[row * APAD + cb + c] - m;
            v += d * d;
        }
        ps[tid] = v;
    }
    __syncthreads();
    if (tid < 64) {
        float v = ps[4 * tid] + ps[4 * tid + 1] + ps[4 * tid + 2] + ps[4 * tid + 3];
        rsv[tid] = rsqrtf(v * (1.0f / DIM) + 1e-5f);
    }
    __syncthreads();

    // out = y(gmem) + LN(h2)
    float* od = out + tok0 * DIM;
    #pragma unroll
    for (int it = 0; it < 8; it++) {
        int e4 = tid + 256 * it;
        int t = e4 >> 5;
        int c = (e4 & 31) << 2;
        float4 yv = *(const float4*)(ysrc + (size_t)t * DIM + c);
        float m = muv[t], r = rsv[t];
        float4 o;
        o.x = yv.x + (Ysm[t * APAD + c + 0] - m) * r * n2w[c + 0] + n2b[c + 0];
        o.y = yv.y + (Ysm[t * APAD + c + 1] - m) * r * n2w[c + 1] + n2b[c + 1];
        o.z = yv.z + (Ysm[t * APAD + c + 2] - m) * r * n2w[c + 2] + n2b[c + 2];
        o.w = yv.w + (Ysm[t * APAD + c + 3] - m) * r * n2w[c + 3] + n2b[c + 3];
        *(float4*)(od + (size_t)t * DIM + c) = o;
    }
}

static const int ATTN_SMEM = (52224 + 64 + 64 + 64) * 4;
static const int MLP_SMEM  = (64 * APAD + 8704 + 64 * HP + 256 + 64 + 64) * 4;

extern "C" void kernel_launch(void* const* d_in, const int* in_sizes, int n_in,
                              void* d_out, int out_size) {
    const float* x      = (const float*)d_in[0];
    const float* qkv_w  = (const float*)d_in[1];
    const float* qkv_b  = (const float*)d_in[2];
    const float* proj_w = (const float*)d_in[3];
    const float* proj_b = (const float*)d_in[4];
    const float* rpe_w1 = (const float*)d_in[5];
    const float* rpe_b1 = (const float*)d_in[6];
    const float* rpe_w2 = (const float*)d_in[7];
    const float* n1w    = (const float*)d_in[8];
    const float* n1b    = (const float*)d_in[9];
    const float* fc1w   = (const float*)d_in[10];
    const float* fc1b   = (const float*)d_in[11];
    const float* fc2w   = (const float*)d_in[12];
    const float* fc2b   = (const float*)d_in[13];
    const float* n2w    = (const float*)d_in[14];
    const float* n2b    = (const float*)d_in[15];
    float* out = (float*)d_out;

    cudaFuncSetAttribute(attn_kernel, cudaFuncAttributeMaxDynamicSharedMemorySize, ATTN_SMEM);
    cudaFuncSetAttribute(mlp_kernel,  cudaFuncAttributeMaxDynamicSharedMemorySize, MLP_SMEM);

    bias_table_kernel<<<225, 128>>>(rpe_w1, rpe_b1, rpe_w2);
    bias_scatter_kernel<<<64, 256>>>();
    attn_kernel<<<2048, 512, ATTN_SMEM>>>(x, qkv_w, qkv_b, proj_w, proj_b, n1w, n1b);
    mlp_kernel<<<2048, 256, MLP_SMEM>>>(fc1w, fc1b, fc2w, fc2b, n2w, n2b, out);
}

// round 6
// speedup vs baseline: 1.0949x; 1.0949x over previous
#include <cuda_runtime.h>
#include <math.h>
#include <stdint.h>

#define WSZ 8
#define NHEAD 4
#define DIM 128
#define NTOK 64
#define HD 32
#define BATCH 32
#define HW 64
#define LSEQ 4096
#define RPE_HID 512
#define APAD 132
#define SBP 67
#define VTP 68
#define WP2 68

__device__ float g_bias[NHEAD * NTOK * NTOK];
__device__ float g_ttab[225 * NHEAD];
__device__ float g_ybuf[(size_t)BATCH * LSEQ * DIM];
// tf32-prerounded weights
__device__ float g_qkvw_r[3 * DIM * DIM];
__device__ float g_projw_r[DIM * DIM];
__device__ float g_fc1w_r[512 * DIM];
__device__ float g_fc2w_r[DIM * 512];

// ---------------- tf32 MMA helpers ----------------
__device__ __forceinline__ uint32_t f2tf32(float f) {
    uint32_t u;
    asm("cvt.rna.tf32.f32 %0, %1;" : "=r"(u) : "f"(f));
    return u;
}
__device__ __forceinline__ float rtf32(float f) { return __uint_as_float(f2tf32(f)); }

__device__ __forceinline__ void mma_tf32(float* c, const uint32_t* a, uint32_t b0, uint32_t b1) {
    asm volatile(
        "mma.sync.aligned.m16n8k8.row.col.f32.tf32.tf32.f32 "
        "{%0,%1,%2,%3}, {%4,%5,%6,%7}, {%8,%9}, {%0,%1,%2,%3};"
        : "+f"(c[0]), "+f"(c[1]), "+f"(c[2]), "+f"(c[3])
        : "r"(a[0]), "r"(a[1]), "r"(a[2]), "r"(a[3]), "r"(b0), "r"(b1));
}

template<int MT, int NT, int KS>
__device__ __forceinline__ void wgemm(const float* __restrict__ Asm, int lda, int aoff,
                                      const float* __restrict__ Bsm, int ldb, int boff,
                                      float (&acc)[MT][NT][4], int rbase, int nbase,
                                      int g, int i)
{
    #pragma unroll
    for (int ks = 0; ks < KS; ks++) {
        int kc = i + ks * 8;
        uint32_t a[MT][4];
        #pragma unroll
        for (int m = 0; m < MT; m++) {
            int r0 = rbase + m * 16 + g;
            a[m][0] = __float_as_uint(Asm[r0 * lda + aoff + kc]);
            a[m][1] = __float_as_uint(Asm[(r0 + 8) * lda + aoff + kc]);
            a[m][2] = __float_as_uint(Asm[r0 * lda + aoff + kc + 4]);
            a[m][3] = __float_as_uint(Asm[(r0 + 8) * lda + aoff + kc + 4]);
        }
        #pragma unroll
        for (int n = 0; n < NT; n++) {
            int nc = nbase + n * 8 + g;
            uint32_t b0 = __float_as_uint(Bsm[nc * ldb + boff + kc]);
            uint32_t b1 = __float_as_uint(Bsm[nc * ldb + boff + kc + 4]);
            #pragma unroll
            for (int m = 0; m < MT; m++) mma_tf32(acc[m][n], a[m], b0, b1);
        }
    }
}

// ---------------- cp.async helpers ----------------
__device__ __forceinline__ void cp16(uint32_t dst, const float* src) {
    asm volatile("cp.async.ca.shared.global [%0], [%1], 16;" :: "r"(dst), "l"(src));
}
__device__ __forceinline__ void cp_commit() { asm volatile("cp.async.commit_group;"); }
__device__ __forceinline__ void cp_wait0()  { asm volatile("cp.async.wait_group 0;"); }

// ---------------- weight pre-rounding ----------------
__global__ void round_weights_kernel(const float* __restrict__ qkvw, const float* __restrict__ projw,
                                     const float* __restrict__ fc1w, const float* __restrict__ fc2w) {
    int e4 = blockIdx.x * 256 + threadIdx.x;   // 49152 float4 total
    const float* src;
    float* dst;
    int off;
    if (e4 < 12288) { src = qkvw; dst = g_qkvw_r; off = e4; }
    else if (e4 < 16384) { src = projw; dst = g_projw_r; off = e4 - 12288; }
    else if (e4 < 32768) { src = fc1w; dst = g_fc1w_r; off = e4 - 16384; }
    else { src = fc2w; dst = g_fc2w_r; off = e4 - 32768; }
    float4 v = *(const float4*)(src + off * 4);
    float4 o;
    o.x = rtf32(v.x); o.y = rtf32(v.y); o.z = rtf32(v.z); o.w = rtf32(v.w);
    *(float4*)(dst + off * 4) = o;
}

// ---------------- RPE bias ----------------
__global__ void bias_table_kernel(const float* __restrict__ w1, const float* __restrict__ b1,
                                  const float* __restrict__ w2) {
    __shared__ float4 red[128];
    int p = blockIdx.x;
    int tid = threadIdx.x;
    int i = p / 15, j = p % 15;
    float v0 = (float)(i - 7) / 7.0f * 8.0f;
    float v1 = (float)(j - 7) / 7.0f * 8.0f;
    float inv_l8 = 1.0f / log2f(8.0f);
    float s0 = (v0 > 0.f) ? 1.f : ((v0 < 0.f) ? -1.f : 0.f);
    float s1 = (v1 > 0.f) ? 1.f : ((v1 < 0.f) ? -1.f : 0.f);
    float x0 = s0 * log2f(fabsf(v0) + 1.0f) * inv_l8;
    float x1 = s1 * log2f(fabsf(v1) + 1.0f) * inv_l8;
    float a0 = 0.f, a1 = 0.f, a2 = 0.f, a3 = 0.f;
    #pragma unroll
    for (int r = 0; r < 4; r++) {
        int h = tid + 128 * r;
        float hid = x0 * w1[2 * h] + x1 * w1[2 * h + 1] + b1[h];
        hid = fmaxf(hid, 0.f);
        a0 += hid * w2[0 * RPE_HID + h];
        a1 += hid * w2[1 * RPE_HID + h];
        a2 += hid * w2[2 * RPE_HID + h];
        a3 += hid * w2[3 * RPE_HID + h];
    }
    red[tid] = make_float4(a0, a1, a2, a3);
    __syncthreads();
    for (int s = 64; s > 0; s >>= 1) {
        if (tid < s) {
            float4 o = red[tid + s];
            red[tid].x += o.x; red[tid].y += o.y; red[tid].z += o.z; red[tid].w += o.w;
        }
        __syncthreads();
    }
    if (tid == 0) {
        g_ttab[p * 4 + 0] = red[0].x; g_ttab[p * 4 + 1] = red[0].y;
        g_ttab[p * 4 + 2] = red[0].z; g_ttab[p * 4 + 3] = red[0].w;
    }
}

__global__ void bias_scatter_kernel() {
    int e = blockIdx.x * 256 + threadIdx.x;
    int h = e >> 12;
    int rem = e & 4095;
    int i = rem >> 6, j = rem & 63;
    int yi = i >> 3, xi = i & 7, yj = j >> 3, xj = j & 7;
    int idx = (yi - yj + 7) * 15 + (xi - xj + 7);
    g_bias[e] = g_ttab[idx * 4 + h];
}

// ---------------- Kernel 2: attention + LN1 + residual (tf32, 256 threads, R3 structure) ----------------
__global__ __launch_bounds__(256) void attn_kernel(
    const float* __restrict__ x, const float* __restrict__ qkv_b,
    const float* __restrict__ proj_b,
    const float* __restrict__ n1w, const float* __restrict__ n1b)
{
    extern __shared__ float sm[];
    float* xw = sm;
    float* sb4 = sm;
    float* wb = sm + 8448;
    float* qb = sm + 25344;
    float* ow = qb;
    float* kb = sm + 33792;
    float* vt = sm + 42240;
    float* rsum4 = sm + 50944;
    int* regid = (int*)(rsum4 + 256);
    float* mu = (float*)(regid + 64);
    float* rstd = mu + 64;

    int tid = threadIdx.x;
    int wid = tid >> 5;
    int lane = tid & 31;
    int g = lane >> 2;
    int i = lane & 3;

    int bx = blockIdx.x;
    int bimg = bx >> 6;
    int wh = (bx >> 3) & 7, ww = bx & 7;
    const float* xbase = x + (size_t)bimg * (LSEQ * DIM);

    #pragma unroll
    for (int it = 0; it < 8; it++) {
        int e4 = tid + 256 * it;
        int t = e4 >> 5;
        int c = (e4 & 31) << 2;
        int ti = t >> 3, tj = t & 7;
        int hh = (wh * 8 + ti + 4) & 63;
        int wwp = (ww * 8 + tj + 4) & 63;
        float4 v = *(const float4*)(xbase + (size_t)((hh << 6) + wwp) * DIM + c);
        float* d = xw + t * APAD + c;
        d[0] = rtf32(v.x); d[1] = rtf32(v.y); d[2] = rtf32(v.z); d[3] = rtf32(v.w);
    }
    if (tid < 64) {
        int ti = tid >> 3, tj = tid & 7;
        int ah = wh * 8 + ti, aw = ww * 8 + tj;
        int rh = ah < 56 ? 0 : (ah < 60 ? 1 : 2);
        int rw = aw < 56 ? 0 : (aw < 60 ? 1 : 2);
        regid[tid] = rh * 3 + rw;
    }

    const float scale = 0.17677669529663687f;

    // ---- QKV: 3 GEMMs 64x128x128, 8 warps 2(M)x4(N) ----
    for (int cidx = 0; cidx < 3; cidx++) {
        const float* wsrc = g_qkvw_r + cidx * DIM * DIM;
        #pragma unroll
        for (int it = 0; it < 16; it++) {
            int e4 = tid + 256 * it;
            int r = e4 >> 5;
            int c = (e4 & 31) << 2;
            float4 v = *(const float4*)(wsrc + r * DIM + c);
            float* d = wb + r * APAD + c;
            d[0] = v.x; d[1] = v.y; d[2] = v.z; d[3] = v.w;
        }
        __syncthreads();

        float acc[2][4][4];
        #pragma unroll
        for (int m = 0; m < 2; m++)
            #pragma unroll
            for (int n = 0; n < 4; n++)
                #pragma unroll
                for (int q = 0; q < 4; q++) acc[m][n][q] = 0.f;
        int rbase = (wid >> 2) * 32;
        int nbase = (wid & 3) * 32;
        wgemm<2, 4, 16>(xw, APAD, 0, wb, APAD, 0, acc, rbase, nbase, g, i);

        #pragma unroll
        for (int n = 0; n < 4; n++) {
            int col = nbase + n * 8 + 2 * i;
            float b0f = qkv_b[cidx * DIM + col];
            float b1f = qkv_b[cidx * DIM + col + 1];
            #pragma unroll
            for (int m = 0; m < 2; m++) {
                int row = rbase + m * 16 + g;
                float v0 = acc[m][n][0] + b0f;
                float v1 = acc[m][n][1] + b1f;
                float v2 = acc[m][n][2] + b0f;
                float v3 = acc[m][n][3] + b1f;
                if (cidx == 0) {
                    qb[row * APAD + col]           = rtf32(v0 * scale);
                    qb[row * APAD + col + 1]       = rtf32(v1 * scale);
                    qb[(row + 8) * APAD + col]     = rtf32(v2 * scale);
                    qb[(row + 8) * APAD + col + 1] = rtf32(v3 * scale);
                } else if (cidx == 1) {
                    kb[row * APAD + col]           = rtf32(v0);
                    kb[row * APAD + col + 1]       = rtf32(v1);
                    kb[(row + 8) * APAD + col]     = rtf32(v2);
                    kb[(row + 8) * APAD + col + 1] = rtf32(v3);
                } else {
                    vt[col * VTP + row]           = rtf32(v0);
                    vt[(col + 1) * VTP + row]     = rtf32(v1);
                    vt[col * VTP + row + 8]       = rtf32(v2);
                    vt[(col + 1) * VTP + row + 8] = rtf32(v3);
                }
            }
        }
        __syncthreads();
    }

    // ---- scores: 4 heads x 2 warps/head ----
    {
        int h = wid >> 1;
        int hoff = h * HD;
        int rbase = (wid & 1) * 32;
        float acc[2][8][4];
        #pragma unroll
        for (int m = 0; m < 2; m++)
            #pragma unroll
            for (int n = 0; n < 8; n++)
                #pragma unroll
                for (int q = 0; q < 4; q++) acc[m][n][q] = 0.f;
        wgemm<2, 8, 4>(qb, APAD, hoff, kb, APAD, hoff, acc, rbase, 0, g, i);

        float* sbh = sb4 + h * (64 * SBP);
        const float* gb = g_bias + h * 4096;
        #pragma unroll
        for (int m = 0; m < 2; m++) {
            int row0 = rbase + m * 16 + g;
            int r0 = regid[row0];
            int r1 = regid[row0 + 8];
            #pragma unroll
            for (int n = 0; n < 8; n++) {
                int col = n * 8 + 2 * i;
                int c0 = regid[col], c1 = regid[col + 1];
                float m00 = (r0 != c0) ? -100.f : 0.f;
                float m01 = (r0 != c1) ? -100.f : 0.f;
                float m10 = (r1 != c0) ? -100.f : 0.f;
                float m11 = (r1 != c1) ? -100.f : 0.f;
                sbh[row0 * SBP + col]           = acc[m][n][0] + gb[row0 * 64 + col] + m00;
                sbh[row0 * SBP + col + 1]       = acc[m][n][1] + gb[row0 * 64 + col + 1] + m01;
                sbh[(row0 + 8) * SBP + col]     = acc[m][n][2] + gb[(row0 + 8) * 64 + col] + m10;
                sbh[(row0 + 8) * SBP + col + 1] = acc[m][n][3] + gb[(row0 + 8) * 64 + col + 1] + m11;
            }
        }
    }
    __syncthreads();

    // ---- softmax: one thread per (head,row) ----
    {
        float* rowp = sb4 + (tid >> 6) * (64 * SBP) + (tid & 63) * SBP;
        float mx = -1e30f;
        #pragma unroll 8
        for (int j = 0; j < 64; j++) mx = fmaxf(mx, rowp[j]);
        float s = 0.f;
        #pragma unroll 8
        for (int j = 0; j < 64; j++) {
            float e = __expf(rowp[j] - mx);
            s += e;
            rowp[j] = rtf32(e);
        }
        rsum4[tid] = 1.0f / s;
    }
    __syncthreads();

    // ---- PV ----
    {
        int h = wid >> 1;
        int hoff = h * HD;
        int rbase = (wid & 1) * 32;
        float acc[2][4][4];
        #pragma unroll
        for (int m = 0; m < 2; m++)
            #pragma unroll
            for (int n = 0; n < 4; n++)
                #pragma unroll
                for (int q = 0; q < 4; q++) acc[m][n][q] = 0.f;
        wgemm<2, 4, 8>(sb4 + h * (64 * SBP), SBP, 0, vt, VTP, 0, acc, rbase, hoff, g, i);

        #pragma unroll
        for (int m = 0; m < 2; m++) {
            int row = rbase + m * 16 + g;
            float rs0 = rsum4[h * 64 + row];
            float rs1 = rsum4[h * 64 + row + 8];
            #pragma unroll
            for (int n = 0; n < 4; n++) {
                int col = hoff + n * 8 + 2 * i;
                ow[row * APAD + col]           = rtf32(acc[m][n][0] * rs0);
                ow[row * APAD + col + 1]       = rtf32(acc[m][n][1] * rs0);
                ow[(row + 8) * APAD + col]     = rtf32(acc[m][n][2] * rs1);
                ow[(row + 8) * APAD + col + 1] = rtf32(acc[m][n][3] * rs1);
            }
        }
    }
    __syncthreads();

    // ---- stage proj_w (pre-rounded) ----
    #pragma unroll
    for (int it = 0; it < 16; it++) {
        int e4 = tid + 256 * it;
        int r = e4 >> 5;
        int c = (e4 & 31) << 2;
        float4 v = *(const float4*)(g_projw_r + r * DIM + c);
        float* d = wb + r * APAD + c;
        d[0] = v.x; d[1] = v.y; d[2] = v.z; d[3] = v.w;
    }
    __syncthreads();

    // ---- proj GEMM ----
    {
        float acc[2][4][4];
        #pragma unroll
        for (int m = 0; m < 2; m++)
            #pragma unroll
            for (int n = 0; n < 4; n++)
                #pragma unroll
                for (int q = 0; q < 4; q++) acc[m][n][q] = 0.f;
        int rbase = (wid >> 2) * 32;
        int nbase = (wid & 3) * 32;
        wgemm<2, 4, 16>(ow, APAD, 0, wb, APAD, 0, acc, rbase, nbase, g, i);
        #pragma unroll
        for (int n = 0; n < 4; n++) {
            int col = nbase + n * 8 + 2 * i;
            float b0f = proj_b[col];
            float b1f = proj_b[col + 1];
            #pragma unroll
            for (int m = 0; m < 2; m++) {
                int row = rbase + m * 16 + g;
                kb[row * APAD + col]           = acc[m][n][0] + b0f;
                kb[row * APAD + col + 1]       = acc[m][n][1] + b1f;
                kb[(row + 8) * APAD + col]     = acc[m][n][2] + b0f;
                kb[(row + 8) * APAD + col + 1] = acc[m][n][3] + b1f;
            }
        }
    }
    __syncthreads();

    // ---- LN1 stats: 4 threads/row ----
    {
        int row = tid >> 2;
        int cb = (tid & 3) * 32;
        float s = 0.f;
        #pragma unroll 8
        for (int c = 0; c < 32; c++) s += kb[row * APAD + cb + c];
        rsum4[tid] = s;
    }
    __syncthreads();
    if (tid < 64) {
        float s = rsum4[4 * tid] + rsum4[4 * tid + 1] + rsum4[4 * tid + 2] + rsum4[4 * tid + 3];
        mu[tid] = s * (1.0f / DIM);
    }
    __syncthreads();
    {
        int row = tid >> 2;
        int cb = (tid & 3) * 32;
        float m = mu[row];
        float v = 0.f;
        #pragma unroll 8
        for (int c = 0; c < 32; c++) {
            float d = kb[row * APAD + cb + c] - m;
            v += d * d;
        }
        rsum4[tid] = v;
    }
    __syncthreads();
    if (tid < 64) {
        float v = rsum4[4 * tid] + rsum4[4 * tid + 1] + rsum4[4 * tid + 2] + rsum4[4 * tid + 3];
        rstd[tid] = rsqrtf(v * (1.0f / DIM) + 1e-5f);
    }
    __syncthreads();

    // ---- y = x + LN(proj) ----
    float* yb = g_ybuf + (size_t)bimg * (LSEQ * DIM);
    #pragma unroll
    for (int it = 0; it < 8; it++) {
        int e4 = tid + 256 * it;
        int t = e4 >> 5;
        int c = (e4 & 31) << 2;
        int ti = t >> 3, tj = t & 7;
        int hh = (wh * 8 + ti + 4) & 63;
        int wwp = (ww * 8 + tj + 4) & 63;
        size_t goff = (size_t)((hh << 6) + wwp) * DIM + c;
        float4 xv = *(const float4*)(xbase + goff);
        float m = mu[t], r = rstd[t];
        float4 o;
        o.x = xv.x + (kb[t * APAD + c + 0] - m) * r * n1w[c + 0] + n1b[c + 0];
        o.y = xv.y + (kb[t * APAD + c + 1] - m) * r * n1w[c + 1] + n1b[c + 1];
        o.z = xv.z + (kb[t * APAD + c + 2] - m) * r * n1w[c + 2] + n1b[c + 2];
        o.w = xv.w + (kb[t * APAD + c + 3] - m) * r * n1w[c + 3] + n1b[c + 3];
        *(float4*)(yb + goff) = o;
    }
}

// ---------------- Kernel 3: MLP + LN2 + residual (128 tok/CTA, cp.async pipelined) ----------------
// smem floats: Ysm [128][132] (tf32) | Hsm [128][132] (tf32 H; fp32 h2 at end) |
//              Wa [8704] | Wb [8704] | ps[256] mu[128] rs[128]
__global__ __launch_bounds__(256, 1) void mlp_kernel(
    const float* __restrict__ fc1b, const float* __restrict__ fc2b,
    const float* __restrict__ n2w, const float* __restrict__ n2b,
    float* __restrict__ out)
{
    extern __shared__ float sm[];
    float* Ysm = sm;                      // 16896
    float* Hsm = Ysm + 128 * APAD;        // 16896
    float* Wa  = Hsm + 128 * APAD;        // 8704
    float* Wb  = Wa + 8704;               // 8704
    float* ps  = Wb + 8704;               // 256
    float* muv = ps + 256;                // 128
    float* rsv = muv + 128;               // 128

    int tid = threadIdx.x;
    int wid = tid >> 5;
    int lane = tid & 31;
    int g = lane >> 2;
    int i = lane & 3;
    // GEMM1 (128x64): 4Mx2N, warp tile 32x32
    int rb1 = (wid >> 1) * 32;
    int nb1 = (wid & 1) * 32;
    // GEMM2 (128x128): 4Mx2N, warp tile 32x64
    int rb2 = (wid >> 1) * 32;
    int nb2 = (wid & 1) * 64;

    uint32_t WaAddr = (uint32_t)__cvta_generic_to_shared(Wa);
    uint32_t WbAddr = (uint32_t)__cvta_generic_to_shared(Wb);

    size_t tok0 = (size_t)blockIdx.x * 128;
    const float* ysrc = g_ybuf + tok0 * DIM;

    // prefetch W1 chunk0 half0 into Wa (64 rows x 128)
    {
        const float* src = g_fc1w_r;
        #pragma unroll
        for (int it = 0; it < 8; it++) {
            int e4 = tid + 256 * it;
            int r = e4 >> 5;
            int c = (e4 & 31) << 2;
            cp16(WaAddr + (r * APAD + c) * 4, src + r * DIM + c);
        }
        cp_commit();
    }

    // load Y (tf32-rounded)
    #pragma unroll
    for (int it = 0; it < 16; it++) {
        int e4 = tid + 256 * it;
        int t = e4 >> 5;
        int c = (e4 & 31) << 2;
        float4 v = *(const float4*)(ysrc + (size_t)t * DIM + c);
        float* d = Ysm + t * APAD + c;
        d[0] = rtf32(v.x); d[1] = rtf32(v.y); d[2] = rtf32(v.z); d[3] = rtf32(v.w);
    }

    float acc2[2][8][4];
    #pragma unroll
    for (int m = 0; m < 2; m++)
        #pragma unroll
        for (int n = 0; n < 8; n++)
            #pragma unroll
            for (int q = 0; q < 4; q++) acc2[m][n][q] = 0.f;

    const float is2 = 0.70710678118654752f;

    for (int hc = 0; hc < 4; hc++) {
        // ================= S1: GEMM1 half0 (uses Wa); prefetch W1 half1 -> Wb =================
        cp_wait0();
        __syncthreads();
        {
            const float* src = g_fc1w_r + ((size_t)hc * 128 + 64) * DIM;
            #pragma unroll
            for (int it = 0; it < 8; it++) {
                int e4 = tid + 256 * it;
                int r = e4 >> 5;
                int c = (e4 & 31) << 2;
                cp16(WbAddr + (r * APAD + c) * 4, src + r * DIM + c);
            }
            cp_commit();
        }
        #pragma unroll
        for (int half = 0; half < 2; half++) {
            const float* Wbuf = half ? Wb : Wa;
            float acc1[2][4][4];
            #pragma unroll
            for (int m = 0; m < 2; m++)
                #pragma unroll
                for (int n = 0; n < 4; n++)
                    #pragma unroll
                    for (int q = 0; q < 4; q++) acc1[m][n][q] = 0.f;
            wgemm<2, 4, 16>(Ysm, APAD, 0, Wbuf, APAD, 0, acc1, rb1, nb1, g, i);

            int hbase = half * 64;
            #pragma unroll
            for (int n = 0; n < 4; n++) {
                int col = nb1 + n * 8 + 2 * i;              // 0..63 local
                float b0f = fc1b[hc * 128 + hbase + col];
                float b1f = fc1b[hc * 128 + hbase + col + 1];
                #pragma unroll
                for (int m = 0; m < 2; m++) {
                    int row = rb1 + m * 16 + g;
                    float v0 = acc1[m][n][0] + b0f;
                    float v1 = acc1[m][n][1] + b1f;
                    float v2 = acc1[m][n][2] + b0f;
                    float v3 = acc1[m][n][3] + b1f;
                    v0 = 0.5f * v0 * (1.0f + erff(v0 * is2));
                    v1 = 0.5f * v1 * (1.0f + erff(v1 * is2));
                    v2 = 0.5f * v2 * (1.0f + erff(v2 * is2));
                    v3 = 0.5f * v3 * (1.0f + erff(v3 * is2));
                    Hsm[row * APAD + hbase + col]           = rtf32(v0);
                    Hsm[row * APAD + hbase + col + 1]       = rtf32(v1);
                    Hsm[(row + 8) * APAD + hbase + col]     = rtf32(v2);
                    Hsm[(row + 8) * APAD + hbase + col + 1] = rtf32(v3);
                }
            }
            // ================= S2 boundary: after half0 compute, wait Wb; prefetch W2 kh0 -> Wa
            if (half == 0) {
                cp_wait0();
                __syncthreads();
                const float* src = g_fc2w_r;   // [128 out][512], cols hc*128 + 0*64
                #pragma unroll
                for (int it = 0; it < 8; it++) {
                    int e4 = tid + 256 * it;
                    int r = e4 >> 4;
                    int c = (e4 & 15) << 2;
                    cp16(WaAddr + (r * WP2 + c) * 4, src + (size_t)r * 512 + hc * 128 + c);
                }
                cp_commit();
            }
        }
        // ================= S3: GEMM2 kh0 (H cols 0-63 @ Wa); prefetch W2 kh1 -> Wb
        cp_wait0();
        __syncthreads();
        {
            const float* src = g_fc2w_r;
            #pragma unroll
            for (int it = 0; it < 8; it++) {
                int e4 = tid + 256 * it;
                int r = e4 >> 4;
                int c = (e4 & 15) << 2;
                cp16(WbAddr + (r * WP2 + c) * 4, src + (size_t)r * 512 + hc * 128 + 64 + c);
            }
            cp_commit();
        }
        wgemm<2, 8, 8>(Hsm, APAD, 0, Wa, WP2, 0, acc2, rb2, nb2, g, i);

        // ================= S4: GEMM2 kh1 (H cols 64-127 @ Wb); prefetch next W1 half0 -> Wa
        cp_wait0();
        __syncthreads();
        if (hc < 3) {
            const float* src = g_fc1w_r + (size_t)(hc + 1) * 128 * DIM;
            #pragma unroll
            for (int it = 0; it < 8; it++) {
                int e4 = tid + 256 * it;
                int r = e4 >> 5;
                int c = (e4 & 31) << 2;
                cp16(WaAddr + (r * APAD + c) * 4, src + r * DIM + c);
            }
            cp_commit();
        }
        wgemm<2, 8, 8>(Hsm, APAD, 64, Wb, WP2, 0, acc2, rb2, nb2, g, i);
    }

    __syncthreads();
    // h2 (+bias) -> Hsm (fp32)
    #pragma unroll
    for (int n = 0; n < 8; n++) {
        int col = nb2 + n * 8 + 2 * i;
        float b0f = fc2b[col];
        float b1f = fc2b[col + 1];
        #pragma unroll
        for (int m = 0; m < 2; m++) {
            int row = rb2 + m * 16 + g;
            Hsm[row * APAD + col]           = acc2[m][n][0] + b0f;
            Hsm[row * APAD + col + 1]       = acc2[m][n][1] + b1f;
            Hsm[(row + 8) * APAD + col]     = acc2[m][n][2] + b0f;
            Hsm[(row + 8) * APAD + col + 1] = acc2[m][n][3] + b1f;
        }
    }
    __syncthreads();

    // LN2 stats: 2 threads/row
    {
        int row = tid >> 1;
        int cb = (tid & 1) * 64;
        float s = 0.f;
        #pragma unroll 8
        for (int c = 0; c < 64; c++) s += Hsm[row * APAD + cb + c];
        ps[tid] = s;
    }
    __syncthreads();
    if (tid < 128) muv[tid] = (ps[2 * tid] + ps[2 * tid + 1]) * (1.0f / DIM);
    __syncthreads();
    {
        int row = tid >> 1;
        int cb = (tid & 1) * 64;
        float m = muv[row];
        float v = 0.f;
        #pragma unroll 8
        for (int c = 0; c < 64; c++) {
            float d = Hsm[row * APAD + cb + c] - m;
            v += d * d;
        }
        ps[tid] = v;
    }
    __syncthreads();
    if (tid < 128) rsv[tid] = rsqrtf((ps[2 * tid] + ps[2 * tid + 1]) * (1.0f / DIM) + 1e-5f);
    __syncthreads();

    // out = y(gmem) + LN(h2)
    float* od = out + tok0 * DIM;
    #pragma unroll
    for (int it = 0; it < 16; it++) {
        int e4 = tid + 256 * it;
        int t = e4 >> 5;
        int c = (e4 & 31) << 2;
        float4 yv = *(const float4*)(ysrc + (size_t)t * DIM + c);
        float m = muv[t], r = rsv[t];
        float4 o;
        o.x = yv.x + (Hsm[t * APAD + c + 0] - m) * r * n2w[c + 0] + n2b[c + 0];
        o.y = yv.y + (Hsm[t * APAD + c + 1] - m) * r * n2w[c + 1] + n2b[c + 1];
        o.z = yv.z + (Hsm[t * APAD + c + 2] - m) * r * n2w[c + 2] + n2b[c + 2];
        o.w = yv.w + (Hsm[t * APAD + c + 3] - m) * r * n2w[c + 3] + n2b[c + 3];
        *(float4*)(od + (size_t)t * DIM + c) = o;
    }
}

static const int ATTN_SMEM = (50944 + 256 + 64 + 64 + 64) * 4;
static const int MLP_SMEM  = (2 * 128 * APAD + 2 * 8704 + 256 + 128 + 128) * 4;

extern "C" void kernel_launch(void* const* d_in, const int* in_sizes, int n_in,
                              void* d_out, int out_size) {
    const float* x      = (const float*)d_in[0];
    const float* qkv_w  = (const float*)d_in[1];
    const float* qkv_b  = (const float*)d_in[2];
    const float* proj_w = (const float*)d_in[3];
    const float* proj_b = (const float*)d_in[4];
    const float* rpe_w1 = (const float*)d_in[5];
    const float* rpe_b1 = (const float*)d_in[6];
    const float* rpe_w2 = (const float*)d_in[7];
    const float* n1w    = (const float*)d_in[8];
    const float* n1b    = (const float*)d_in[9];
    const float* fc1w   = (const float*)d_in[10];
    const float* fc1b   = (const float*)d_in[11];
    const float* fc2w   = (const float*)d_in[12];
    const float* fc2b   = (const float*)d_in[13];
    const float* n2w    = (const float*)d_in[14];
    const float* n2b    = (const float*)d_in[15];
    float* out = (float*)d_out;

    cudaFuncSetAttribute(attn_kernel, cudaFuncAttributeMaxDynamicSharedMemorySize, ATTN_SMEM);
    cudaFuncSetAttribute(mlp_kernel,  cudaFuncAttributeMaxDynamicSharedMemorySize, MLP_SMEM);

    round_weights_kernel<<<192, 256>>>(qkv_w, proj_w, fc1w, fc2w);
    bias_table_kernel<<<225, 128>>>(rpe_w1, rpe_b1, rpe_w2);
    bias_scatter_kernel<<<64, 256>>>();
    attn_kernel<<<2048, 256, ATTN_SMEM>>>(x, qkv_b, proj_b, n1w, n1b);
    mlp_kernel<<<1024, 256, MLP_SMEM>>>(fc1b, fc2b, n2w, n2b, out);
}

// round 8
// speedup vs baseline: 1.2896x; 1.1778x over previous
#include <cuda_runtime.h>
#include <cuda_fp16.h>
#include <math.h>
#include <stdint.h>

#define WSZ 8
#define NHEAD 4
#define DIM 128
#define NTOK 64
#define HD 32
#define BATCH 32
#define HW 64
#define LSEQ 4096
#define RPE_HID 512
#define APAD 132
#define SBP 67
#define VTP 68
#define YPH 136    // fp16 smem pitch (halves): bank = (4*row + i) % 32, conflict-free

__device__ float g_bias[NHEAD * NTOK * NTOK];
__device__ float g_ttab[225 * NHEAD];
__device__ float g_ybuf[(size_t)BATCH * LSEQ * DIM];
__device__ float g_qkvw_r[3 * DIM * DIM];
__device__ float g_projw_r[DIM * DIM];
__device__ __half g_fc1w_h[512 * DIM];
__device__ __half g_fc2w_h[DIM * 512];

// ---------------- tf32 MMA helpers (attention) ----------------
__device__ __forceinline__ uint32_t f2tf32(float f) {
    uint32_t u;
    asm("cvt.rna.tf32.f32 %0, %1;" : "=r"(u) : "f"(f));
    return u;
}
__device__ __forceinline__ float rtf32(float f) { return __uint_as_float(f2tf32(f)); }

__device__ __forceinline__ void mma_tf32(float* c, const uint32_t* a, uint32_t b0, uint32_t b1) {
    asm volatile(
        "mma.sync.aligned.m16n8k8.row.col.f32.tf32.tf32.f32 "
        "{%0,%1,%2,%3}, {%4,%5,%6,%7}, {%8,%9}, {%0,%1,%2,%3};"
        : "+f"(c[0]), "+f"(c[1]), "+f"(c[2]), "+f"(c[3])
        : "r"(a[0]), "r"(a[1]), "r"(a[2]), "r"(a[3]), "r"(b0), "r"(b1));
}

template<int MT, int NT, int KS>
__device__ __forceinline__ void wgemm(const float* __restrict__ Asm, int lda, int aoff,
                                      const float* __restrict__ Bsm, int ldb, int boff,
                                      float (&acc)[MT][NT][4], int rbase, int nbase,
                                      int g, int i)
{
    #pragma unroll
    for (int ks = 0; ks < KS; ks++) {
        int kc = i + ks * 8;
        uint32_t a[MT][4];
        #pragma unroll
        for (int m = 0; m < MT; m++) {
            int r0 = rbase + m * 16 + g;
            a[m][0] = __float_as_uint(Asm[r0 * lda + aoff + kc]);
            a[m][1] = __float_as_uint(Asm[(r0 + 8) * lda + aoff + kc]);
            a[m][2] = __float_as_uint(Asm[r0 * lda + aoff + kc + 4]);
            a[m][3] = __float_as_uint(Asm[(r0 + 8) * lda + aoff + kc + 4]);
        }
        #pragma unroll
        for (int n = 0; n < NT; n++) {
            int nc = nbase + n * 8 + g;
            uint32_t b0 = __float_as_uint(Bsm[nc * ldb + boff + kc]);
            uint32_t b1 = __float_as_uint(Bsm[nc * ldb + boff + kc + 4]);
            #pragma unroll
            for (int m = 0; m < MT; m++) mma_tf32(acc[m][n], a[m], b0, b1);
        }
    }
}

// ---------------- fp16 MMA helpers (MLP) ----------------
__device__ __forceinline__ void mma_f16(float* c, const uint32_t* a, uint32_t b0, uint32_t b1) {
    asm volatile(
        "mma.sync.aligned.m16n8k16.row.col.f32.f16.f16.f32 "
        "{%0,%1,%2,%3}, {%4,%5,%6,%7}, {%8,%9}, {%0,%1,%2,%3};"
        : "+f"(c[0]), "+f"(c[1]), "+f"(c[2]), "+f"(c[3])
        : "r"(a[0]), "r"(a[1]), "r"(a[2]), "r"(a[3]), "r"(b0), "r"(b1));
}

// C[MT*16 x NT*8] += A @ B^T with fp16 operands, fp32 accum. K = KS*16.
// A: [row][lda halves], B: [n][ldb halves] (both K-contiguous).
template<int MT, int NT, int KS>
__device__ __forceinline__ void wgemm_h(const __half* __restrict__ A, int lda,
                                        const __half* __restrict__ B, int ldb,
                                        float (&acc)[MT][NT][4], int rbase, int nbase,
                                        int g, int i)
{
    #pragma unroll
    for (int ks = 0; ks < KS; ks++) {
        int kc = ks * 16 + 2 * i;
        uint32_t a[MT][4];
        #pragma unroll
        for (int m = 0; m < MT; m++) {
            int r0 = rbase + m * 16 + g;
            a[m][0] = *(const uint32_t*)(A + r0 * lda + kc);
            a[m][1] = *(const uint32_t*)(A + (r0 + 8) * lda + kc);
            a[m][2] = *(const uint32_t*)(A + r0 * lda + kc + 8);
            a[m][3] = *(const uint32_t*)(A + (r0 + 8) * lda + kc + 8);
        }
        #pragma unroll
        for (int n = 0; n < NT; n++) {
            int nc = nbase + n * 8 + g;
            uint32_t b0 = *(const uint32_t*)(B + nc * ldb + kc);
            uint32_t b1 = *(const uint32_t*)(B + nc * ldb + kc + 8);
            #pragma unroll
            for (int m = 0; m < MT; m++) mma_f16(acc[m][n], a[m], b0, b1);
        }
    }
}

// ---------------- weight prep ----------------
__global__ void prep_weights_kernel(const float* __restrict__ qkvw, const float* __restrict__ projw,
                                    const float* __restrict__ fc1w, const float* __restrict__ fc2w) {
    int e4 = blockIdx.x * 256 + threadIdx.x;   // 49152
    if (e4 < 12288) {
        float4 v = *(const float4*)(qkvw + e4 * 4);
        float4 o; o.x = rtf32(v.x); o.y = rtf32(v.y); o.z = rtf32(v.z); o.w = rtf32(v.w);
        *(float4*)(g_qkvw_r + e4 * 4) = o;
    } else if (e4 < 16384) {
        int off = e4 - 12288;
        float4 v = *(const float4*)(projw + off * 4);
        float4 o; o.x = rtf32(v.x); o.y = rtf32(v.y); o.z = rtf32(v.z); o.w = rtf32(v.w);
        *(float4*)(g_projw_r + off * 4) = o;
    } else if (e4 < 32768) {
        int off = e4 - 16384;
        float4 v = *(const float4*)(fc1w + off * 4);
        *(__half2*)(g_fc1w_h + off * 4)     = __floats2half2_rn(v.x, v.y);
        *(__half2*)(g_fc1w_h + off * 4 + 2) = __floats2half2_rn(v.z, v.w);
    } else {
        int off = e4 - 32768;
        float4 v = *(const float4*)(fc2w + off * 4);
        *(__half2*)(g_fc2w_h + off * 4)     = __floats2half2_rn(v.x, v.y);
        *(__half2*)(g_fc2w_h + off * 4 + 2) = __floats2half2_rn(v.z, v.w);
    }
}

// ---------------- RPE bias ----------------
__global__ void bias_table_kernel(const float* __restrict__ w1, const float* __restrict__ b1,
                                  const float* __restrict__ w2) {
    __shared__ float4 red[128];
    int p = blockIdx.x;
    int tid = threadIdx.x;
    int i = p / 15, j = p % 15;
    float v0 = (float)(i - 7) / 7.0f * 8.0f;
    float v1 = (float)(j - 7) / 7.0f * 8.0f;
    float inv_l8 = 1.0f / log2f(8.0f);
    float s0 = (v0 > 0.f) ? 1.f : ((v0 < 0.f) ? -1.f : 0.f);
    float s1 = (v1 > 0.f) ? 1.f : ((v1 < 0.f) ? -1.f : 0.f);
    float x0 = s0 * log2f(fabsf(v0) + 1.0f) * inv_l8;
    float x1 = s1 * log2f(fabsf(v1) + 1.0f) * inv_l8;
    float a0 = 0.f, a1 = 0.f, a2 = 0.f, a3 = 0.f;
    #pragma unroll
    for (int r = 0; r < 4; r++) {
        int h = tid + 128 * r;
        float hid = x0 * w1[2 * h] + x1 * w1[2 * h + 1] + b1[h];
        hid = fmaxf(hid, 0.f);
        a0 += hid * w2[0 * RPE_HID + h];
        a1 += hid * w2[1 * RPE_HID + h];
        a2 += hid * w2[2 * RPE_HID + h];
        a3 += hid * w2[3 * RPE_HID + h];
    }
    red[tid] = make_float4(a0, a1, a2, a3);
    __syncthreads();
    for (int s = 64; s > 0; s >>= 1) {
        if (tid < s) {
            float4 o = red[tid + s];
            red[tid].x += o.x; red[tid].y += o.y; red[tid].z += o.z; red[tid].w += o.w;
        }
        __syncthreads();
    }
    if (tid == 0) {
        g_ttab[p * 4 + 0] = red[0].x; g_ttab[p * 4 + 1] = red[0].y;
        g_ttab[p * 4 + 2] = red[0].z; g_ttab[p * 4 + 3] = red[0].w;
    }
}

__global__ void bias_scatter_kernel() {
    int e = blockIdx.x * 256 + threadIdx.x;
    int h = e >> 12;
    int rem = e & 4095;
    int i = rem >> 6, j = rem & 63;
    int yi = i >> 3, xi = i & 7, yj = j >> 3, xj = j & 7;
    int idx = (yi - yj + 7) * 15 + (xi - xj + 7);
    g_bias[e] = g_ttab[idx * 4 + h];
}

// ---------------- Kernel 2: attention + LN1 + residual (tf32, unchanged from R5) ----------------
__global__ __launch_bounds__(256) void attn_kernel(
    const float* __restrict__ x, const float* __restrict__ qkv_b,
    const float* __restrict__ proj_b,
    const float* __restrict__ n1w, const float* __restrict__ n1b)
{
    extern __shared__ float sm[];
    float* xw = sm;
    float* sb4 = sm;
    float* wb = sm + 8448;
    float* qb = sm + 25344;
    float* ow = qb;
    float* kb = sm + 33792;
    float* vt = sm + 42240;
    float* rsum4 = sm + 50944;
    int* regid = (int*)(rsum4 + 256);
    float* mu = (float*)(regid + 64);
    float* rstd = mu + 64;

    int tid = threadIdx.x;
    int wid = tid >> 5;
    int lane = tid & 31;
    int g = lane >> 2;
    int i = lane & 3;

    int bx = blockIdx.x;
    int bimg = bx >> 6;
    int wh = (bx >> 3) & 7, ww = bx & 7;
    const float* xbase = x + (size_t)bimg * (LSEQ * DIM);

    #pragma unroll
    for (int it = 0; it < 8; it++) {
        int e4 = tid + 256 * it;
        int t = e4 >> 5;
        int c = (e4 & 31) << 2;
        int ti = t >> 3, tj = t & 7;
        int hh = (wh * 8 + ti + 4) & 63;
        int wwp = (ww * 8 + tj + 4) & 63;
        float4 v = *(const float4*)(xbase + (size_t)((hh << 6) + wwp) * DIM + c);
        float* d = xw + t * APAD + c;
        d[0] = rtf32(v.x); d[1] = rtf32(v.y); d[2] = rtf32(v.z); d[3] = rtf32(v.w);
    }
    if (tid < 64) {
        int ti = tid >> 3, tj = tid & 7;
        int ah = wh * 8 + ti, aw = ww * 8 + tj;
        int rh = ah < 56 ? 0 : (ah < 60 ? 1 : 2);
        int rw = aw < 56 ? 0 : (aw < 60 ? 1 : 2);
        regid[tid] = rh * 3 + rw;
    }

    const float scale = 0.17677669529663687f;

    for (int cidx = 0; cidx < 3; cidx++) {
        const float* wsrc = g_qkvw_r + cidx * DIM * DIM;
        #pragma unroll
        for (int it = 0; it < 16; it++) {
            int e4 = tid + 256 * it;
            int r = e4 >> 5;
            int c = (e4 & 31) << 2;
            float4 v = *(const float4*)(wsrc + r * DIM + c);
            float* d = wb + r * APAD + c;
            d[0] = v.x; d[1] = v.y; d[2] = v.z; d[3] = v.w;
        }
        __syncthreads();

        float acc[2][4][4];
        #pragma unroll
        for (int m = 0; m < 2; m++)
            #pragma unroll
            for (int n = 0; n < 4; n++)
                #pragma unroll
                for (int q = 0; q < 4; q++) acc[m][n][q] = 0.f;
        int rbase = (wid >> 2) * 32;
        int nbase = (wid & 3) * 32;
        wgemm<2, 4, 16>(xw, APAD, 0, wb, APAD, 0, acc, rbase, nbase, g, i);

        #pragma unroll
        for (int n = 0; n < 4; n++) {
            int col = nbase + n * 8 + 2 * i;
            float b0f = qkv_b[cidx * DIM + col];
            float b1f = qkv_b[cidx * DIM + col + 1];
            #pragma unroll
            for (int m = 0; m < 2; m++) {
                int row = rbase + m * 16 + g;
                float v0 = acc[m][n][0] + b0f;
                float v1 = acc[m][n][1] + b1f;
                float v2 = acc[m][n][2] + b0f;
                float v3 = acc[m][n][3] + b1f;
                if (cidx == 0) {
                    qb[row * APAD + col]           = rtf32(v0 * scale);
                    qb[row * APAD + col + 1]       = rtf32(v1 * scale);
                    qb[(row + 8) * APAD + col]     = rtf32(v2 * scale);
                    qb[(row + 8) * APAD + col + 1] = rtf32(v3 * scale);
                } else if (cidx == 1) {
                    kb[row * APAD + col]           = rtf32(v0);
                    kb[row * APAD + col + 1]       = rtf32(v1);
                    kb[(row + 8) * APAD + col]     = rtf32(v2);
                    kb[(row + 8) * APAD + col + 1] = rtf32(v3);
                } else {
                    vt[col * VTP + row]           = rtf32(v0);
                    vt[(col + 1) * VTP + row]     = rtf32(v1);
                    vt[col * VTP + row + 8]       = rtf32(v2);
                    vt[(col + 1) * VTP + row + 8] = rtf32(v3);
                }
            }
        }
        __syncthreads();
    }

    {
        int h = wid >> 1;
        int hoff = h * HD;
        int rbase = (wid & 1) * 32;
        float acc[2][8][4];
        #pragma unroll
        for (int m = 0; m < 2; m++)
            #pragma unroll
            for (int n = 0; n < 8; n++)
                #pragma unroll
                for (int q = 0; q < 4; q++) acc[m][n][q] = 0.f;
        wgemm<2, 8, 4>(qb, APAD, hoff, kb, APAD, hoff, acc, rbase, 0, g, i);

        float* sbh = sb4 + h * (64 * SBP);
        const float* gb = g_bias + h * 4096;
        #pragma unroll
        for (int m = 0; m < 2; m++) {
            int row0 = rbase + m * 16 + g;
            int r0 = regid[row0];
            int r1 = regid[row0 + 8];
            #pragma unroll
            for (int n = 0; n < 8; n++) {
                int col = n * 8 + 2 * i;
                int c0 = regid[col], c1 = regid[col + 1];
                float m00 = (r0 != c0) ? -100.f : 0.f;
                float m01 = (r0 != c1) ? -100.f : 0.f;
                float m10 = (r1 != c0) ? -100.f : 0.f;
                float m11 = (r1 != c1) ? -100.f : 0.f;
                sbh[row0 * SBP + col]           = acc[m][n][0] + gb[row0 * 64 + col] + m00;
                sbh[row0 * SBP + col + 1]       = acc[m][n][1] + gb[row0 * 64 + col + 1] + m01;
                sbh[(row0 + 8) * SBP + col]     = acc[m][n][2] + gb[(row0 + 8) * 64 + col] + m10;
                sbh[(row0 + 8) * SBP + col + 1] = acc[m][n][3] + gb[(row0 + 8) * 64 + col + 1] + m11;
            }
        }
    }
    __syncthreads();

    {
        float* rowp = sb4 + (tid >> 6) * (64 * SBP) + (tid & 63) * SBP;
        float mx = -1e30f;
        #pragma unroll 8
        for (int j = 0; j < 64; j++) mx = fmaxf(mx, rowp[j]);
        float s = 0.f;
        #pragma unroll 8
        for (int j = 0; j < 64; j++) {
            float e = __expf(rowp[j] - mx);
            s += e;
            rowp[j] = rtf32(e);
        }
        rsum4[tid] = 1.0f / s;
    }
    __syncthreads();

    {
        int h = wid >> 1;
        int hoff = h * HD;
        int rbase = (wid & 1) * 32;
        float acc[2][4][4];
        #pragma unroll
        for (int m = 0; m < 2; m++)
            #pragma unroll
            for (int n = 0; n < 4; n++)
                #pragma unroll
                for (int q = 0; q < 4; q++) acc[m][n][q] = 0.f;
        wgemm<2, 4, 8>(sb4 + h * (64 * SBP), SBP, 0, vt, VTP, 0, acc, rbase, hoff, g, i);

        #pragma unroll
        for (int m = 0; m < 2; m++) {
            int row = rbase + m * 16 + g;
            float rs0 = rsum4[h * 64 + row];
            float rs1 = rsum4[h * 64 + row + 8];
            #pragma unroll
            for (int n = 0; n < 4; n++) {
                int col = hoff + n * 8 + 2 * i;
                ow[row * APAD + col]           = rtf32(acc[m][n][0] * rs0);
                ow[row * APAD + col + 1]       = rtf32(acc[m][n][1] * rs0);
                ow[(row + 8) * APAD + col]     = rtf32(acc[m][n][2] * rs1);
                ow[(row + 8) * APAD + col + 1] = rtf32(acc[m][n][3] * rs1);
            }
        }
    }
    __syncthreads();

    #pragma unroll
    for (int it = 0; it < 16; it++) {
        int e4 = tid + 256 * it;
        int r = e4 >> 5;
        int c = (e4 & 31) << 2;
        float4 v = *(const float4*)(g_projw_r + r * DIM + c);
        float* d = wb + r * APAD + c;
        d[0] = v.x; d[1] = v.y; d[2] = v.z; d[3] = v.w;
    }
    __syncthreads();

    {
        float acc[2][4][4];
        #pragma unroll
        for (int m = 0; m < 2; m++)
            #pragma unroll
            for (int n = 0; n < 4; n++)
                #pragma unroll
                for (int q = 0; q < 4; q++) acc[m][n][q] = 0.f;
        int rbase = (wid >> 2) * 32;
        int nbase = (wid & 3) * 32;
        wgemm<2, 4, 16>(ow, APAD, 0, wb, APAD, 0, acc, rbase, nbase, g, i);
        #pragma unroll
        for (int n = 0; n < 4; n++) {
            int col = nbase + n * 8 + 2 * i;
            float b0f = proj_b[col];
            float b1f = proj_b[col + 1];
            #pragma unroll
            for (int m = 0; m < 2; m++) {
                int row = rbase + m * 16 + g;
                kb[row * APAD + col]           = acc[m][n][0] + b0f;
                kb[row * APAD + col + 1]       = acc[m][n][1] + b1f;
                kb[(row + 8) * APAD + col]     = acc[m][n][2] + b0f;
                kb[(row + 8) * APAD + col + 1] = acc[m][n][3] + b1f;
            }
        }
    }
    __syncthreads();

    {
        int row = tid >> 2;
        int cb = (tid & 3) * 32;
        float s = 0.f;
        #pragma unroll 8
        for (int c = 0; c < 32; c++) s += kb[row * APAD + cb + c];
        rsum4[tid] = s;
    }
    __syncthreads();
    if (tid < 64) {
        float s = rsum4[4 * tid] + rsum4[4 * tid + 1] + rsum4[4 * tid + 2] + rsum4[4 * tid + 3];
        mu[tid] = s * (1.0f / DIM);
    }
    __syncthreads();
    {
        int row = tid >> 2;
        int cb = (tid & 3) * 32;
        float m = mu[row];
        float v = 0.f;
        #pragma unroll 8
        for (int c = 0; c < 32; c++) {
            float d = kb[row * APAD + cb + c] - m;
            v += d * d;
        }
        rsum4[tid] = v;
    }
    __syncthreads();
    if (tid < 64) {
        float v = rsum4[4 * tid] + rsum4[4 * tid + 1] + rsum4[4 * tid + 2] + rsum4[4 * tid + 3];
        rstd[tid] = rsqrtf(v * (1.0f / DIM) + 1e-5f);
    }
    __syncthreads();

    float* yb = g_ybuf + (size_t)bimg * (LSEQ * DIM);
    #pragma unroll
    for (int it = 0; it < 8; it++) {
        int e4 = tid + 256 * it;
        int t = e4 >> 5;
        int c = (e4 & 31) << 2;
        int ti = t >> 3, tj = t & 7;
        int hh = (wh * 8 + ti + 4) & 63;
        int wwp = (ww * 8 + tj + 4) & 63;
        size_t goff = (size_t)((hh << 6) + wwp) * DIM + c;
        float4 xv = *(const float4*)(xbase + goff);
        float m = mu[t], r = rstd[t];
        float4 o;
        o.x = xv.x + (kb[t * APAD + c + 0] - m) * r * n1w[c + 0] + n1b[c + 0];
        o.y = xv.y + (kb[t * APAD + c + 1] - m) * r * n1w[c + 1] + n1b[c + 1];
        o.z = xv.z + (kb[t * APAD + c + 2] - m) * r * n1w[c + 2] + n1b[c + 2];
        o.w = xv.w + (kb[t * APAD + c + 3] - m) * r * n1w[c + 3] + n1b[c + 3];
        *(float4*)(yb + goff) = o;
    }
}

// ---------------- Kernel 3: MLP + LN2 + residual (fp16 m16n8k16, 128 tok/CTA) ----------------
// smem bytes: Yh @0 [128][136]h (34816) | Wh @34816 (34816) | Hh @69632 (34816) |
//             stats @104448 (ps 256f, mu 128f, rs 128f = 2048)
//             h2 fp32 overlay [128][132] @0 after GEMMs (67584 <= 69632).
#define MLP_SMEM_BYTES 106496

__global__ __launch_bounds__(256) void mlp_kernel(
    const float* __restrict__ fc1b, const float* __restrict__ fc2b,
    const float* __restrict__ n2w, const float* __restrict__ n2b,
    float* __restrict__ out)
{
    extern __shared__ char smc[];
    __half* Yh = (__half*)smc;
    __half* Wh = (__half*)(smc + 34816);
    __half* Hh = (__half*)(smc + 69632);
    float* ps  = (float*)(smc + 104448);
    float* muv = ps + 256;
    float* rsv = muv + 128;
    float* h2  = (float*)smc;   // overlay after GEMMs

    int tid = threadIdx.x;
    int wid = tid >> 5;
    int lane = tid & 31;
    int g = lane >> 2;
    int i = lane & 3;
    int rb = (wid >> 1) * 32;     // 4 M-warps
    int nb = (wid & 1) * 64;      // 2 N-warps

    size_t tok0 = (size_t)blockIdx.x * 128;
    const float* ysrc = g_ybuf + tok0 * DIM;

    // stage Y fp32 -> fp16 [128][YPH]
    #pragma unroll
    for (int it = 0; it < 16; it++) {
        int e4 = tid + 256 * it;
        int t = e4 >> 5;
        int c = (e4 & 31) << 2;
        float4 v = *(const float4*)(ysrc + (size_t)t * DIM + c);
        *(__half2*)(Yh + t * YPH + c)     = __floats2half2_rn(v.x, v.y);
        *(__half2*)(Yh + t * YPH + c + 2) = __floats2half2_rn(v.z, v.w);
    }

    float acc2[2][8][4];
    #pragma unroll
    for (int m = 0; m < 2; m++)
        #pragma unroll
        for (int n = 0; n < 8; n++)
            #pragma unroll
            for (int q = 0; q < 4; q++) acc2[m][n][q] = 0.f;

    const float is2 = 0.70710678118654752f;

    for (int hc = 0; hc < 4; hc++) {
        __syncthreads();   // prior GEMM2 done (Wh, Hh free)
        // stage W1 chunk [128 hid][128 k] fp16
        {
            const __half* src = g_fc1w_h + (size_t)hc * 128 * DIM;
            #pragma unroll
            for (int it = 0; it < 8; it++) {
                int idx = tid + 256 * it;       // 2048 x 16B
                int r = idx >> 4;
                int col = (idx & 15) << 3;
                *(uint4*)(Wh + r * YPH + col) = *(const uint4*)(src + r * DIM + col);
            }
        }
        __syncthreads();

        // GEMM1: H = gelu(Y @ W1c^T + b1), 128x128 k=128
        float acc1[2][8][4];
        #pragma unroll
        for (int m = 0; m < 2; m++)
            #pragma unroll
            for (int n = 0; n < 8; n++)
                #pragma unroll
                for (int q = 0; q < 4; q++) acc1[m][n][q] = 0.f;
        wgemm_h<2, 8, 8>(Yh, YPH, Wh, YPH, acc1, rb, nb, g, i);

        #pragma unroll
        for (int n = 0; n < 8; n++) {
            int col = nb + n * 8 + 2 * i;
            float b0f = fc1b[hc * 128 + col];
            float b1f = fc1b[hc * 128 + col + 1];
            #pragma unroll
            for (int m = 0; m < 2; m++) {
                int row = rb + m * 16 + g;
                float v0 = acc1[m][n][0] + b0f;
                float v1 = acc1[m][n][1] + b1f;
                float v2 = acc1[m][n][2] + b0f;
                float v3 = acc1[m][n][3] + b1f;
                v0 = 0.5f * v0 * (1.0f + erff(v0 * is2));
                v1 = 0.5f * v1 * (1.0f + erff(v1 * is2));
                v2 = 0.5f * v2 * (1.0f + erff(v2 * is2));
                v3 = 0.5f * v3 * (1.0f + erff(v3 * is2));
                *(__half2*)(Hh + row * YPH + col)       = __floats2half2_rn(v0, v1);
                *(__half2*)(Hh + (row + 8) * YPH + col) = __floats2half2_rn(v2, v3);
            }
        }
        __syncthreads();   // GEMM1 + H writes done before Wh overwrite

        // stage W2 chunk [128 dim][128 k-hid] fp16
        {
            const __half* src = g_fc2w_h + hc * 128;
            #pragma unroll
            for (int it = 0; it < 8; it++) {
                int idx = tid + 256 * it;
                int r = idx >> 4;
                int col = (idx & 15) << 3;
                *(uint4*)(Wh + r * YPH + col) = *(const uint4*)(src + (size_t)r * 512 + col);
            }
        }
        __syncthreads();

        // GEMM2: acc2 += H @ W2c^T
        wgemm_h<2, 8, 8>(Hh, YPH, Wh, YPH, acc2, rb, nb, g, i);
    }

    __syncthreads();
    // h2 (+bias) -> fp32 overlay
    #pragma unroll
    for (int n = 0; n < 8; n++) {
        int col = nb + n * 8 + 2 * i;
        float b0f = fc2b[col];
        float b1f = fc2b[col + 1];
        #pragma unroll
        for (int m = 0; m < 2; m++) {
            int row = rb + m * 16 + g;
            h2[row * APAD + col]           = acc2[m][n][0] + b0f;
            h2[row * APAD + col + 1]       = acc2[m][n][1] + b1f;
            h2[(row + 8) * APAD + col]     = acc2[m][n][2] + b0f;
            h2[(row + 8) * APAD + col + 1] = acc2[m][n][3] + b1f;
        }
    }
    __syncthreads();

    // LN2 stats: 2 threads/row
    {
        int row = tid >> 1;
        int cb = (tid & 1) * 64;
        float s = 0.f;
        #pragma unroll 8
        for (int c = 0; c < 64; c++) s += h2[row * APAD + cb + c];
        ps[tid] = s;
    }
    __syncthreads();
    if (tid < 128) muv[tid] = (ps[2 * tid] + ps[2 * tid + 1]) * (1.0f / DIM);
    __syncthreads();
    {
        int row = tid >> 1;
        int cb = (tid & 1) * 64;
        float m = muv[row];
        float v = 0.f;
        #pragma unroll 8
        for (int c = 0; c < 64; c++) {
            float d = h2[row * APAD + cb + c] - m;
            v += d * d;
        }
        ps[tid] = v;
    }
    __syncthreads();
    if (tid < 128) rsv[tid] = rsqrtf((ps[2 * tid] + ps[2 * tid + 1]) * (1.0f / DIM) + 1e-5f);
    __syncthreads();

    // out = y(gmem) + LN(h2)
    float* od = out + tok0 * DIM;
    #pragma unroll
    for (int it = 0; it < 16; it++) {
        int e4 = tid + 256 * it;
        int t = e4 >> 5;
        int c = (e4 & 31) << 2;
        float4 yv = *(const float4*)(ysrc + (size_t)t * DIM + c);
        float m = muv[t], r = rsv[t];
        float4 o;
        o.x = yv.x + (h2[t * APAD + c + 0] - m) * r * n2w[c + 0] + n2b[c + 0];
        o.y = yv.y + (h2[t * APAD + c + 1] - m) * r * n2w[c + 1] + n2b[c + 1];
        o.z = yv.z + (h2[t * APAD + c + 2] - m) * r * n2w[c + 2] + n2b[c + 2];
        o.w = yv.w + (h2[t * APAD + c + 3] - m) * r * n2w[c + 3] + n2b[c + 3];
        *(float4*)(od + (size_t)t * DIM + c) = o;
    }
}

static const int ATTN_SMEM = (50944 + 256 + 64 + 64 + 64) * 4;

extern "C" void kernel_launch(void* const* d_in, const int* in_sizes, int n_in,
                              void* d_out, int out_size) {
    const float* x      = (const float*)d_in[0];
    const float* qkv_w  = (const float*)d_in[1];
    const float* qkv_b  = (const float*)d_in[2];
    const float* proj_w = (const float*)d_in[3];
    const float* proj_b = (const float*)d_in[4];
    const float* rpe_w1 = (const float*)d_in[5];
    const float* rpe_b1 = (const float*)d_in[6];
    const float* rpe_w2 = (const float*)d_in[7];
    const float* n1w    = (const float*)d_in[8];
    const float* n1b    = (const float*)d_in[9];
    const float* fc1w   = (const float*)d_in[10];
    const float* fc1b   = (const float*)d_in[11];
    const float* fc2w   = (const float*)d_in[12];
    const float* fc2b   = (const float*)d_in[13];
    const float* n2w    = (const float*)d_in[14];
    const float* n2b    = (const float*)d_in[15];
    float* out = (float*)d_out;

    cudaFuncSetAttribute(attn_kernel, cudaFuncAttributeMaxDynamicSharedMemorySize, ATTN_SMEM);
    cudaFuncSetAttribute(mlp_kernel,  cudaFuncAttributeMaxDynamicSharedMemorySize, MLP_SMEM_BYTES);

    prep_weights_kernel<<<192, 256>>>(qkv_w, proj_w, fc1w, fc2w);
    bias_table_kernel<<<225, 128>>>(rpe_w1, rpe_b1, rpe_w2);
    bias_scatter_kernel<<<64, 256>>>();
    attn_kernel<<<2048, 256, ATTN_SMEM>>>(x, qkv_b, proj_b, n1w, n1b);
    mlp_kernel<<<1024, 256, MLP_SMEM_BYTES>>>(fc1b, fc2b, n2w, n2b, out);
}

// round 9
// speedup vs baseline: 1.5650x; 1.2135x over previous
#include <cuda_runtime.h>
#include <cuda_fp16.h>
#include <math.h>
#include <stdint.h>

#define WSZ 8
#define NHEAD 4
#define DIM 128
#define NTOK 64
#define HD 32
#define BATCH 32
#define HW 64
#define LSEQ 4096
#define RPE_HID 512
#define APAD 132
#define YPH 136    // fp16 smem pitch (halves) -> bank (4*row+i)%32, conflict-free
#define PPH 72     // P / Vt fp16 pitch (halves) -> bank (4*row+i)%32, conflict-free

__device__ float g_bias[NHEAD * NTOK * NTOK];
__device__ float g_ttab[225 * NHEAD];
__device__ float g_ybuf[(size_t)BATCH * LSEQ * DIM];
__device__ __half g_qkvw_h[3 * DIM * DIM];
__device__ __half g_projw_h[DIM * DIM];
__device__ __half g_fc1w_h[512 * DIM];
__device__ __half g_fc2w_h[DIM * 512];

// ---------------- fp16 MMA helpers ----------------
__device__ __forceinline__ void mma_f16(float* c, const uint32_t* a, uint32_t b0, uint32_t b1) {
    asm volatile(
        "mma.sync.aligned.m16n8k16.row.col.f32.f16.f16.f32 "
        "{%0,%1,%2,%3}, {%4,%5,%6,%7}, {%8,%9}, {%0,%1,%2,%3};"
        : "+f"(c[0]), "+f"(c[1]), "+f"(c[2]), "+f"(c[3])
        : "r"(a[0]), "r"(a[1]), "r"(a[2]), "r"(a[3]), "r"(b0), "r"(b1));
}

// C[MT*16 x NT*8] += A @ B^T, fp16 operands, fp32 accum. K = KS*16.
template<int MT, int NT, int KS>
__device__ __forceinline__ void wgemm_h(const __half* __restrict__ A, int lda,
                                        const __half* __restrict__ B, int ldb,
                                        float (&acc)[MT][NT][4], int rbase, int nbase,
                                        int g, int i)
{
    #pragma unroll
    for (int ks = 0; ks < KS; ks++) {
        int kc = ks * 16 + 2 * i;
        uint32_t a[MT][4];
        #pragma unroll
        for (int m = 0; m < MT; m++) {
            int r0 = rbase + m * 16 + g;
            a[m][0] = *(const uint32_t*)(A + r0 * lda + kc);
            a[m][1] = *(const uint32_t*)(A + (r0 + 8) * lda + kc);
            a[m][2] = *(const uint32_t*)(A + r0 * lda + kc + 8);
            a[m][3] = *(const uint32_t*)(A + (r0 + 8) * lda + kc + 8);
        }
        #pragma unroll
        for (int n = 0; n < NT; n++) {
            int nc = nbase + n * 8 + g;
            uint32_t b0 = *(const uint32_t*)(B + nc * ldb + kc);
            uint32_t b1 = *(const uint32_t*)(B + nc * ldb + kc + 8);
            #pragma unroll
            for (int m = 0; m < MT; m++) mma_f16(acc[m][n], a[m], b0, b1);
        }
    }
}

// ---------------- weight prep: everything to fp16 ----------------
__global__ void prep_weights_kernel(const float* __restrict__ qkvw, const float* __restrict__ projw,
                                    const float* __restrict__ fc1w, const float* __restrict__ fc2w) {
    int e4 = blockIdx.x * 256 + threadIdx.x;   // 49152
    const float* src;
    __half* dst;
    int off;
    if (e4 < 12288)      { src = qkvw;  dst = g_qkvw_h;  off = e4; }
    else if (e4 < 16384) { src = projw; dst = g_projw_h; off = e4 - 12288; }
    else if (e4 < 32768) { src = fc1w;  dst = g_fc1w_h;  off = e4 - 16384; }
    else                 { src = fc2w;  dst = g_fc2w_h;  off = e4 - 32768; }
    float4 v = *(const float4*)(src + off * 4);
    *(__half2*)(dst + off * 4)     = __floats2half2_rn(v.x, v.y);
    *(__half2*)(dst + off * 4 + 2) = __floats2half2_rn(v.z, v.w);
}

// ---------------- RPE bias ----------------
__global__ void bias_table_kernel(const float* __restrict__ w1, const float* __restrict__ b1,
                                  const float* __restrict__ w2) {
    __shared__ float4 red[128];
    int p = blockIdx.x;
    int tid = threadIdx.x;
    int i = p / 15, j = p % 15;
    float v0 = (float)(i - 7) / 7.0f * 8.0f;
    float v1 = (float)(j - 7) / 7.0f * 8.0f;
    float inv_l8 = 1.0f / log2f(8.0f);
    float s0 = (v0 > 0.f) ? 1.f : ((v0 < 0.f) ? -1.f : 0.f);
    float s1 = (v1 > 0.f) ? 1.f : ((v1 < 0.f) ? -1.f : 0.f);
    float x0 = s0 * log2f(fabsf(v0) + 1.0f) * inv_l8;
    float x1 = s1 * log2f(fabsf(v1) + 1.0f) * inv_l8;
    float a0 = 0.f, a1 = 0.f, a2 = 0.f, a3 = 0.f;
    #pragma unroll
    for (int r = 0; r < 4; r++) {
        int h = tid + 128 * r;
        float hid = x0 * w1[2 * h] + x1 * w1[2 * h + 1] + b1[h];
        hid = fmaxf(hid, 0.f);
        a0 += hid * w2[0 * RPE_HID + h];
        a1 += hid * w2[1 * RPE_HID + h];
        a2 += hid * w2[2 * RPE_HID + h];
        a3 += hid * w2[3 * RPE_HID + h];
    }
    red[tid] = make_float4(a0, a1, a2, a3);
    __syncthreads();
    for (int s = 64; s > 0; s >>= 1) {
        if (tid < s) {
            float4 o = red[tid + s];
            red[tid].x += o.x; red[tid].y += o.y; red[tid].z += o.z; red[tid].w += o.w;
        }
        __syncthreads();
    }
    if (tid == 0) {
        g_ttab[p * 4 + 0] = red[0].x; g_ttab[p * 4 + 1] = red[0].y;
        g_ttab[p * 4 + 2] = red[0].z; g_ttab[p * 4 + 3] = red[0].w;
    }
}

__global__ void bias_scatter_kernel() {
    int e = blockIdx.x * 256 + threadIdx.x;
    int h = e >> 12;
    int rem = e & 4095;
    int i = rem >> 6, j = rem & 63;
    int yi = i >> 3, xi = i & 7, yj = j >> 3, xj = j & 7;
    int idx = (yi - yj + 7) * 15 + (xi - xj + 7);
    g_bias[e] = g_ttab[idx * 4 + h];
}

// ---------------- Kernel 2: attention + LN1 + residual (fp16, register softmax) ----------------
// smem bytes:
//   xw_h  @0      [64][136]h (17408)  -- reused as ow_h (attn out)
//   wb_h  @17408  [128][136]h (34816) -- qkv chunks, then proj_w
//   qb_h  @52224  [64][136]h (17408)  -- with kb_h, overlaid by proj fp32 out [64][132] (33792)
//   kb_h  @69632  [64][136]h (17408)
//   vt_h  @87040  [128][72]h (18432)  -- V transposed [dim][tok]
//   P_h   @105472 [4][64][72]h (36864) -- exp(scores)
//   rsum4 @142336 [256]f | regid @143360 [64]i | mu @143616 | rstd @143872
#define AT_XW 0
#define AT_WB 17408
#define AT_QB 52224
#define AT_KB 69632
#define AT_VT 87040
#define AT_P  105472
#define AT_RS 142336
#define AT_RG 143360
#define AT_MU 143616
#define AT_RSTD 143872
#define ATTN_SMEM_BYTES 144128

__global__ __launch_bounds__(256) void attn_kernel(
    const float* __restrict__ x, const float* __restrict__ qkv_b,
    const float* __restrict__ proj_b,
    const float* __restrict__ n1w, const float* __restrict__ n1b)
{
    extern __shared__ char smc[];
    __half* xw = (__half*)(smc + AT_XW);
    __half* ow = xw;
    __half* wb = (__half*)(smc + AT_WB);
    __half* qb = (__half*)(smc + AT_QB);
    __half* kb = (__half*)(smc + AT_KB);
    __half* vt = (__half*)(smc + AT_VT);
    __half* Ph = (__half*)(smc + AT_P);
    float* rsum4 = (float*)(smc + AT_RS);
    int* regid = (int*)(smc + AT_RG);
    float* mu = (float*)(smc + AT_MU);
    float* rstd = (float*)(smc + AT_RSTD);
    float* projf = (float*)(smc + AT_QB);   // overlay, pitch APAD

    int tid = threadIdx.x;
    int wid = tid >> 5;
    int lane = tid & 31;
    int g = lane >> 2;
    int i = lane & 3;

    int bx = blockIdx.x;
    int bimg = bx >> 6;
    int wh = (bx >> 3) & 7, ww = bx & 7;
    const float* xbase = x + (size_t)bimg * (LSEQ * DIM);

    // ---- load window (rolled -4) -> fp16 ----
    #pragma unroll
    for (int it = 0; it < 8; it++) {
        int e4 = tid + 256 * it;
        int t = e4 >> 5;
        int c = (e4 & 31) << 2;
        int ti = t >> 3, tj = t & 7;
        int hh = (wh * 8 + ti + 4) & 63;
        int wwp = (ww * 8 + tj + 4) & 63;
        float4 v = *(const float4*)(xbase + (size_t)((hh << 6) + wwp) * DIM + c);
        *(__half2*)(xw + t * YPH + c)     = __floats2half2_rn(v.x, v.y);
        *(__half2*)(xw + t * YPH + c + 2) = __floats2half2_rn(v.z, v.w);
    }
    if (tid < 64) {
        int ti = tid >> 3, tj = tid & 7;
        int ah = wh * 8 + ti, aw = ww * 8 + tj;
        int rh = ah < 56 ? 0 : (ah < 60 ? 1 : 2);
        int rw = aw < 56 ? 0 : (aw < 60 ? 1 : 2);
        regid[tid] = rh * 3 + rw;
    }

    const float scale = 0.17677669529663687f;

    // ---- QKV: 3 GEMMs 64x128 k=128 fp16, 8 warps 2Mx4N ----
    for (int cidx = 0; cidx < 3; cidx++) {
        const __half* wsrc = g_qkvw_h + cidx * DIM * DIM;
        #pragma unroll
        for (int it = 0; it < 8; it++) {
            int idx = tid + 256 * it;            // 2048 x 16B
            int r = idx >> 4;
            int col = (idx & 15) << 3;
            *(uint4*)(wb + r * YPH + col) = *(const uint4*)(wsrc + r * DIM + col);
        }
        __syncthreads();

        float acc[2][4][4];
        #pragma unroll
        for (int m = 0; m < 2; m++)
            #pragma unroll
            for (int n = 0; n < 4; n++)
                #pragma unroll
                for (int q = 0; q < 4; q++) acc[m][n][q] = 0.f;
        int rbase = (wid >> 2) * 32;
        int nbase = (wid & 3) * 32;
        wgemm_h<2, 4, 8>(xw, YPH, wb, YPH, acc, rbase, nbase, g, i);

        #pragma unroll
        for (int n = 0; n < 4; n++) {
            int col = nbase + n * 8 + 2 * i;
            float b0f = qkv_b[cidx * DIM + col];
            float b1f = qkv_b[cidx * DIM + col + 1];
            #pragma unroll
            for (int m = 0; m < 2; m++) {
                int row = rbase + m * 16 + g;
                float v0 = acc[m][n][0] + b0f;
                float v1 = acc[m][n][1] + b1f;
                float v2 = acc[m][n][2] + b0f;
                float v3 = acc[m][n][3] + b1f;
                if (cidx == 0) {
                    *(__half2*)(qb + row * YPH + col)       = __floats2half2_rn(v0 * scale, v1 * scale);
                    *(__half2*)(qb + (row + 8) * YPH + col) = __floats2half2_rn(v2 * scale, v3 * scale);
                } else if (cidx == 1) {
                    *(__half2*)(kb + row * YPH + col)       = __floats2half2_rn(v0, v1);
                    *(__half2*)(kb + (row + 8) * YPH + col) = __floats2half2_rn(v2, v3);
                } else {
                    vt[col * PPH + row]           = __float2half_rn(v0);
                    vt[(col + 1) * PPH + row]     = __float2half_rn(v1);
                    vt[col * PPH + row + 8]       = __float2half_rn(v2);
                    vt[(col + 1) * PPH + row + 8] = __float2half_rn(v3);
                }
            }
        }
        __syncthreads();
    }

    // ---- scores + in-register softmax: 4 heads x 2 warps, warp = 32 rows x 64 cols, k=32 ----
    int h = wid >> 1;
    int hoff = h * HD;
    int rbase_h = (wid & 1) * 32;
    {
        float s[2][8][4];
        #pragma unroll
        for (int m = 0; m < 2; m++)
            #pragma unroll
            for (int n = 0; n < 8; n++)
                #pragma unroll
                for (int q = 0; q < 4; q++) s[m][n][q] = 0.f;
        wgemm_h<2, 8, 2>(qb + hoff, YPH, kb + hoff, YPH, s, rbase_h, 0, g, i);

        const float* gb = g_bias + h * 4096;
        __half* Prow = Ph + h * (64 * PPH);
        // mask regids for this thread's 16 columns
        int cmask[8][2];
        #pragma unroll
        for (int n = 0; n < 8; n++) {
            cmask[n][0] = regid[n * 8 + 2 * i];
            cmask[n][1] = regid[n * 8 + 2 * i + 1];
        }
        #pragma unroll
        for (int m = 0; m < 2; m++) {
            #pragma unroll
            for (int ss = 0; ss < 2; ss++) {
                int row = rbase_h + m * 16 + 8 * ss + g;
                int rreg = regid[row];
                const float* gbr = gb + row * 64;
                float v[16];
                float mx = -1e30f;
                #pragma unroll
                for (int n = 0; n < 8; n++) {
                    int col = n * 8 + 2 * i;
                    float a0 = s[m][n][2 * ss]     + gbr[col]     + ((rreg != cmask[n][0]) ? -100.f : 0.f);
                    float a1 = s[m][n][2 * ss + 1] + gbr[col + 1] + ((rreg != cmask[n][1]) ? -100.f : 0.f);
                    v[2 * n] = a0; v[2 * n + 1] = a1;
                    mx = fmaxf(mx, fmaxf(a0, a1));
                }
                mx = fmaxf(mx, __shfl_xor_sync(0xFFFFFFFF, mx, 1));
                mx = fmaxf(mx, __shfl_xor_sync(0xFFFFFFFF, mx, 2));
                float sum = 0.f;
                #pragma unroll
                for (int n = 0; n < 8; n++) {
                    float e0 = __expf(v[2 * n] - mx);
                    float e1 = __expf(v[2 * n + 1] - mx);
                    sum += e0 + e1;
                    *(__half2*)(Prow + row * PPH + n * 8 + 2 * i) = __floats2half2_rn(e0, e1);
                }
                sum += __shfl_xor_sync(0xFFFFFFFF, sum, 1);
                sum += __shfl_xor_sync(0xFFFFFFFF, sum, 2);
                if (i == 0) rsum4[h * 64 + row] = 1.0f / sum;
            }
        }
    }
    __syncwarp();

    // ---- PV: warp = 32 rows x 32 head-dims, k=64 ----
    {
        float o[2][4][4];
        #pragma unroll
        for (int m = 0; m < 2; m++)
            #pragma unroll
            for (int n = 0; n < 4; n++)
                #pragma unroll
                for (int q = 0; q < 4; q++) o[m][n][q] = 0.f;
        wgemm_h<2, 4, 4>(Ph + h * (64 * PPH), PPH, vt + hoff * PPH, PPH, o, rbase_h, 0, g, i);

        #pragma unroll
        for (int m = 0; m < 2; m++) {
            int row = rbase_h + m * 16 + g;
            float rs0 = rsum4[h * 64 + row];
            float rs1 = rsum4[h * 64 + row + 8];
            #pragma unroll
            for (int n = 0; n < 4; n++) {
                int col = hoff + n * 8 + 2 * i;
                *(__half2*)(ow + row * YPH + col)       = __floats2half2_rn(o[m][n][0] * rs0, o[m][n][1] * rs0);
                *(__half2*)(ow + (row + 8) * YPH + col) = __floats2half2_rn(o[m][n][2] * rs1, o[m][n][3] * rs1);
            }
        }
    }
    __syncthreads();

    // ---- stage proj_w fp16 ----
    #pragma unroll
    for (int it = 0; it < 8; it++) {
        int idx = tid + 256 * it;
        int r = idx >> 4;
        int col = (idx & 15) << 3;
        *(uint4*)(wb + r * YPH + col) = *(const uint4*)(g_projw_h + r * DIM + col);
    }
    __syncthreads();

    // ---- proj GEMM 64x128 k=128 -> fp32 projf ----
    {
        float acc[2][4][4];
        #pragma unroll
        for (int m = 0; m < 2; m++)
            #pragma unroll
            for (int n = 0; n < 4; n++)
                #pragma unroll
                for (int q = 0; q < 4; q++) acc[m][n][q] = 0.f;
        int rbase = (wid >> 2) * 32;
        int nbase = (wid & 3) * 32;
        wgemm_h<2, 4, 8>(ow, YPH, wb, YPH, acc, rbase, nbase, g, i);
        #pragma unroll
        for (int n = 0; n < 4; n++) {
            int col = nbase + n * 8 + 2 * i;
            float b0f = proj_b[col];
            float b1f = proj_b[col + 1];
            #pragma unroll
            for (int m = 0; m < 2; m++) {
                int row = rbase + m * 16 + g;
                projf[row * APAD + col]           = acc[m][n][0] + b0f;
                projf[row * APAD + col + 1]       = acc[m][n][1] + b1f;
                projf[(row + 8) * APAD + col]     = acc[m][n][2] + b0f;
                projf[(row + 8) * APAD + col + 1] = acc[m][n][3] + b1f;
            }
        }
    }
    __syncthreads();

    // ---- LN1 stats: 4 threads/row ----
    {
        int row = tid >> 2;
        int cb = (tid & 3) * 32;
        float s = 0.f;
        #pragma unroll 8
        for (int c = 0; c < 32; c++) s += projf[row * APAD + cb + c];
        rsum4[tid] = s;
    }
    __syncthreads();
    if (tid < 64) {
        float s = rsum4[4 * tid] + rsum4[4 * tid + 1] + rsum4[4 * tid + 2] + rsum4[4 * tid + 3];
        mu[tid] = s * (1.0f / DIM);
    }
    __syncthreads();
    {
        int row = tid >> 2;
        int cb = (tid & 3) * 32;
        float m = mu[row];
        float v = 0.f;
        #pragma unroll 8
        for (int c = 0; c < 32; c++) {
            float d = projf[row * APAD + cb + c] - m;
            v += d * d;
        }
        rsum4[tid] = v;
    }
    __syncthreads();
    if (tid < 64) {
        float v = rsum4[4 * tid] + rsum4[4 * tid + 1] + rsum4[4 * tid + 2] + rsum4[4 * tid + 3];
        rstd[tid] = rsqrtf(v * (1.0f / DIM) + 1e-5f);
    }
    __syncthreads();

    // ---- y = x + LN(proj) ----
    float* yb = g_ybuf + (size_t)bimg * (LSEQ * DIM);
    #pragma unroll
    for (int it = 0; it < 8; it++) {
        int e4 = tid + 256 * it;
        int t = e4 >> 5;
        int c = (e4 & 31) << 2;
        int ti = t >> 3, tj = t & 7;
        int hh = (wh * 8 + ti + 4) & 63;
        int wwp = (ww * 8 + tj + 4) & 63;
        size_t goff = (size_t)((hh << 6) + wwp) * DIM + c;
        float4 xv = *(const float4*)(xbase + goff);
        float m = mu[t], r = rstd[t];
        float4 o;
        o.x = xv.x + (projf[t * APAD + c + 0] - m) * r * n1w[c + 0] + n1b[c + 0];
        o.y = xv.y + (projf[t * APAD + c + 1] - m) * r * n1w[c + 1] + n1b[c + 1];
        o.z = xv.z + (projf[t * APAD + c + 2] - m) * r * n1w[c + 2] + n1b[c + 2];
        o.w = xv.w + (projf[t * APAD + c + 3] - m) * r * n1w[c + 3] + n1b[c + 3];
        *(float4*)(yb + goff) = o;
    }
}

// ---------------- Kernel 3: MLP + LN2 + residual (fp16, unchanged from R7) ----------------
#define MLP_SMEM_BYTES 106496

__global__ __launch_bounds__(256) void mlp_kernel(
    const float* __restrict__ fc1b, const float* __restrict__ fc2b,
    const float* __restrict__ n2w, const float* __restrict__ n2b,
    float* __restrict__ out)
{
    extern __shared__ char smc[];
    __half* Yh = (__half*)smc;
    __half* Wh = (__half*)(smc + 34816);
    __half* Hh = (__half*)(smc + 69632);
    float* ps  = (float*)(smc + 104448);
    float* muv = ps + 256;
    float* rsv = muv + 128;
    float* h2  = (float*)smc;

    int tid = threadIdx.x;
    int wid = tid >> 5;
    int lane = tid & 31;
    int g = lane >> 2;
    int i = lane & 3;
    int rb = (wid >> 1) * 32;
    int nb = (wid & 1) * 64;

    size_t tok0 = (size_t)blockIdx.x * 128;
    const float* ysrc = g_ybuf + tok0 * DIM;

    #pragma unroll
    for (int it = 0; it < 16; it++) {
        int e4 = tid + 256 * it;
        int t = e4 >> 5;
        int c = (e4 & 31) << 2;
        float4 v = *(const float4*)(ysrc + (size_t)t * DIM + c);
        *(__half2*)(Yh + t * YPH + c)     = __floats2half2_rn(v.x, v.y);
        *(__half2*)(Yh + t * YPH + c + 2) = __floats2half2_rn(v.z, v.w);
    }

    float acc2[2][8][4];
    #pragma unroll
    for (int m = 0; m < 2; m++)
        #pragma unroll
        for (int n = 0; n < 8; n++)
            #pragma unroll
            for (int q = 0; q < 4; q++) acc2[m][n][q] = 0.f;

    const float is2 = 0.70710678118654752f;

    for (int hc = 0; hc < 4; hc++) {
        __syncthreads();
        {
            const __half* src = g_fc1w_h + (size_t)hc * 128 * DIM;
            #pragma unroll
            for (int it = 0; it < 8; it++) {
                int idx = tid + 256 * it;
                int r = idx >> 4;
                int col = (idx & 15) << 3;
                *(uint4*)(Wh + r * YPH + col) = *(const uint4*)(src + r * DIM + col);
            }
        }
        __syncthreads();

        float acc1[2][8][4];
        #pragma unroll
        for (int m = 0; m < 2; m++)
            #pragma unroll
            for (int n = 0; n < 8; n++)
                #pragma unroll
                for (int q = 0; q < 4; q++) acc1[m][n][q] = 0.f;
        wgemm_h<2, 8, 8>(Yh, YPH, Wh, YPH, acc1, rb, nb, g, i);

        #pragma unroll
        for (int n = 0; n < 8; n++) {
            int col = nb + n * 8 + 2 * i;
            float b0f = fc1b[hc * 128 + col];
            float b1f = fc1b[hc * 128 + col + 1];
            #pragma unroll
            for (int m = 0; m < 2; m++) {
                int row = rb + m * 16 + g;
                float v0 = acc1[m][n][0] + b0f;
                float v1 = acc1[m][n][1] + b1f;
                float v2 = acc1[m][n][2] + b0f;
                float v3 = acc1[m][n][3] + b1f;
                v0 = 0.5f * v0 * (1.0f + erff(v0 * is2));
                v1 = 0.5f * v1 * (1.0f + erff(v1 * is2));
                v2 = 0.5f * v2 * (1.0f + erff(v2 * is2));
                v3 = 0.5f * v3 * (1.0f + erff(v3 * is2));
                *(__half2*)(Hh + row * YPH + col)       = __floats2half2_rn(v0, v1);
                *(__half2*)(Hh + (row + 8) * YPH + col) = __floats2half2_rn(v2, v3);
            }
        }
        __syncthreads();

        {
            const __half* src = g_fc2w_h + hc * 128;
            #pragma unroll
            for (int it = 0; it < 8; it++) {
                int idx = tid + 256 * it;
                int r = idx >> 4;
                int col = (idx & 15) << 3;
                *(uint4*)(Wh + r * YPH + col) = *(const uint4*)(src + (size_t)r * 512 + col);
            }
        }
        __syncthreads();

        wgemm_h<2, 8, 8>(Hh, YPH, Wh, YPH, acc2, rb, nb, g, i);
    }

    __syncthreads();
    #pragma unroll
    for (int n = 0; n < 8; n++) {
        int col = nb + n * 8 + 2 * i;
        float b0f = fc2b[col];
        float b1f = fc2b[col + 1];
        #pragma unroll
        for (int m = 0; m < 2; m++) {
            int row = rb + m * 16 + g;
            h2[row * APAD + col]           = acc2[m][n][0] + b0f;
            h2[row * APAD + col + 1]       = acc2[m][n][1] + b1f;
            h2[(row + 8) * APAD + col]     = acc2[m][n][2] + b0f;
            h2[(row + 8) * APAD + col + 1] = acc2[m][n][3] + b1f;
        }
    }
    __syncthreads();

    {
        int row = tid >> 1;
        int cb = (tid & 1) * 64;
        float s = 0.f;
        #pragma unroll 8
        for (int c = 0; c < 64; c++) s += h2[row * APAD + cb + c];
        ps[tid] = s;
    }
    __syncthreads();
    if (tid < 128) muv[tid] = (ps[2 * tid] + ps[2 * tid + 1]) * (1.0f / DIM);
    __syncthreads();
    {
        int row = tid >> 1;
        int cb = (tid & 1) * 64;
        float m = muv[row];
        float v = 0.f;
        #pragma unroll 8
        for (int c = 0; c < 64; c++) {
            float d = h2[row * APAD + cb + c] - m;
            v += d * d;
        }
        ps[tid] = v;
    }
    __syncthreads();
    if (tid < 128) rsv[tid] = rsqrtf((ps[2 * tid] + ps[2 * tid + 1]) * (1.0f / DIM) + 1e-5f);
    __syncthreads();

    float* od = out + tok0 * DIM;
    #pragma unroll
    for (int it = 0; it < 16; it++) {
        int e4 = tid + 256 * it;
        int t = e4 >> 5;
        int c = (e4 & 31) << 2;
        float4 yv = *(const float4*)(ysrc + (size_t)t * DIM + c);
        float m = muv[t], r = rsv[t];
        float4 o;
        o.x = yv.x + (h2[t * APAD + c + 0] - m) * r * n2w[c + 0] + n2b[c + 0];
        o.y = yv.y + (h2[t * APAD + c + 1] - m) * r * n2w[c + 1] + n2b[c + 1];
        o.z = yv.z + (h2[t * APAD + c + 2] - m) * r * n2w[c + 2] + n2b[c + 2];
        o.w = yv.w + (h2[t * APAD + c + 3] - m) * r * n2w[c + 3] + n2b[c + 3];
        *(float4*)(od + (size_t)t * DIM + c) = o;
    }
}

extern "C" void kernel_launch(void* const* d_in, const int* in_sizes, int n_in,
                              void* d_out, int out_size) {
    const float* x      = (const float*)d_in[0];
    const float* qkv_w  = (const float*)d_in[1];
    const float* qkv_b  = (const float*)d_in[2];
    const float* proj_w = (const float*)d_in[3];
    const float* proj_b = (const float*)d_in[4];
    const float* rpe_w1 = (const float*)d_in[5];
    const float* rpe_b1 = (const float*)d_in[6];
    const float* rpe_w2 = (const float*)d_in[7];
    const float* n1w    = (const float*)d_in[8];
    const float* n1b    = (const float*)d_in[9];
    const float* fc1w   = (const float*)d_in[10];
    const float* fc1b   = (const float*)d_in[11];
    const float* fc2w   = (const float*)d_in[12];
    const float* fc2b   = (const float*)d_in[13];
    const float* n2w    = (const float*)d_in[14];
    const float* n2b    = (const float*)d_in[15];
    float* out = (float*)d_out;

    cudaFuncSetAttribute(attn_kernel, cudaFuncAttributeMaxDynamicSharedMemorySize, ATTN_SMEM_BYTES);
    cudaFuncSetAttribute(mlp_kernel,  cudaFuncAttributeMaxDynamicSharedMemorySize, MLP_SMEM_BYTES);

    prep_weights_kernel<<<192, 256>>>(qkv_w, proj_w, fc1w, fc2w);
    bias_table_kernel<<<225, 128>>>(rpe_w1, rpe_b1, rpe_w2);
    bias_scatter_kernel<<<64, 256>>>();
    attn_kernel<<<2048, 256, ATTN_SMEM_BYTES>>>(x, qkv_b, proj_b, n1w, n1b);
    mlp_kernel<<<1024, 256, MLP_SMEM_BYTES>>>(fc1b, fc2b, n2w, n2b, out);
}

// round 10
// speedup vs baseline: 1.6637x; 1.0631x over previous
#include <cuda_runtime.h>
#include <cuda_fp16.h>
#include <math.h>
#include <stdint.h>

#define WSZ 8
#define NHEAD 4
#define DIM 128
#define NTOK 64
#define HD 32
#define BATCH 32
#define HW 64
#define LSEQ 4096
#define RPE_HID 512
#define APAD 132
#define YPH 136    // fp16 smem pitch (halves) -> bank (4*row+i)%32, conflict-free
#define PPH 72     // Vt fp16 pitch (halves) -> conflict-free

__device__ float g_bias[NHEAD * NTOK * NTOK];
__device__ float g_ttab[225 * NHEAD];
__device__ float g_ybuf[(size_t)BATCH * LSEQ * DIM];
__device__ __half g_qkvw_h[3 * DIM * DIM];
__device__ __half g_projw_h[DIM * DIM];
__device__ __half g_fc1w_h[512 * DIM];
__device__ __half g_fc2w_h[DIM * 512];

// ---------------- fp16 MMA helpers ----------------
__device__ __forceinline__ void mma_f16(float* c, const uint32_t* a, uint32_t b0, uint32_t b1) {
    asm volatile(
        "mma.sync.aligned.m16n8k16.row.col.f32.f16.f16.f32 "
        "{%0,%1,%2,%3}, {%4,%5,%6,%7}, {%8,%9}, {%0,%1,%2,%3};"
        : "+f"(c[0]), "+f"(c[1]), "+f"(c[2]), "+f"(c[3])
        : "r"(a[0]), "r"(a[1]), "r"(a[2]), "r"(a[3]), "r"(b0), "r"(b1));
}

template<int MT, int NT, int KS>
__device__ __forceinline__ void wgemm_h(const __half* __restrict__ A, int lda,
                                        const __half* __restrict__ B, int ldb,
                                        float (&acc)[MT][NT][4], int rbase, int nbase,
                                        int g, int i)
{
    #pragma unroll
    for (int ks = 0; ks < KS; ks++) {
        int kc = ks * 16 + 2 * i;
        uint32_t a[MT][4];
        #pragma unroll
        for (int m = 0; m < MT; m++) {
            int r0 = rbase + m * 16 + g;
            a[m][0] = *(const uint32_t*)(A + r0 * lda + kc);
            a[m][1] = *(const uint32_t*)(A + (r0 + 8) * lda + kc);
            a[m][2] = *(const uint32_t*)(A + r0 * lda + kc + 8);
            a[m][3] = *(const uint32_t*)(A + (r0 + 8) * lda + kc + 8);
        }
        #pragma unroll
        for (int n = 0; n < NT; n++) {
            int nc = nbase + n * 8 + g;
            uint32_t b0 = *(const uint32_t*)(B + nc * ldb + kc);
            uint32_t b1 = *(const uint32_t*)(B + nc * ldb + kc + 8);
            #pragma unroll
            for (int m = 0; m < MT; m++) mma_f16(acc[m][n], a[m], b0, b1);
        }
    }
}

// ---------------- weight prep ----------------
__global__ void prep_weights_kernel(const float* __restrict__ qkvw, const float* __restrict__ projw,
                                    const float* __restrict__ fc1w, const float* __restrict__ fc2w) {
    int e4 = blockIdx.x * 256 + threadIdx.x;   // 49152
    const float* src;
    __half* dst;
    int off;
    if (e4 < 12288)      { src = qkvw;  dst = g_qkvw_h;  off = e4; }
    else if (e4 < 16384) { src = projw; dst = g_projw_h; off = e4 - 12288; }
    else if (e4 < 32768) { src = fc1w;  dst = g_fc1w_h;  off = e4 - 16384; }
    else                 { src = fc2w;  dst = g_fc2w_h;  off = e4 - 32768; }
    float4 v = *(const float4*)(src + off * 4);
    *(__half2*)(dst + off * 4)     = __floats2half2_rn(v.x, v.y);
    *(__half2*)(dst + off * 4 + 2) = __floats2half2_rn(v.z, v.w);
}

// ---------------- RPE bias ----------------
__global__ void bias_table_kernel(const float* __restrict__ w1, const float* __restrict__ b1,
                                  const float* __restrict__ w2) {
    __shared__ float4 red[128];
    int p = blockIdx.x;
    int tid = threadIdx.x;
    int i = p / 15, j = p % 15;
    float v0 = (float)(i - 7) / 7.0f * 8.0f;
    float v1 = (float)(j - 7) / 7.0f * 8.0f;
    float inv_l8 = 1.0f / log2f(8.0f);
    float s0 = (v0 > 0.f) ? 1.f : ((v0 < 0.f) ? -1.f : 0.f);
    float s1 = (v1 > 0.f) ? 1.f : ((v1 < 0.f) ? -1.f : 0.f);
    float x0 = s0 * log2f(fabsf(v0) + 1.0f) * inv_l8;
    float x1 = s1 * log2f(fabsf(v1) + 1.0f) * inv_l8;
    float a0 = 0.f, a1 = 0.f, a2 = 0.f, a3 = 0.f;
    #pragma unroll
    for (int r = 0; r < 4; r++) {
        int h = tid + 128 * r;
        float hid = x0 * w1[2 * h] + x1 * w1[2 * h + 1] + b1[h];
        hid = fmaxf(hid, 0.f);
        a0 += hid * w2[0 * RPE_HID + h];
        a1 += hid * w2[1 * RPE_HID + h];
        a2 += hid * w2[2 * RPE_HID + h];
        a3 += hid * w2[3 * RPE_HID + h];
    }
    red[tid] = make_float4(a0, a1, a2, a3);
    __syncthreads();
    for (int s = 64; s > 0; s >>= 1) {
        if (tid < s) {
            float4 o = red[tid + s];
            red[tid].x += o.x; red[tid].y += o.y; red[tid].z += o.z; red[tid].w += o.w;
        }
        __syncthreads();
    }
    if (tid == 0) {
        g_ttab[p * 4 + 0] = red[0].x; g_ttab[p * 4 + 1] = red[0].y;
        g_ttab[p * 4 + 2] = red[0].z; g_ttab[p * 4 + 3] = red[0].w;
    }
}

__global__ void bias_scatter_kernel() {
    int e = blockIdx.x * 256 + threadIdx.x;
    int h = e >> 12;
    int rem = e & 4095;
    int i = rem >> 6, j = rem & 63;
    int yi = i >> 3, xi = i & 7, yj = j >> 3, xj = j & 7;
    int idx = (yi - yj + 7) * 15 + (xi - xj + 7);
    g_bias[e] = g_ttab[idx * 4 + h];
}

// ---------------- Kernel 2: attention + LN1 + residual (fp16, register P, 2 CTAs/SM) ----------------
// smem bytes:
//   xw_h @0      [64][136]h (17408)  -- reused as ow_h
//   wb_h @17408  [128][136]h (34816)
//   qb_h @52224  [64][136]h (17408)  -- with kb_h overlaid by proj fp32 out [64][132]
//   kb_h @69632  [64][136]h (17408)
//   vt_h @87040  [128][72]h (18432)
//   ps   @105472 [256]f | regid @106496 [64]i | mu @106752 | rstd @107008
#define AT_XW 0
#define AT_WB 17408
#define AT_QB 52224
#define AT_KB 69632
#define AT_VT 87040
#define AT_PS 105472
#define AT_RG 106496
#define AT_MU 106752
#define AT_RSTD 107008
#define ATTN_SMEM_BYTES 107264

__global__ __launch_bounds__(256, 2) void attn_kernel(
    const float* __restrict__ x, const float* __restrict__ qkv_b,
    const float* __restrict__ proj_b,
    const float* __restrict__ n1w, const float* __restrict__ n1b)
{
    extern __shared__ char smc[];
    __half* xw = (__half*)(smc + AT_XW);
    __half* ow = xw;
    __half* wb = (__half*)(smc + AT_WB);
    __half* qb = (__half*)(smc + AT_QB);
    __half* kb = (__half*)(smc + AT_KB);
    __half* vt = (__half*)(smc + AT_VT);
    float* ps = (float*)(smc + AT_PS);
    int* regid = (int*)(smc + AT_RG);
    float* mu = (float*)(smc + AT_MU);
    float* rstd = (float*)(smc + AT_RSTD);
    float* projf = (float*)(smc + AT_QB);   // overlay, pitch APAD

    int tid = threadIdx.x;
    int wid = tid >> 5;
    int lane = tid & 31;
    int g = lane >> 2;
    int i = lane & 3;

    int bx = blockIdx.x;
    int bimg = bx >> 6;
    int wh = (bx >> 3) & 7, ww = bx & 7;
    const float* xbase = x + (size_t)bimg * (LSEQ * DIM);

    // ---- load window (rolled -4) -> fp16 ----
    #pragma unroll
    for (int it = 0; it < 8; it++) {
        int e4 = tid + 256 * it;
        int t = e4 >> 5;
        int c = (e4 & 31) << 2;
        int ti = t >> 3, tj = t & 7;
        int hh = (wh * 8 + ti + 4) & 63;
        int wwp = (ww * 8 + tj + 4) & 63;
        float4 v = *(const float4*)(xbase + (size_t)((hh << 6) + wwp) * DIM + c);
        *(__half2*)(xw + t * YPH + c)     = __floats2half2_rn(v.x, v.y);
        *(__half2*)(xw + t * YPH + c + 2) = __floats2half2_rn(v.z, v.w);
    }
    if (tid < 64) {
        int ti = tid >> 3, tj = tid & 7;
        int ah = wh * 8 + ti, aw = ww * 8 + tj;
        int rh = ah < 56 ? 0 : (ah < 60 ? 1 : 2);
        int rw = aw < 56 ? 0 : (aw < 60 ? 1 : 2);
        regid[tid] = rh * 3 + rw;
    }

    const float scale = 0.17677669529663687f;

    // ---- QKV: 3 GEMMs 64x128 k=128, 8 warps 2Mx4N ----
    for (int cidx = 0; cidx < 3; cidx++) {
        const __half* wsrc = g_qkvw_h + cidx * DIM * DIM;
        #pragma unroll
        for (int it = 0; it < 8; it++) {
            int idx = tid + 256 * it;
            int r = idx >> 4;
            int col = (idx & 15) << 3;
            *(uint4*)(wb + r * YPH + col) = *(const uint4*)(wsrc + r * DIM + col);
        }
        __syncthreads();

        float acc[2][4][4];
        #pragma unroll
        for (int m = 0; m < 2; m++)
            #pragma unroll
            for (int n = 0; n < 4; n++)
                #pragma unroll
                for (int q = 0; q < 4; q++) acc[m][n][q] = 0.f;
        int rbase = (wid >> 2) * 32;
        int nbase = (wid & 3) * 32;
        wgemm_h<2, 4, 8>(xw, YPH, wb, YPH, acc, rbase, nbase, g, i);

        #pragma unroll
        for (int n = 0; n < 4; n++) {
            int col = nbase + n * 8 + 2 * i;
            float b0f = qkv_b[cidx * DIM + col];
            float b1f = qkv_b[cidx * DIM + col + 1];
            #pragma unroll
            for (int m = 0; m < 2; m++) {
                int row = rbase + m * 16 + g;
                float v0 = acc[m][n][0] + b0f;
                float v1 = acc[m][n][1] + b1f;
                float v2 = acc[m][n][2] + b0f;
                float v3 = acc[m][n][3] + b1f;
                if (cidx == 0) {
                    *(__half2*)(qb + row * YPH + col)       = __floats2half2_rn(v0 * scale, v1 * scale);
                    *(__half2*)(qb + (row + 8) * YPH + col) = __floats2half2_rn(v2 * scale, v3 * scale);
                } else if (cidx == 1) {
                    *(__half2*)(kb + row * YPH + col)       = __floats2half2_rn(v0, v1);
                    *(__half2*)(kb + (row + 8) * YPH + col) = __floats2half2_rn(v2, v3);
                } else {
                    vt[col * PPH + row]           = __float2half_rn(v0);
                    vt[(col + 1) * PPH + row]     = __float2half_rn(v1);
                    vt[col * PPH + row + 8]       = __float2half_rn(v2);
                    vt[(col + 1) * PPH + row + 8] = __float2half_rn(v3);
                }
            }
        }
        __syncthreads();
    }

    // ---- scores + register softmax + register P ----
    int h = wid >> 1;
    int hoff = h * HD;
    int rbase_h = (wid & 1) * 32;
    uint32_t pr[2][2][8];   // [mblock][row-half(ss)][n]: half2 of exp at cols 8n+2i,8n+2i+1
    float rsinv[2][2];
    {
        float s[2][8][4];
        #pragma unroll
        for (int m = 0; m < 2; m++)
            #pragma unroll
            for (int n = 0; n < 8; n++)
                #pragma unroll
                for (int q = 0; q < 4; q++) s[m][n][q] = 0.f;
        wgemm_h<2, 8, 2>(qb + hoff, YPH, kb + hoff, YPH, s, rbase_h, 0, g, i);

        const float* gb = g_bias + h * 4096;
        int cmask[8][2];
        #pragma unroll
        for (int n = 0; n < 8; n++) {
            cmask[n][0] = regid[n * 8 + 2 * i];
            cmask[n][1] = regid[n * 8 + 2 * i + 1];
        }
        #pragma unroll
        for (int m = 0; m < 2; m++) {
            #pragma unroll
            for (int ss = 0; ss < 2; ss++) {
                int row = rbase_h + m * 16 + 8 * ss + g;
                int rreg = regid[row];
                const float* gbr = gb + row * 64;
                float v[16];
                float mx = -1e30f;
                #pragma unroll
                for (int n = 0; n < 8; n++) {
                    int col = n * 8 + 2 * i;
                    float a0 = s[m][n][2 * ss]     + gbr[col]     + ((rreg != cmask[n][0]) ? -100.f : 0.f);
                    float a1 = s[m][n][2 * ss + 1] + gbr[col + 1] + ((rreg != cmask[n][1]) ? -100.f : 0.f);
                    v[2 * n] = a0; v[2 * n + 1] = a1;
                    mx = fmaxf(mx, fmaxf(a0, a1));
                }
                mx = fmaxf(mx, __shfl_xor_sync(0xFFFFFFFF, mx, 1));
                mx = fmaxf(mx, __shfl_xor_sync(0xFFFFFFFF, mx, 2));
                float sum = 0.f;
                #pragma unroll
                for (int n = 0; n < 8; n++) {
                    float e0 = __expf(v[2 * n] - mx);
                    float e1 = __expf(v[2 * n + 1] - mx);
                    sum += e0 + e1;
                    __half2 hp = __floats2half2_rn(e0, e1);
                    pr[m][ss][n] = *(uint32_t*)&hp;
                }
                sum += __shfl_xor_sync(0xFFFFFFFF, sum, 1);
                sum += __shfl_xor_sync(0xFFFFFFFF, sum, 2);
                rsinv[m][ss] = 1.0f / sum;
            }
        }
    }

    // ---- PV straight from register P: 32 rows x 32 head-dims, k=64 ----
    {
        float o[2][4][4];
        #pragma unroll
        for (int m = 0; m < 2; m++)
            #pragma unroll
            for (int n = 0; n < 4; n++)
                #pragma unroll
                for (int q = 0; q < 4; q++) o[m][n][q] = 0.f;
        const __half* Vb = vt + hoff * PPH;
        #pragma unroll
        for (int ks = 0; ks < 4; ks++) {
            int kc = ks * 16 + 2 * i;
            uint32_t a[2][4];
            #pragma unroll
            for (int m = 0; m < 2; m++) {
                a[m][0] = pr[m][0][2 * ks];
                a[m][1] = pr[m][1][2 * ks];
                a[m][2] = pr[m][0][2 * ks + 1];
                a[m][3] = pr[m][1][2 * ks + 1];
            }
            #pragma unroll
            for (int n = 0; n < 4; n++) {
                int nc = n * 8 + g;
                uint32_t b0 = *(const uint32_t*)(Vb + nc * PPH + kc);
                uint32_t b1 = *(const uint32_t*)(Vb + nc * PPH + kc + 8);
                #pragma unroll
                for (int m = 0; m < 2; m++) mma_f16(o[m][n], a[m], b0, b1);
            }
        }
        #pragma unroll
        for (int m = 0; m < 2; m++) {
            int row = rbase_h + m * 16 + g;
            float rs0 = rsinv[m][0];
            float rs1 = rsinv[m][1];
            #pragma unroll
            for (int n = 0; n < 4; n++) {
                int col = hoff + n * 8 + 2 * i;
                *(__half2*)(ow + row * YPH + col)       = __floats2half2_rn(o[m][n][0] * rs0, o[m][n][1] * rs0);
                *(__half2*)(ow + (row + 8) * YPH + col) = __floats2half2_rn(o[m][n][2] * rs1, o[m][n][3] * rs1);
            }
        }
    }
    __syncthreads();

    // ---- stage proj_w ----
    #pragma unroll
    for (int it = 0; it < 8; it++) {
        int idx = tid + 256 * it;
        int r = idx >> 4;
        int col = (idx & 15) << 3;
        *(uint4*)(wb + r * YPH + col) = *(const uint4*)(g_projw_h + r * DIM + col);
    }
    __syncthreads();

    // ---- proj GEMM 64x128 k=128 -> fp32 projf ----
    {
        float acc[2][4][4];
        #pragma unroll
        for (int m = 0; m < 2; m++)
            #pragma unroll
            for (int n = 0; n < 4; n++)
                #pragma unroll
                for (int q = 0; q < 4; q++) acc[m][n][q] = 0.f;
        int rbase = (wid >> 2) * 32;
        int nbase = (wid & 3) * 32;
        wgemm_h<2, 4, 8>(ow, YPH, wb, YPH, acc, rbase, nbase, g, i);
        #pragma unroll
        for (int n = 0; n < 4; n++) {
            int col = nbase + n * 8 + 2 * i;
            float b0f = proj_b[col];
            float b1f = proj_b[col + 1];
            #pragma unroll
            for (int m = 0; m < 2; m++) {
                int row = rbase + m * 16 + g;
                projf[row * APAD + col]           = acc[m][n][0] + b0f;
                projf[row * APAD + col + 1]       = acc[m][n][1] + b1f;
                projf[(row + 8) * APAD + col]     = acc[m][n][2] + b0f;
                projf[(row + 8) * APAD + col + 1] = acc[m][n][3] + b1f;
            }
        }
    }
    __syncthreads();

    // ---- LN1 stats: 4 threads/row ----
    {
        int row = tid >> 2;
        int cb = (tid & 3) * 32;
        float s = 0.f;
        #pragma unroll 8
        for (int c = 0; c < 32; c++) s += projf[row * APAD + cb + c];
        ps[tid] = s;
    }
    __syncthreads();
    if (tid < 64) {
        float s = ps[4 * tid] + ps[4 * tid + 1] + ps[4 * tid + 2] + ps[4 * tid + 3];
        mu[tid] = s * (1.0f / DIM);
    }
    __syncthreads();
    {
        int row = tid >> 2;
        int cb = (tid & 3) * 32;
        float m = mu[row];
        float v = 0.f;
        #pragma unroll 8
        for (int c = 0; c < 32; c++) {
            float d = projf[row * APAD + cb + c] - m;
            v += d * d;
        }
        ps[tid] = v;
    }
    __syncthreads();
    if (tid < 64) {
        float v = ps[4 * tid] + ps[4 * tid + 1] + ps[4 * tid + 2] + ps[4 * tid + 3];
        rstd[tid] = rsqrtf(v * (1.0f / DIM) + 1e-5f);
    }
    __syncthreads();

    // ---- y = x + LN(proj) ----
    float* yb = g_ybuf + (size_t)bimg * (LSEQ * DIM);
    #pragma unroll
    for (int it = 0; it < 8; it++) {
        int e4 = tid + 256 * it;
        int t = e4 >> 5;
        int c = (e4 & 31) << 2;
        int ti = t >> 3, tj = t & 7;
        int hh = (wh * 8 + ti + 4) & 63;
        int wwp = (ww * 8 + tj + 4) & 63;
        size_t goff = (size_t)((hh << 6) + wwp) * DIM + c;
        float4 xv = *(const float4*)(xbase + goff);
        float m = mu[t], r = rstd[t];
        float4 o;
        o.x = xv.x + (projf[t * APAD + c + 0] - m) * r * n1w[c + 0] + n1b[c + 0];
        o.y = xv.y + (projf[t * APAD + c + 1] - m) * r * n1w[c + 1] + n1b[c + 1];
        o.z = xv.z + (projf[t * APAD + c + 2] - m) * r * n1w[c + 2] + n1b[c + 2];
        o.w = xv.w + (projf[t * APAD + c + 3] - m) * r * n1w[c + 3] + n1b[c + 3];
        *(float4*)(yb + goff) = o;
    }
}

// ---------------- Kernel 3: MLP + LN2 + residual (fp16, unchanged from R7/R8) ----------------
#define MLP_SMEM_BYTES 106496

__global__ __launch_bounds__(256) void mlp_kernel(
    const float* __restrict__ fc1b, const float* __restrict__ fc2b,
    const float* __restrict__ n2w, const float* __restrict__ n2b,
    float* __restrict__ out)
{
    extern __shared__ char smc[];
    __half* Yh = (__half*)smc;
    __half* Wh = (__half*)(smc + 34816);
    __half* Hh = (__half*)(smc + 69632);
    float* ps  = (float*)(smc + 104448);
    float* muv = ps + 256;
    float* rsv = muv + 128;
    float* h2  = (float*)smc;

    int tid = threadIdx.x;
    int wid = tid >> 5;
    int lane = tid & 31;
    int g = lane >> 2;
    int i = lane & 3;
    int rb = (wid >> 1) * 32;
    int nb = (wid & 1) * 64;

    size_t tok0 = (size_t)blockIdx.x * 128;
    const float* ysrc = g_ybuf + tok0 * DIM;

    #pragma unroll
    for (int it = 0; it < 16; it++) {
        int e4 = tid + 256 * it;
        int t = e4 >> 5;
        int c = (e4 & 31) << 2;
        float4 v = *(const float4*)(ysrc + (size_t)t * DIM + c);
        *(__half2*)(Yh + t * YPH + c)     = __floats2half2_rn(v.x, v.y);
        *(__half2*)(Yh + t * YPH + c + 2) = __floats2half2_rn(v.z, v.w);
    }

    float acc2[2][8][4];
    #pragma unroll
    for (int m = 0; m < 2; m++)
        #pragma unroll
        for (int n = 0; n < 8; n++)
            #pragma unroll
            for (int q = 0; q < 4; q++) acc2[m][n][q] = 0.f;

    const float is2 = 0.70710678118654752f;

    for (int hc = 0; hc < 4; hc++) {
        __syncthreads();
        {
            const __half* src = g_fc1w_h + (size_t)hc * 128 * DIM;
            #pragma unroll
            for (int it = 0; it < 8; it++) {
                int idx = tid + 256 * it;
                int r = idx >> 4;
                int col = (idx & 15) << 3;
                *(uint4*)(Wh + r * YPH + col) = *(const uint4*)(src + r * DIM + col);
            }
        }
        __syncthreads();

        float acc1[2][8][4];
        #pragma unroll
        for (int m = 0; m < 2; m++)
            #pragma unroll
            for (int n = 0; n < 8; n++)
                #pragma unroll
                for (int q = 0; q < 4; q++) acc1[m][n][q] = 0.f;
        wgemm_h<2, 8, 8>(Yh, YPH, Wh, YPH, acc1, rb, nb, g, i);

        #pragma unroll
        for (int n = 0; n < 8; n++) {
            int col = nb + n * 8 + 2 * i;
            float b0f = fc1b[hc * 128 + col];
            float b1f = fc1b[hc * 128 + col + 1];
            #pragma unroll
            for (int m = 0; m < 2; m++) {
                int row = rb + m * 16 + g;
                float v0 = acc1[m][n][0] + b0f;
                float v1 = acc1[m][n][1] + b1f;
                float v2 = acc1[m][n][2] + b0f;
                float v3 = acc1[m][n][3] + b1f;
                v0 = 0.5f * v0 * (1.0f + erff(v0 * is2));
                v1 = 0.5f * v1 * (1.0f + erff(v1 * is2));
                v2 = 0.5f * v2 * (1.0f + erff(v2 * is2));
                v3 = 0.5f * v3 * (1.0f + erff(v3 * is2));
                *(__half2*)(Hh + row * YPH + col)       = __floats2half2_rn(v0, v1);
                *(__half2*)(Hh + (row + 8) * YPH + col) = __floats2half2_rn(v2, v3);
            }
        }
        __syncthreads();

        {
            const __half* src = g_fc2w_h + hc * 128;
            #pragma unroll
            for (int it = 0; it < 8; it++) {
                int idx = tid + 256 * it;
                int r = idx >> 4;
                int col = (idx & 15) << 3;
                *(uint4*)(Wh + r * YPH + col) = *(const uint4*)(src + (size_t)r * 512 + col);
            }
        }
        __syncthreads();

        wgemm_h<2, 8, 8>(Hh, YPH, Wh, YPH, acc2, rb, nb, g, i);
    }

    __syncthreads();
    #pragma unroll
    for (int n = 0; n < 8; n++) {
        int col = nb + n * 8 + 2 * i;
        float b0f = fc2b[col];
        float b1f = fc2b[col + 1];
        #pragma unroll
        for (int m = 0; m < 2; m++) {
            int row = rb + m * 16 + g;
            h2[row * APAD + col]           = acc2[m][n][0] + b0f;
            h2[row * APAD + col + 1]       = acc2[m][n][1] + b1f;
            h2[(row + 8) * APAD + col]     = acc2[m][n][2] + b0f;
            h2[(row + 8) * APAD + col + 1] = acc2[m][n][3] + b1f;
        }
    }
    __syncthreads();

    {
        int row = tid >> 1;
        int cb = (tid & 1) * 64;
        float s = 0.f;
        #pragma unroll 8
        for (int c = 0; c < 64; c++) s += h2[row * APAD + cb + c];
        ps[tid] = s;
    }
    __syncthreads();
    if (tid < 128) muv[tid] = (ps[2 * tid] + ps[2 * tid + 1]) * (1.0f / DIM);
    __syncthreads();
    {
        int row = tid >> 1;
        int cb = (tid & 1) * 64;
        float m = muv[row];
        float v = 0.f;
        #pragma unroll 8
        for (int c = 0; c < 64; c++) {
            float d = h2[row * APAD + cb + c] - m;
            v += d * d;
        }
        ps[tid] = v;
    }
    __syncthreads();
    if (tid < 128) rsv[tid] = rsqrtf((ps[2 * tid] + ps[2 * tid + 1]) * (1.0f / DIM) + 1e-5f);
    __syncthreads();

    float* od = out + tok0 * DIM;
    #pragma unroll
    for (int it = 0; it < 16; it++) {
        int e4 = tid + 256 * it;
        int t = e4 >> 5;
        int c = (e4 & 31) << 2;
        float4 yv = *(const float4*)(ysrc + (size_t)t * DIM + c);
        float m = muv[t], r = rsv[t];
        float4 o;
        o.x = yv.x + (h2[t * APAD + c + 0] - m) * r * n2w[c + 0] + n2b[c + 0];
        o.y = yv.y + (h2[t * APAD + c + 1] - m) * r * n2w[c + 1] + n2b[c + 1];
        o.z = yv.z + (h2[t * APAD + c + 2] - m) * r * n2w[c + 2] + n2b[c + 2];
        o.w = yv.w + (h2[t * APAD + c + 3] - m) * r * n2w[c + 3] + n2b[c + 3];
        *(float4*)(od + (size_t)t * DIM + c) = o;
    }
}

extern "C" void kernel_launch(void* const* d_in, const int* in_sizes, int n_in,
                              void* d_out, int out_size) {
    const float* x      = (const float*)d_in[0];
    const float* qkv_w  = (const float*)d_in[1];
    const float* qkv_b  = (const float*)d_in[2];
    const float* proj_w = (const float*)d_in[3];
    const float* proj_b = (const float*)d_in[4];
    const float* rpe_w1 = (const float*)d_in[5];
    const float* rpe_b1 = (const float*)d_in[6];
    const float* rpe_w2 = (const float*)d_in[7];
    const float* n1w    = (const float*)d_in[8];
    const float* n1b    = (const float*)d_in[9];
    const float* fc1w   = (const float*)d_in[10];
    const float* fc1b   = (const float*)d_in[11];
    const float* fc2w   = (const float*)d_in[12];
    const float* fc2b   = (const float*)d_in[13];
    const float* n2w    = (const float*)d_in[14];
    const float* n2b    = (const float*)d_in[15];
    float* out = (float*)d_out;

    cudaFuncSetAttribute(attn_kernel, cudaFuncAttributeMaxDynamicSharedMemorySize, ATTN_SMEM_BYTES);
    cudaFuncSetAttribute(mlp_kernel,  cudaFuncAttributeMaxDynamicSharedMemorySize, MLP_SMEM_BYTES);

    prep_weights_kernel<<<192, 256>>>(qkv_w, proj_w, fc1w, fc2w);
    bias_table_kernel<<<225, 128>>>(rpe_w1, rpe_b1, rpe_w2);
    bias_scatter_kernel<<<64, 256>>>();
    attn_kernel<<<2048, 256, ATTN_SMEM_BYTES>>>(x, qkv_b, proj_b, n1w, n1b);
    mlp_kernel<<<1024, 256, MLP_SMEM_BYTES>>>(fc1b, fc2b, n2w, n2b, out);
}

// round 11
// speedup vs baseline: 1.7171x; 1.0321x over previous
#include <cuda_runtime.h>
#include <cuda_fp16.h>
#include <math.h>
#include <stdint.h>

#define WSZ 8
#define NHEAD 4
#define DIM 128
#define NTOK 64
#define HD 32
#define BATCH 32
#define HW 64
#define LSEQ 4096
#define RPE_HID 512
#define APAD 132
#define YPH 136    // fp16 smem pitch (halves): 272B rows -> ldmatrix bank idx row*17 mod 8, conflict-free
#define PPH 72     // Vt fp16 pitch (halves): 144B rows -> row*9 mod 8, conflict-free

__device__ float g_bias[NHEAD * NTOK * NTOK];
__device__ float g_ttab[225 * NHEAD];
__device__ float g_ybuf[(size_t)BATCH * LSEQ * DIM];
__device__ __half g_qkvw_h[3 * DIM * DIM];
__device__ __half g_projw_h[DIM * DIM];
__device__ __half g_fc1w_h[512 * DIM];
__device__ __half g_fc2w_h[DIM * 512];

// ---------------- fp16 MMA + ldmatrix helpers ----------------
__device__ __forceinline__ void mma_f16(float* c, const uint32_t* a, uint32_t b0, uint32_t b1) {
    asm volatile(
        "mma.sync.aligned.m16n8k16.row.col.f32.f16.f16.f32 "
        "{%0,%1,%2,%3}, {%4,%5,%6,%7}, {%8,%9}, {%0,%1,%2,%3};"
        : "+f"(c[0]), "+f"(c[1]), "+f"(c[2]), "+f"(c[3])
        : "r"(a[0]), "r"(a[1]), "r"(a[2]), "r"(a[3]), "r"(b0), "r"(b1));
}

__device__ __forceinline__ void ldsm_x4(uint32_t& r0, uint32_t& r1, uint32_t& r2, uint32_t& r3,
                                        uint32_t addr) {
    asm volatile("ldmatrix.sync.aligned.m8n8.x4.shared.b16 {%0,%1,%2,%3}, [%4];"
                 : "=r"(r0), "=r"(r1), "=r"(r2), "=r"(r3) : "r"(addr));
}

// C[MT*16 x NT*8] += A @ B^T, fp16 operands via ldmatrix, fp32 accum. K = KS*16. NT even.
// ldmatrix.x4 lane addressing: rows base+(lane&15), k-half (lane>>4)*8.
// A frags -> a0..a3 directly; B frags -> (b0 of n-tile 2nn, b0 of 2nn+1, b1 of 2nn, b1 of 2nn+1).
template<int MT, int NT, int KS>
__device__ __forceinline__ void wgemm_l(const __half* __restrict__ A, int lda,
                                        const __half* __restrict__ B, int ldb,
                                        float (&acc)[MT][NT][4], int rbase, int nbase, int lane)
{
    int lr = lane & 15;
    int lk = (lane >> 4) << 3;
    uint32_t ab[MT], bb[NT / 2];
    #pragma unroll
    for (int m = 0; m < MT; m++)
        ab[m] = (uint32_t)__cvta_generic_to_shared(A + (rbase + m * 16 + lr) * lda + lk);
    #pragma unroll
    for (int nn = 0; nn < NT / 2; nn++)
        bb[nn] = (uint32_t)__cvta_generic_to_shared(B + (nbase + nn * 16 + lr) * ldb + lk);
    #pragma unroll
    for (int ks = 0; ks < KS; ks++) {
        uint32_t a[MT][4];
        #pragma unroll
        for (int m = 0; m < MT; m++)
            ldsm_x4(a[m][0], a[m][1], a[m][2], a[m][3], ab[m] + ks * 32);
        #pragma unroll
        for (int nn = 0; nn < NT / 2; nn++) {
            uint32_t b0, b1, b2, b3;
            ldsm_x4(b0, b1, b2, b3, bb[nn] + ks * 32);
            #pragma unroll
            for (int m = 0; m < MT; m++) {
                mma_f16(acc[m][2 * nn],     a[m], b0, b2);
                mma_f16(acc[m][2 * nn + 1], a[m], b1, b3);
            }
        }
    }
}

// ---------------- weight prep ----------------
__global__ void prep_weights_kernel(const float* __restrict__ qkvw, const float* __restrict__ projw,
                                    const float* __restrict__ fc1w, const float* __restrict__ fc2w) {
    int e4 = blockIdx.x * 256 + threadIdx.x;   // 49152
    const float* src;
    __half* dst;
    int off;
    if (e4 < 12288)      { src = qkvw;  dst = g_qkvw_h;  off = e4; }
    else if (e4 < 16384) { src = projw; dst = g_projw_h; off = e4 - 12288; }
    else if (e4 < 32768) { src = fc1w;  dst = g_fc1w_h;  off = e4 - 16384; }
    else                 { src = fc2w;  dst = g_fc2w_h;  off = e4 - 32768; }
    float4 v = *(const float4*)(src + off * 4);
    *(__half2*)(dst + off * 4)     = __floats2half2_rn(v.x, v.y);
    *(__half2*)(dst + off * 4 + 2) = __floats2half2_rn(v.z, v.w);
}

// ---------------- RPE bias ----------------
__global__ void bias_table_kernel(const float* __restrict__ w1, const float* __restrict__ b1,
                                  const float* __restrict__ w2) {
    __shared__ float4 red[128];
    int p = blockIdx.x;
    int tid = threadIdx.x;
    int i = p / 15, j = p % 15;
    float v0 = (float)(i - 7) / 7.0f * 8.0f;
    float v1 = (float)(j - 7) / 7.0f * 8.0f;
    float inv_l8 = 1.0f / log2f(8.0f);
    float s0 = (v0 > 0.f) ? 1.f : ((v0 < 0.f) ? -1.f : 0.f);
    float s1 = (v1 > 0.f) ? 1.f : ((v1 < 0.f) ? -1.f : 0.f);
    float x0 = s0 * log2f(fabsf(v0) + 1.0f) * inv_l8;
    float x1 = s1 * log2f(fabsf(v1) + 1.0f) * inv_l8;
    float a0 = 0.f, a1 = 0.f, a2 = 0.f, a3 = 0.f;
    #pragma unroll
    for (int r = 0; r < 4; r++) {
        int h = tid + 128 * r;
        float hid = x0 * w1[2 * h] + x1 * w1[2 * h + 1] + b1[h];
        hid = fmaxf(hid, 0.f);
        a0 += hid * w2[0 * RPE_HID + h];
        a1 += hid * w2[1 * RPE_HID + h];
        a2 += hid * w2[2 * RPE_HID + h];
        a3 += hid * w2[3 * RPE_HID + h];
    }
    red[tid] = make_float4(a0, a1, a2, a3);
    __syncthreads();
    for (int s = 64; s > 0; s >>= 1) {
        if (tid < s) {
            float4 o = red[tid + s];
            red[tid].x += o.x; red[tid].y += o.y; red[tid].z += o.z; red[tid].w += o.w;
        }
        __syncthreads();
    }
    if (tid == 0) {
        g_ttab[p * 4 + 0] = red[0].x; g_ttab[p * 4 + 1] = red[0].y;
        g_ttab[p * 4 + 2] = red[0].z; g_ttab[p * 4 + 3] = red[0].w;
    }
}

__global__ void bias_scatter_kernel() {
    int e = blockIdx.x * 256 + threadIdx.x;
    int h = e >> 12;
    int rem = e & 4095;
    int i = rem >> 6, j = rem & 63;
    int yi = i >> 3, xi = i & 7, yj = j >> 3, xj = j & 7;
    int idx = (yi - yj + 7) * 15 + (xi - xj + 7);
    g_bias[e] = g_ttab[idx * 4 + h];
}

// ---------------- Kernel 2: attention + LN1 + residual (fp16 + ldmatrix, 2 CTAs/SM) ----------------
#define AT_XW 0
#define AT_WB 17408
#define AT_QB 52224
#define AT_KB 69632
#define AT_VT 87040
#define AT_PS 105472
#define AT_RG 106496
#define AT_MU 106752
#define AT_RSTD 107008
#define ATTN_SMEM_BYTES 107264

__global__ __launch_bounds__(256, 2) void attn_kernel(
    const float* __restrict__ x, const float* __restrict__ qkv_b,
    const float* __restrict__ proj_b,
    const float* __restrict__ n1w, const float* __restrict__ n1b)
{
    extern __shared__ char smc[];
    __half* xw = (__half*)(smc + AT_XW);
    __half* ow = xw;
    __half* wb = (__half*)(smc + AT_WB);
    __half* qb = (__half*)(smc + AT_QB);
    __half* kb = (__half*)(smc + AT_KB);
    __half* vt = (__half*)(smc + AT_VT);
    float* ps = (float*)(smc + AT_PS);
    int* regid = (int*)(smc + AT_RG);
    float* mu = (float*)(smc + AT_MU);
    float* rstd = (float*)(smc + AT_RSTD);
    float* projf = (float*)(smc + AT_QB);   // overlay, pitch APAD

    int tid = threadIdx.x;
    int wid = tid >> 5;
    int lane = tid & 31;
    int g = lane >> 2;
    int i = lane & 3;

    int bx = blockIdx.x;
    int bimg = bx >> 6;
    int wh = (bx >> 3) & 7, ww = bx & 7;
    const float* xbase = x + (size_t)bimg * (LSEQ * DIM);

    // ---- load window (rolled -4) -> fp16 ----
    #pragma unroll
    for (int it = 0; it < 8; it++) {
        int e4 = tid + 256 * it;
        int t = e4 >> 5;
        int c = (e4 & 31) << 2;
        int ti = t >> 3, tj = t & 7;
        int hh = (wh * 8 + ti + 4) & 63;
        int wwp = (ww * 8 + tj + 4) & 63;
        float4 v = *(const float4*)(xbase + (size_t)((hh << 6) + wwp) * DIM + c);
        *(__half2*)(xw + t * YPH + c)     = __floats2half2_rn(v.x, v.y);
        *(__half2*)(xw + t * YPH + c + 2) = __floats2half2_rn(v.z, v.w);
    }
    if (tid < 64) {
        int ti = tid >> 3, tj = tid & 7;
        int ah = wh * 8 + ti, aw = ww * 8 + tj;
        int rh = ah < 56 ? 0 : (ah < 60 ? 1 : 2);
        int rw = aw < 56 ? 0 : (aw < 60 ? 1 : 2);
        regid[tid] = rh * 3 + rw;
    }

    const float scale = 0.17677669529663687f;

    // ---- QKV: 3 GEMMs 64x128 k=128, 8 warps 2Mx4N ----
    for (int cidx = 0; cidx < 3; cidx++) {
        const __half* wsrc = g_qkvw_h + cidx * DIM * DIM;
        #pragma unroll
        for (int it = 0; it < 8; it++) {
            int idx = tid + 256 * it;
            int r = idx >> 4;
            int col = (idx & 15) << 3;
            *(uint4*)(wb + r * YPH + col) = *(const uint4*)(wsrc + r * DIM + col);
        }
        __syncthreads();

        float acc[2][4][4];
        #pragma unroll
        for (int m = 0; m < 2; m++)
            #pragma unroll
            for (int n = 0; n < 4; n++)
                #pragma unroll
                for (int q = 0; q < 4; q++) acc[m][n][q] = 0.f;
        int rbase = (wid >> 2) * 32;
        int nbase = (wid & 3) * 32;
        wgemm_l<2, 4, 8>(xw, YPH, wb, YPH, acc, rbase, nbase, lane);

        #pragma unroll
        for (int n = 0; n < 4; n++) {
            int col = nbase + n * 8 + 2 * i;
            float b0f = qkv_b[cidx * DIM + col];
            float b1f = qkv_b[cidx * DIM + col + 1];
            #pragma unroll
            for (int m = 0; m < 2; m++) {
                int row = rbase + m * 16 + g;
                float v0 = acc[m][n][0] + b0f;
                float v1 = acc[m][n][1] + b1f;
                float v2 = acc[m][n][2] + b0f;
                float v3 = acc[m][n][3] + b1f;
                if (cidx == 0) {
                    *(__half2*)(qb + row * YPH + col)       = __floats2half2_rn(v0 * scale, v1 * scale);
                    *(__half2*)(qb + (row + 8) * YPH + col) = __floats2half2_rn(v2 * scale, v3 * scale);
                } else if (cidx == 1) {
                    *(__half2*)(kb + row * YPH + col)       = __floats2half2_rn(v0, v1);
                    *(__half2*)(kb + (row + 8) * YPH + col) = __floats2half2_rn(v2, v3);
                } else {
                    vt[col * PPH + row]           = __float2half_rn(v0);
                    vt[(col + 1) * PPH + row]     = __float2half_rn(v1);
                    vt[col * PPH + row + 8]       = __float2half_rn(v2);
                    vt[(col + 1) * PPH + row + 8] = __float2half_rn(v3);
                }
            }
        }
        __syncthreads();
    }

    // ---- scores + register softmax + register P ----
    int h = wid >> 1;
    int hoff = h * HD;
    int rbase_h = (wid & 1) * 32;
    uint32_t pr[2][2][8];
    float rsinv[2][2];
    {
        float s[2][8][4];
        #pragma unroll
        for (int m = 0; m < 2; m++)
            #pragma unroll
            for (int n = 0; n < 8; n++)
                #pragma unroll
                for (int q = 0; q < 4; q++) s[m][n][q] = 0.f;
        wgemm_l<2, 8, 2>(qb + hoff, YPH, kb + hoff, YPH, s, rbase_h, 0, lane);

        const float* gb = g_bias + h * 4096;
        int cmask[8][2];
        #pragma unroll
        for (int n = 0; n < 8; n++) {
            cmask[n][0] = regid[n * 8 + 2 * i];
            cmask[n][1] = regid[n * 8 + 2 * i + 1];
        }
        #pragma unroll
        for (int m = 0; m < 2; m++) {
            #pragma unroll
            for (int ss = 0; ss < 2; ss++) {
                int row = rbase_h + m * 16 + 8 * ss + g;
                int rreg = regid[row];
                const float* gbr = gb + row * 64;
                float v[16];
                float mx = -1e30f;
                #pragma unroll
                for (int n = 0; n < 8; n++) {
                    int col = n * 8 + 2 * i;
                    float a0 = s[m][n][2 * ss]     + gbr[col]     + ((rreg != cmask[n][0]) ? -100.f : 0.f);
                    float a1 = s[m][n][2 * ss + 1] + gbr[col + 1] + ((rreg != cmask[n][1]) ? -100.f : 0.f);
                    v[2 * n] = a0; v[2 * n + 1] = a1;
                    mx = fmaxf(mx, fmaxf(a0, a1));
                }
                mx = fmaxf(mx, __shfl_xor_sync(0xFFFFFFFF, mx, 1));
                mx = fmaxf(mx, __shfl_xor_sync(0xFFFFFFFF, mx, 2));
                float sum = 0.f;
                #pragma unroll
                for (int n = 0; n < 8; n++) {
                    float e0 = __expf(v[2 * n] - mx);
                    float e1 = __expf(v[2 * n + 1] - mx);
                    sum += e0 + e1;
                    __half2 hp = __floats2half2_rn(e0, e1);
                    pr[m][ss][n] = *(uint32_t*)&hp;
                }
                sum += __shfl_xor_sync(0xFFFFFFFF, sum, 1);
                sum += __shfl_xor_sync(0xFFFFFFFF, sum, 2);
                rsinv[m][ss] = 1.0f / sum;
            }
        }
    }

    // ---- PV from register P; B via ldmatrix ----
    {
        float o[2][4][4];
        #pragma unroll
        for (int m = 0; m < 2; m++)
            #pragma unroll
            for (int n = 0; n < 4; n++)
                #pragma unroll
                for (int q = 0; q < 4; q++) o[m][n][q] = 0.f;
        const __half* Vb = vt + hoff * PPH;
        int lr = lane & 15;
        int lk = (lane >> 4) << 3;
        uint32_t bb[2];
        #pragma unroll
        for (int nn = 0; nn < 2; nn++)
            bb[nn] = (uint32_t)__cvta_generic_to_shared(Vb + (nn * 16 + lr) * PPH + lk);
        #pragma unroll
        for (int ks = 0; ks < 4; ks++) {
            uint32_t a[2][4];
            #pragma unroll
            for (int m = 0; m < 2; m++) {
                a[m][0] = pr[m][0][2 * ks];
                a[m][1] = pr[m][1][2 * ks];
                a[m][2] = pr[m][0][2 * ks + 1];
                a[m][3] = pr[m][1][2 * ks + 1];
            }
            #pragma unroll
            for (int nn = 0; nn < 2; nn++) {
                uint32_t b0, b1, b2, b3;
                ldsm_x4(b0, b1, b2, b3, bb[nn] + ks * 32);
                #pragma unroll
                for (int m = 0; m < 2; m++) {
                    mma_f16(o[m][2 * nn],     a[m], b0, b2);
                    mma_f16(o[m][2 * nn + 1], a[m], b1, b3);
                }
            }
        }
        #pragma unroll
        for (int m = 0; m < 2; m++) {
            int row = rbase_h + m * 16 + g;
            float rs0 = rsinv[m][0];
            float rs1 = rsinv[m][1];
            #pragma unroll
            for (int n = 0; n < 4; n++) {
                int col = hoff + n * 8 + 2 * i;
                *(__half2*)(ow + row * YPH + col)       = __floats2half2_rn(o[m][n][0] * rs0, o[m][n][1] * rs0);
                *(__half2*)(ow + (row + 8) * YPH + col) = __floats2half2_rn(o[m][n][2] * rs1, o[m][n][3] * rs1);
            }
        }
    }
    __syncthreads();

    // ---- stage proj_w ----
    #pragma unroll
    for (int it = 0; it < 8; it++) {
        int idx = tid + 256 * it;
        int r = idx >> 4;
        int col = (idx & 15) << 3;
        *(uint4*)(wb + r * YPH + col) = *(const uint4*)(g_projw_h + r * DIM + col);
    }
    __syncthreads();

    // ---- proj GEMM 64x128 k=128 -> fp32 projf ----
    {
        float acc[2][4][4];
        #pragma unroll
        for (int m = 0; m < 2; m++)
            #pragma unroll
            for (int n = 0; n < 4; n++)
                #pragma unroll
                for (int q = 0; q < 4; q++) acc[m][n][q] = 0.f;
        int rbase = (wid >> 2) * 32;
        int nbase = (wid & 3) * 32;
        wgemm_l<2, 4, 8>(ow, YPH, wb, YPH, acc, rbase, nbase, lane);
        #pragma unroll
        for (int n = 0; n < 4; n++) {
            int col = nbase + n * 8 + 2 * i;
            float b0f = proj_b[col];
            float b1f = proj_b[col + 1];
            #pragma unroll
            for (int m = 0; m < 2; m++) {
                int row = rbase + m * 16 + g;
                projf[row * APAD + col]           = acc[m][n][0] + b0f;
                projf[row * APAD + col + 1]       = acc[m][n][1] + b1f;
                projf[(row + 8) * APAD + col]     = acc[m][n][2] + b0f;
                projf[(row + 8) * APAD + col + 1] = acc[m][n][3] + b1f;
            }
        }
    }
    __syncthreads();

    // ---- LN1 stats: 4 threads/row ----
    {
        int row = tid >> 2;
        int cb = (tid & 3) * 32;
        float s = 0.f;
        #pragma unroll 8
        for (int c = 0; c < 32; c++) s += projf[row * APAD + cb + c];
        ps[tid] = s;
    }
    __syncthreads();
    if (tid < 64) {
        float s = ps[4 * tid] + ps[4 * tid + 1] + ps[4 * tid + 2] + ps[4 * tid + 3];
        mu[tid] = s * (1.0f / DIM);
    }
    __syncthreads();
    {
        int row = tid >> 2;
        int cb = (tid & 3) * 32;
        float m = mu[row];
        float v = 0.f;
        #pragma unroll 8
        for (int c = 0; c < 32; c++) {
            float d = projf[row * APAD + cb + c] - m;
            v += d * d;
        }
        ps[tid] = v;
    }
    __syncthreads();
    if (tid < 64) {
        float v = ps[4 * tid] + ps[4 * tid + 1] + ps[4 * tid + 2] + ps[4 * tid + 3];
        rstd[tid] = rsqrtf(v * (1.0f / DIM) + 1e-5f);
    }
    __syncthreads();

    // ---- y = x + LN(proj) ----
    float* yb = g_ybuf + (size_t)bimg * (LSEQ * DIM);
    #pragma unroll
    for (int it = 0; it < 8; it++) {
        int e4 = tid + 256 * it;
        int t = e4 >> 5;
        int c = (e4 & 31) << 2;
        int ti = t >> 3, tj = t & 7;
        int hh = (wh * 8 + ti + 4) & 63;
        int wwp = (ww * 8 + tj + 4) & 63;
        size_t goff = (size_t)((hh << 6) + wwp) * DIM + c;
        float4 xv = *(const float4*)(xbase + goff);
        float m = mu[t], r = rstd[t];
        float4 o;
        o.x = xv.x + (projf[t * APAD + c + 0] - m) * r * n1w[c + 0] + n1b[c + 0];
        o.y = xv.y + (projf[t * APAD + c + 1] - m) * r * n1w[c + 1] + n1b[c + 1];
        o.z = xv.z + (projf[t * APAD + c + 2] - m) * r * n1w[c + 2] + n1b[c + 2];
        o.w = xv.w + (projf[t * APAD + c + 3] - m) * r * n1w[c + 3] + n1b[c + 3];
        *(float4*)(yb + goff) = o;
    }
}

// ---------------- Kernel 3: MLP + LN2 + residual (fp16 + ldmatrix) ----------------
#define MLP_SMEM_BYTES 106496

__global__ __launch_bounds__(256) void mlp_kernel(
    const float* __restrict__ fc1b, const float* __restrict__ fc2b,
    const float* __restrict__ n2w, const float* __restrict__ n2b,
    float* __restrict__ out)
{
    extern __shared__ char smc[];
    __half* Yh = (__half*)smc;
    __half* Wh = (__half*)(smc + 34816);
    __half* Hh = (__half*)(smc + 69632);
    float* ps  = (float*)(smc + 104448);
    float* muv = ps + 256;
    float* rsv = muv + 128;
    float* h2  = (float*)smc;

    int tid = threadIdx.x;
    int wid = tid >> 5;
    int lane = tid & 31;
    int g = lane >> 2;
    int i = lane & 3;
    int rb = (wid >> 1) * 32;
    int nb = (wid & 1) * 64;

    size_t tok0 = (size_t)blockIdx.x * 128;
    const float* ysrc = g_ybuf + tok0 * DIM;

    #pragma unroll
    for (int it = 0; it < 16; it++) {
        int e4 = tid + 256 * it;
        int t = e4 >> 5;
        int c = (e4 & 31) << 2;
        float4 v = *(const float4*)(ysrc + (size_t)t * DIM + c);
        *(__half2*)(Yh + t * YPH + c)     = __floats2half2_rn(v.x, v.y);
        *(__half2*)(Yh + t * YPH + c + 2) = __floats2half2_rn(v.z, v.w);
    }

    float acc2[2][8][4];
    #pragma unroll
    for (int m = 0; m < 2; m++)
        #pragma unroll
        for (int n = 0; n < 8; n++)
            #pragma unroll
            for (int q = 0; q < 4; q++) acc2[m][n][q] = 0.f;

    const float is2 = 0.70710678118654752f;

    for (int hc = 0; hc < 4; hc++) {
        __syncthreads();
        {
            const __half* src = g_fc1w_h + (size_t)hc * 128 * DIM;
            #pragma unroll
            for (int it = 0; it < 8; it++) {
                int idx = tid + 256 * it;
                int r = idx >> 4;
                int col = (idx & 15) << 3;
                *(uint4*)(Wh + r * YPH + col) = *(const uint4*)(src + r * DIM + col);
            }
        }
        __syncthreads();

        float acc1[2][8][4];
        #pragma unroll
        for (int m = 0; m < 2; m++)
            #pragma unroll
            for (int n = 0; n < 8; n++)
                #pragma unroll
                for (int q = 0; q < 4; q++) acc1[m][n][q] = 0.f;
        wgemm_l<2, 8, 8>(Yh, YPH, Wh, YPH, acc1, rb, nb, lane);

        #pragma unroll
        for (int n = 0; n < 8; n++) {
            int col = nb + n * 8 + 2 * i;
            float b0f = fc1b[hc * 128 + col];
            float b1f = fc1b[hc * 128 + col + 1];
            #pragma unroll
            for (int m = 0; m < 2; m++) {
                int row = rb + m * 16 + g;
                float v0 = acc1[m][n][0] + b0f;
                float v1 = acc1[m][n][1] + b1f;
                float v2 = acc1[m][n][2] + b0f;
                float v3 = acc1[m][n][3] + b1f;
                v0 = 0.5f * v0 * (1.0f + erff(v0 * is2));
                v1 = 0.5f * v1 * (1.0f + erff(v1 * is2));
                v2 = 0.5f * v2 * (1.0f + erff(v2 * is2));
                v3 = 0.5f * v3 * (1.0f + erff(v3 * is2));
                *(__half2*)(Hh + row * YPH + col)       = __floats2half2_rn(v0, v1);
                *(__half2*)(Hh + (row + 8) * YPH + col) = __floats2half2_rn(v2, v3);
            }
        }
        __syncthreads();

        {
            const __half* src = g_fc2w_h + hc * 128;
            #pragma unroll
            for (int it = 0; it < 8; it++) {
                int idx = tid + 256 * it;
                int r = idx >> 4;
                int col = (idx & 15) << 3;
                *(uint4*)(Wh + r * YPH + col) = *(const uint4*)(src + (size_t)r * 512 + col);
            }
        }
        __syncthreads();

        wgemm_l<2, 8, 8>(Hh, YPH, Wh, YPH, acc2, rb, nb, lane);
    }

    __syncthreads();
    #pragma unroll
    for (int n = 0; n < 8; n++) {
        int col = nb + n * 8 + 2 * i;
        float b0f = fc2b[col];
        float b1f = fc2b[col + 1];
        #pragma unroll
        for (int m = 0; m < 2; m++) {
            int row = rb + m * 16 + g;
            h2[row * APAD + col]           = acc2[m][n][0] + b0f;
            h2[row * APAD + col + 1]       = acc2[m][n][1] + b1f;
            h2[(row + 8) * APAD + col]     = acc2[m][n][2] + b0f;
            h2[(row + 8) * APAD + col + 1] = acc2[m][n][3] + b1f;
        }
    }
    __syncthreads();

    {
        int row = tid >> 1;
        int cb = (tid & 1) * 64;
        float s = 0.f;
        #pragma unroll 8
        for (int c = 0; c < 64; c++) s += h2[row * APAD + cb + c];
        ps[tid] = s;
    }
    __syncthreads();
    if (tid < 128) muv[tid] = (ps[2 * tid] + ps[2 * tid + 1]) * (1.0f / DIM);
    __syncthreads();
    {
        int row = tid >> 1;
        int cb = (tid & 1) * 64;
        float m = muv[row];
        float v = 0.f;
        #pragma unroll 8
        for (int c = 0; c < 64; c++) {
            float d = h2[row * APAD + cb + c] - m;
            v += d * d;
        }
        ps[tid] = v;
    }
    __syncthreads();
    if (tid < 128) rsv[tid] = rsqrtf((ps[2 * tid] + ps[2 * tid + 1]) * (1.0f / DIM) + 1e-5f);
    __syncthreads();

    float* od = out + tok0 * DIM;
    #pragma unroll
    for (int it = 0; it < 16; it++) {
        int e4 = tid + 256 * it;
        int t = e4 >> 5;
        int c = (e4 & 31) << 2;
        float4 yv = *(const float4*)(ysrc + (size_t)t * DIM + c);
        float m = muv[t], r = rsv[t];
        float4 o;
        o.x = yv.x + (h2[t * APAD + c + 0] - m) * r * n2w[c + 0] + n2b[c + 0];
        o.y = yv.y + (h2[t * APAD + c + 1] - m) * r * n2w[c + 1] + n2b[c + 1];
        o.z = yv.z + (h2[t * APAD + c + 2] - m) * r * n2w[c + 2] + n2b[c + 2];
        o.w = yv.w + (h2[t * APAD + c + 3] - m) * r * n2w[c + 3] + n2b[c + 3];
        *(float4*)(od + (size_t)t * DIM + c) = o;
    }
}

extern "C" void kernel_launch(void* const* d_in, const int* in_sizes, int n_in,
                              void* d_out, int out_size) {
    const float* x      = (const float*)d_in[0];
    const float* qkv_w  = (const float*)d_in[1];
    const float* qkv_b  = (const float*)d_in[2];
    const float* proj_w = (const float*)d_in[3];
    const float* proj_b = (const float*)d_in[4];
    const float* rpe_w1 = (const float*)d_in[5];
    const float* rpe_b1 = (const float*)d_in[6];
    const float* rpe_w2 = (const float*)d_in[7];
    const float* n1w    = (const float*)d_in[8];
    const float* n1b    = (const float*)d_in[9];
    const float* fc1w   = (const float*)d_in[10];
    const float* fc1b   = (const float*)d_in[11];
    const float* fc2w   = (const float*)d_in[12];
    const float* fc2b   = (const float*)d_in[13];
    const float* n2w    = (const float*)d_in[14];
    const float* n2b    = (const float*)d_in[15];
    float* out = (float*)d_out;

    cudaFuncSetAttribute(attn_kernel, cudaFuncAttributeMaxDynamicSharedMemorySize, ATTN_SMEM_BYTES);
    cudaFuncSetAttribute(mlp_kernel,  cudaFuncAttributeMaxDynamicSharedMemorySize, MLP_SMEM_BYTES);

    prep_weights_kernel<<<192, 256>>>(qkv_w, proj_w, fc1w, fc2w);
    bias_table_kernel<<<225, 128>>>(rpe_w1, rpe_b1, rpe_w2);
    bias_scatter_kernel<<<64, 256>>>();
    attn_kernel<<<2048, 256, ATTN_SMEM_BYTES>>>(x, qkv_b, proj_b, n1w, n1b);
    mlp_kernel<<<1024, 256, MLP_SMEM_BYTES>>>(fc1b, fc2b, n2w, n2b, out);
}

// round 12
// speedup vs baseline: 1.8093x; 1.0537x over previous
#include <cuda_runtime.h>
#include <cuda_fp16.h>
#include <math.h>
#include <stdint.h>

#define WSZ 8
#define NHEAD 4
#define DIM 128
#define NTOK 64
#define HD 32
#define BATCH 32
#define HW 64
#define LSEQ 4096
#define RPE_HID 512
#define APAD 132
#define YPH 136    // fp16 smem pitch (halves)
#define PPH 72     // Vt fp16 pitch (halves)

__device__ float g_bias[NHEAD * NTOK * NTOK];
__device__ float g_ttab[225 * NHEAD];
__device__ float g_ybuf[(size_t)BATCH * LSEQ * DIM];
__device__ __half g_qkvw_h[3 * DIM * DIM];
__device__ __half g_projw_h[DIM * DIM];
__device__ __half g_fc1w_h[512 * DIM];
__device__ __half g_fc2w_h[DIM * 512];

// ---------------- fp16 MMA + ldmatrix helpers ----------------
__device__ __forceinline__ void mma_f16(float* c, const uint32_t* a, uint32_t b0, uint32_t b1) {
    asm volatile(
        "mma.sync.aligned.m16n8k16.row.col.f32.f16.f16.f32 "
        "{%0,%1,%2,%3}, {%4,%5,%6,%7}, {%8,%9}, {%0,%1,%2,%3};"
        : "+f"(c[0]), "+f"(c[1]), "+f"(c[2]), "+f"(c[3])
        : "r"(a[0]), "r"(a[1]), "r"(a[2]), "r"(a[3]), "r"(b0), "r"(b1));
}

__device__ __forceinline__ void ldsm_x4(uint32_t& r0, uint32_t& r1, uint32_t& r2, uint32_t& r3,
                                        uint32_t addr) {
    asm volatile("ldmatrix.sync.aligned.m8n8.x4.shared.b16 {%0,%1,%2,%3}, [%4];"
                 : "=r"(r0), "=r"(r1), "=r"(r2), "=r"(r3) : "r"(addr));
}

template<int MT, int NT, int KS>
__device__ __forceinline__ void wgemm_l(const __half* __restrict__ A, int lda,
                                        const __half* __restrict__ B, int ldb,
                                        float (&acc)[MT][NT][4], int rbase, int nbase, int lane)
{
    int lr = lane & 15;
    int lk = (lane >> 4) << 3;
    uint32_t ab[MT], bb[NT / 2];
    #pragma unroll
    for (int m = 0; m < MT; m++)
        ab[m] = (uint32_t)__cvta_generic_to_shared(A + (rbase + m * 16 + lr) * lda + lk);
    #pragma unroll
    for (int nn = 0; nn < NT / 2; nn++)
        bb[nn] = (uint32_t)__cvta_generic_to_shared(B + (nbase + nn * 16 + lr) * ldb + lk);
    #pragma unroll
    for (int ks = 0; ks < KS; ks++) {
        uint32_t a[MT][4];
        #pragma unroll
        for (int m = 0; m < MT; m++)
            ldsm_x4(a[m][0], a[m][1], a[m][2], a[m][3], ab[m] + ks * 32);
        #pragma unroll
        for (int nn = 0; nn < NT / 2; nn++) {
            uint32_t b0, b1, b2, b3;
            ldsm_x4(b0, b1, b2, b3, bb[nn] + ks * 32);
            #pragma unroll
            for (int m = 0; m < MT; m++) {
                mma_f16(acc[m][2 * nn],     a[m], b0, b2);
                mma_f16(acc[m][2 * nn + 1], a[m], b1, b3);
            }
        }
    }
}

// ---------------- cp.async helpers ----------------
__device__ __forceinline__ void cp16(uint32_t dst, const void* src) {
    asm volatile("cp.async.ca.shared.global [%0], [%1], 16;" :: "r"(dst), "l"(src));
}
__device__ __forceinline__ void cp_commit() { asm volatile("cp.async.commit_group;"); }
__device__ __forceinline__ void cp_wait0()  { asm volatile("cp.async.wait_group 0;"); }

// ---------------- weight prep ----------------
__global__ void prep_weights_kernel(const float* __restrict__ qkvw, const float* __restrict__ projw,
                                    const float* __restrict__ fc1w, const float* __restrict__ fc2w) {
    int e4 = blockIdx.x * 256 + threadIdx.x;   // 49152
    const float* src;
    __half* dst;
    int off;
    if (e4 < 12288)      { src = qkvw;  dst = g_qkvw_h;  off = e4; }
    else if (e4 < 16384) { src = projw; dst = g_projw_h; off = e4 - 12288; }
    else if (e4 < 32768) { src = fc1w;  dst = g_fc1w_h;  off = e4 - 16384; }
    else                 { src = fc2w;  dst = g_fc2w_h;  off = e4 - 32768; }
    float4 v = *(const float4*)(src + off * 4);
    *(__half2*)(dst + off * 4)     = __floats2half2_rn(v.x, v.y);
    *(__half2*)(dst + off * 4 + 2) = __floats2half2_rn(v.z, v.w);
}

// ---------------- RPE bias ----------------
__global__ void bias_table_kernel(const float* __restrict__ w1, const float* __restrict__ b1,
                                  const float* __restrict__ w2) {
    __shared__ float4 red[128];
    int p = blockIdx.x;
    int tid = threadIdx.x;
    int i = p / 15, j = p % 15;
    float v0 = (float)(i - 7) / 7.0f * 8.0f;
    float v1 = (float)(j - 7) / 7.0f * 8.0f;
    float inv_l8 = 1.0f / log2f(8.0f);
    float s0 = (v0 > 0.f) ? 1.f : ((v0 < 0.f) ? -1.f : 0.f);
    float s1 = (v1 > 0.f) ? 1.f : ((v1 < 0.f) ? -1.f : 0.f);
    float x0 = s0 * log2f(fabsf(v0) + 1.0f) * inv_l8;
    float x1 = s1 * log2f(fabsf(v1) + 1.0f) * inv_l8;
    float a0 = 0.f, a1 = 0.f, a2 = 0.f, a3 = 0.f;
    #pragma unroll
    for (int r = 0; r < 4; r++) {
        int h = tid + 128 * r;
        float hid = x0 * w1[2 * h] + x1 * w1[2 * h + 1] + b1[h];
        hid = fmaxf(hid, 0.f);
        a0 += hid * w2[0 * RPE_HID + h];
        a1 += hid * w2[1 * RPE_HID + h];
        a2 += hid * w2[2 * RPE_HID + h];
        a3 += hid * w2[3 * RPE_HID + h];
    }
    red[tid] = make_float4(a0, a1, a2, a3);
    __syncthreads();
    for (int s = 64; s > 0; s >>= 1) {
        if (tid < s) {
            float4 o = red[tid + s];
            red[tid].x += o.x; red[tid].y += o.y; red[tid].z += o.z; red[tid].w += o.w;
        }
        __syncthreads();
    }
    if (tid == 0) {
        g_ttab[p * 4 + 0] = red[0].x; g_ttab[p * 4 + 1] = red[0].y;
        g_ttab[p * 4 + 2] = red[0].z; g_ttab[p * 4 + 3] = red[0].w;
    }
}

__global__ void bias_scatter_kernel() {
    int e = blockIdx.x * 256 + threadIdx.x;
    int h = e >> 12;
    int rem = e & 4095;
    int i = rem >> 6, j = rem & 63;
    int yi = i >> 3, xi = i & 7, yj = j >> 3, xj = j & 7;
    int idx = (yi - yj + 7) * 15 + (xi - xj + 7);
    g_bias[e] = g_ttab[idx * 4 + h];
}

// ---------------- Kernel 2: attention + LN1 + residual (unchanged from R10) ----------------
#define AT_XW 0
#define AT_WB 17408
#define AT_QB 52224
#define AT_KB 69632
#define AT_VT 87040
#define AT_PS 105472
#define AT_RG 106496
#define AT_MU 106752
#define AT_RSTD 107008
#define ATTN_SMEM_BYTES 107264

__global__ __launch_bounds__(256, 2) void attn_kernel(
    const float* __restrict__ x, const float* __restrict__ qkv_b,
    const float* __restrict__ proj_b,
    const float* __restrict__ n1w, const float* __restrict__ n1b)
{
    extern __shared__ char smc[];
    __half* xw = (__half*)(smc + AT_XW);
    __half* ow = xw;
    __half* wb = (__half*)(smc + AT_WB);
    __half* qb = (__half*)(smc + AT_QB);
    __half* kb = (__half*)(smc + AT_KB);
    __half* vt = (__half*)(smc + AT_VT);
    float* ps = (float*)(smc + AT_PS);
    int* regid = (int*)(smc + AT_RG);
    float* mu = (float*)(smc + AT_MU);
    float* rstd = (float*)(smc + AT_RSTD);
    float* projf = (float*)(smc + AT_QB);   // overlay, pitch APAD

    int tid = threadIdx.x;
    int wid = tid >> 5;
    int lane = tid & 31;
    int g = lane >> 2;
    int i = lane & 3;

    int bx = blockIdx.x;
    int bimg = bx >> 6;
    int wh = (bx >> 3) & 7, ww = bx & 7;
    const float* xbase = x + (size_t)bimg * (LSEQ * DIM);

    #pragma unroll
    for (int it = 0; it < 8; it++) {
        int e4 = tid + 256 * it;
        int t = e4 >> 5;
        int c = (e4 & 31) << 2;
        int ti = t >> 3, tj = t & 7;
        int hh = (wh * 8 + ti + 4) & 63;
        int wwp = (ww * 8 + tj + 4) & 63;
        float4 v = *(const float4*)(xbase + (size_t)((hh << 6) + wwp) * DIM + c);
        *(__half2*)(xw + t * YPH + c)     = __floats2half2_rn(v.x, v.y);
        *(__half2*)(xw + t * YPH + c + 2) = __floats2half2_rn(v.z, v.w);
    }
    if (tid < 64) {
        int ti = tid >> 3, tj = tid & 7;
        int ah = wh * 8 + ti, aw = ww * 8 + tj;
        int rh = ah < 56 ? 0 : (ah < 60 ? 1 : 2);
        int rw = aw < 56 ? 0 : (aw < 60 ? 1 : 2);
        regid[tid] = rh * 3 + rw;
    }

    const float scale = 0.17677669529663687f;

    for (int cidx = 0; cidx < 3; cidx++) {
        const __half* wsrc = g_qkvw_h + cidx * DIM * DIM;
        #pragma unroll
        for (int it = 0; it < 8; it++) {
            int idx = tid + 256 * it;
            int r = idx >> 4;
            int col = (idx & 15) << 3;
            *(uint4*)(wb + r * YPH + col) = *(const uint4*)(wsrc + r * DIM + col);
        }
        __syncthreads();

        float acc[2][4][4];
        #pragma unroll
        for (int m = 0; m < 2; m++)
            #pragma unroll
            for (int n = 0; n < 4; n++)
                #pragma unroll
                for (int q = 0; q < 4; q++) acc[m][n][q] = 0.f;
        int rbase = (wid >> 2) * 32;
        int nbase = (wid & 3) * 32;
        wgemm_l<2, 4, 8>(xw, YPH, wb, YPH, acc, rbase, nbase, lane);

        #pragma unroll
        for (int n = 0; n < 4; n++) {
            int col = nbase + n * 8 + 2 * i;
            float b0f = qkv_b[cidx * DIM + col];
            float b1f = qkv_b[cidx * DIM + col + 1];
            #pragma unroll
            for (int m = 0; m < 2; m++) {
                int row = rbase + m * 16 + g;
                float v0 = acc[m][n][0] + b0f;
                float v1 = acc[m][n][1] + b1f;
                float v2 = acc[m][n][2] + b0f;
                float v3 = acc[m][n][3] + b1f;
                if (cidx == 0) {
                    *(__half2*)(qb + row * YPH + col)       = __floats2half2_rn(v0 * scale, v1 * scale);
                    *(__half2*)(qb + (row + 8) * YPH + col) = __floats2half2_rn(v2 * scale, v3 * scale);
                } else if (cidx == 1) {
                    *(__half2*)(kb + row * YPH + col)       = __floats2half2_rn(v0, v1);
                    *(__half2*)(kb + (row + 8) * YPH + col) = __floats2half2_rn(v2, v3);
                } else {
                    vt[col * PPH + row]           = __float2half_rn(v0);
                    vt[(col + 1) * PPH + row]     = __float2half_rn(v1);
                    vt[col * PPH + row + 8]       = __float2half_rn(v2);
                    vt[(col + 1) * PPH + row + 8] = __float2half_rn(v3);
                }
            }
        }
        __syncthreads();
    }

    int h = wid >> 1;
    int hoff = h * HD;
    int rbase_h = (wid & 1) * 32;
    uint32_t pr[2][2][8];
    float rsinv[2][2];
    {
        float s[2][8][4];
        #pragma unroll
        for (int m = 0; m < 2; m++)
            #pragma unroll
            for (int n = 0; n < 8; n++)
                #pragma unroll
                for (int q = 0; q < 4; q++) s[m][n][q] = 0.f;
        wgemm_l<2, 8, 2>(qb + hoff, YPH, kb + hoff, YPH, s, rbase_h, 0, lane);

        const float* gb = g_bias + h * 4096;
        int cmask[8][2];
        #pragma unroll
        for (int n = 0; n < 8; n++) {
            cmask[n][0] = regid[n * 8 + 2 * i];
            cmask[n][1] = regid[n * 8 + 2 * i + 1];
        }
        #pragma unroll
        for (int m = 0; m < 2; m++) {
            #pragma unroll
            for (int ss = 0; ss < 2; ss++) {
                int row = rbase_h + m * 16 + 8 * ss + g;
                int rreg = regid[row];
                const float* gbr = gb + row * 64;
                float v[16];
                float mx = -1e30f;
                #pragma unroll
                for (int n = 0; n < 8; n++) {
                    int col = n * 8 + 2 * i;
                    float a0 = s[m][n][2 * ss]     + gbr[col]     + ((rreg != cmask[n][0]) ? -100.f : 0.f);
                    float a1 = s[m][n][2 * ss + 1] + gbr[col + 1] + ((rreg != cmask[n][1]) ? -100.f : 0.f);
                    v[2 * n] = a0; v[2 * n + 1] = a1;
                    mx = fmaxf(mx, fmaxf(a0, a1));
                }
                mx = fmaxf(mx, __shfl_xor_sync(0xFFFFFFFF, mx, 1));
                mx = fmaxf(mx, __shfl_xor_sync(0xFFFFFFFF, mx, 2));
                float sum = 0.f;
                #pragma unroll
                for (int n = 0; n < 8; n++) {
                    float e0 = __expf(v[2 * n] - mx);
                    float e1 = __expf(v[2 * n + 1] - mx);
                    sum += e0 + e1;
                    __half2 hp = __floats2half2_rn(e0, e1);
                    pr[m][ss][n] = *(uint32_t*)&hp;
                }
                sum += __shfl_xor_sync(0xFFFFFFFF, sum, 1);
                sum += __shfl_xor_sync(0xFFFFFFFF, sum, 2);
                rsinv[m][ss] = 1.0f / sum;
            }
        }
    }

    {
        float o[2][4][4];
        #pragma unroll
        for (int m = 0; m < 2; m++)
            #pragma unroll
            for (int n = 0; n < 4; n++)
                #pragma unroll
                for (int q = 0; q < 4; q++) o[m][n][q] = 0.f;
        const __half* Vb = vt + hoff * PPH;
        int lr = lane & 15;
        int lk = (lane >> 4) << 3;
        uint32_t bb[2];
        #pragma unroll
        for (int nn = 0; nn < 2; nn++)
            bb[nn] = (uint32_t)__cvta_generic_to_shared(Vb + (nn * 16 + lr) * PPH + lk);
        #pragma unroll
        for (int ks = 0; ks < 4; ks++) {
            uint32_t a[2][4];
            #pragma unroll
            for (int m = 0; m < 2; m++) {
                a[m][0] = pr[m][0][2 * ks];
                a[m][1] = pr[m][1][2 * ks];
                a[m][2] = pr[m][0][2 * ks + 1];
                a[m][3] = pr[m][1][2 * ks + 1];
            }
            #pragma unroll
            for (int nn = 0; nn < 2; nn++) {
                uint32_t b0, b1, b2, b3;
                ldsm_x4(b0, b1, b2, b3, bb[nn] + ks * 32);
                #pragma unroll
                for (int m = 0; m < 2; m++) {
                    mma_f16(o[m][2 * nn],     a[m], b0, b2);
                    mma_f16(o[m][2 * nn + 1], a[m], b1, b3);
                }
            }
        }
        #pragma unroll
        for (int m = 0; m < 2; m++) {
            int row = rbase_h + m * 16 + g;
            float rs0 = rsinv[m][0];
            float rs1 = rsinv[m][1];
            #pragma unroll
            for (int n = 0; n < 4; n++) {
                int col = hoff + n * 8 + 2 * i;
                *(__half2*)(ow + row * YPH + col)       = __floats2half2_rn(o[m][n][0] * rs0, o[m][n][1] * rs0);
                *(__half2*)(ow + (row + 8) * YPH + col) = __floats2half2_rn(o[m][n][2] * rs1, o[m][n][3] * rs1);
            }
        }
    }
    __syncthreads();

    #pragma unroll
    for (int it = 0; it < 8; it++) {
        int idx = tid + 256 * it;
        int r = idx >> 4;
        int col = (idx & 15) << 3;
        *(uint4*)(wb + r * YPH + col) = *(const uint4*)(g_projw_h + r * DIM + col);
    }
    __syncthreads();

    {
        float acc[2][4][4];
        #pragma unroll
        for (int m = 0; m < 2; m++)
            #pragma unroll
            for (int n = 0; n < 4; n++)
                #pragma unroll
                for (int q = 0; q < 4; q++) acc[m][n][q] = 0.f;
        int rbase = (wid >> 2) * 32;
        int nbase = (wid & 3) * 32;
        wgemm_l<2, 4, 8>(ow, YPH, wb, YPH, acc, rbase, nbase, lane);
        #pragma unroll
        for (int n = 0; n < 4; n++) {
            int col = nbase + n * 8 + 2 * i;
            float b0f = proj_b[col];
            float b1f = proj_b[col + 1];
            #pragma unroll
            for (int m = 0; m < 2; m++) {
                int row = rbase + m * 16 + g;
                projf[row * APAD + col]           = acc[m][n][0] + b0f;
                projf[row * APAD + col + 1]       = acc[m][n][1] + b1f;
                projf[(row + 8) * APAD + col]     = acc[m][n][2] + b0f;
                projf[(row + 8) * APAD + col + 1] = acc[m][n][3] + b1f;
            }
        }
    }
    __syncthreads();

    {
        int row = tid >> 2;
        int cb = (tid & 3) * 32;
        float s = 0.f;
        #pragma unroll 8
        for (int c = 0; c < 32; c++) s += projf[row * APAD + cb + c];
        ps[tid] = s;
    }
    __syncthreads();
    if (tid < 64) {
        float s = ps[4 * tid] + ps[4 * tid + 1] + ps[4 * tid + 2] + ps[4 * tid + 3];
        mu[tid] = s * (1.0f / DIM);
    }
    __syncthreads();
    {
        int row = tid >> 2;
        int cb = (tid & 3) * 32;
        float m = mu[row];
        float v = 0.f;
        #pragma unroll 8
        for (int c = 0; c < 32; c++) {
            float d = projf[row * APAD + cb + c] - m;
            v += d * d;
        }
        ps[tid] = v;
    }
    __syncthreads();
    if (tid < 64) {
        float v = ps[4 * tid] + ps[4 * tid + 1] + ps[4 * tid + 2] + ps[4 * tid + 3];
        rstd[tid] = rsqrtf(v * (1.0f / DIM) + 1e-5f);
    }
    __syncthreads();

    float* yb = g_ybuf + (size_t)bimg * (LSEQ * DIM);
    #pragma unroll
    for (int it = 0; it < 8; it++) {
        int e4 = tid + 256 * it;
        int t = e4 >> 5;
        int c = (e4 & 31) << 2;
        int ti = t >> 3, tj = t & 7;
        int hh = (wh * 8 + ti + 4) & 63;
        int wwp = (ww * 8 + tj + 4) & 63;
        size_t goff = (size_t)((hh << 6) + wwp) * DIM + c;
        float4 xv = *(const float4*)(xbase + goff);
        float m = mu[t], r = rstd[t];
        float4 o;
        o.x = xv.x + (projf[t * APAD + c + 0] - m) * r * n1w[c + 0] + n1b[c + 0];
        o.y = xv.y + (projf[t * APAD + c + 1] - m) * r * n1w[c + 1] + n1b[c + 1];
        o.z = xv.z + (projf[t * APAD + c + 2] - m) * r * n1w[c + 2] + n1b[c + 2];
        o.w = xv.w + (projf[t * APAD + c + 3] - m) * r * n1w[c + 3] + n1b[c + 3];
        *(float4*)(yb + goff) = o;
    }
}

// ---------------- Kernel 3: MLP + LN2 + residual (fp16 + ldmatrix + cp.async double-buffered W) ----------------
// smem bytes: Yh @0 (34816) | Wa @34816 (34816, W1 chunks) | Wb @69632 (34816, W2 chunks) |
//             Hh @104448 (34816) | stats @139264 (ps 1024 + mu 512 + rs 512)
//             h2 fp32 overlay [128][132] @0 (67584 <= Yh+Wa = 69632) after GEMMs.
#define MLP_SMEM_BYTES 141312

__global__ __launch_bounds__(256) void mlp_kernel(
    const float* __restrict__ fc1b, const float* __restrict__ fc2b,
    const float* __restrict__ n2w, const float* __restrict__ n2b,
    float* __restrict__ out)
{
    extern __shared__ char smc[];
    __half* Yh = (__half*)smc;
    __half* Wa = (__half*)(smc + 34816);
    __half* Wb = (__half*)(smc + 69632);
    __half* Hh = (__half*)(smc + 104448);
    float* ps  = (float*)(smc + 139264);
    float* muv = ps + 256;
    float* rsv = muv + 128;
    float* h2  = (float*)smc;

    uint32_t WaA = (uint32_t)__cvta_generic_to_shared(Wa);
    uint32_t WbA = (uint32_t)__cvta_generic_to_shared(Wb);

    int tid = threadIdx.x;
    int wid = tid >> 5;
    int lane = tid & 31;
    int g = lane >> 2;
    int i = lane & 3;
    int rb = (wid >> 1) * 32;
    int nb = (wid & 1) * 64;

    size_t tok0 = (size_t)blockIdx.x * 128;
    const float* ysrc = g_ybuf + tok0 * DIM;

    // prefetch W1 chunk 0 -> Wa
    #pragma unroll
    for (int it = 0; it < 8; it++) {
        int idx = tid + 256 * it;
        int r = idx >> 4;
        int col = (idx & 15) << 3;
        cp16(WaA + (r * YPH + col) * 2, g_fc1w_h + r * DIM + col);
    }
    cp_commit();

    // load + convert Y
    #pragma unroll
    for (int it = 0; it < 16; it++) {
        int e4 = tid + 256 * it;
        int t = e4 >> 5;
        int c = (e4 & 31) << 2;
        float4 v = *(const float4*)(ysrc + (size_t)t * DIM + c);
        *(__half2*)(Yh + t * YPH + c)     = __floats2half2_rn(v.x, v.y);
        *(__half2*)(Yh + t * YPH + c + 2) = __floats2half2_rn(v.z, v.w);
    }

    float acc2[2][8][4];
    #pragma unroll
    for (int m = 0; m < 2; m++)
        #pragma unroll
        for (int n = 0; n < 8; n++)
            #pragma unroll
            for (int q = 0; q < 4; q++) acc2[m][n][q] = 0.f;

    const float is2 = 0.70710678118654752f;

    for (int hc = 0; hc < 4; hc++) {
        // W1[hc] ready in Wa; also previous GEMM2 (reader of Wb) is complete after this bar
        cp_wait0();
        __syncthreads();

        // prefetch W2[hc] -> Wb (flies during GEMM1)
        #pragma unroll
        for (int it = 0; it < 8; it++) {
            int idx = tid + 256 * it;
            int r = idx >> 4;
            int col = (idx & 15) << 3;
            cp16(WbA + (r * YPH + col) * 2, g_fc2w_h + (size_t)r * 512 + hc * 128 + col);
        }
        cp_commit();

        // GEMM1: H = gelu(Y @ W1c^T + b1)
        float acc1[2][8][4];
        #pragma unroll
        for (int m = 0; m < 2; m++)
            #pragma unroll
            for (int n = 0; n < 8; n++)
                #pragma unroll
                for (int q = 0; q < 4; q++) acc1[m][n][q] = 0.f;
        wgemm_l<2, 8, 8>(Yh, YPH, Wa, YPH, acc1, rb, nb, lane);

        #pragma unroll
        for (int n = 0; n < 8; n++) {
            int col = nb + n * 8 + 2 * i;
            float b0f = fc1b[hc * 128 + col];
            float b1f = fc1b[hc * 128 + col + 1];
            #pragma unroll
            for (int m = 0; m < 2; m++) {
                int row = rb + m * 16 + g;
                float v0 = acc1[m][n][0] + b0f;
                float v1 = acc1[m][n][1] + b1f;
                float v2 = acc1[m][n][2] + b0f;
                float v3 = acc1[m][n][3] + b1f;
                v0 = 0.5f * v0 * (1.0f + erff(v0 * is2));
                v1 = 0.5f * v1 * (1.0f + erff(v1 * is2));
                v2 = 0.5f * v2 * (1.0f + erff(v2 * is2));
                v3 = 0.5f * v3 * (1.0f + erff(v3 * is2));
                *(__half2*)(Hh + row * YPH + col)       = __floats2half2_rn(v0, v1);
                *(__half2*)(Hh + (row + 8) * YPH + col) = __floats2half2_rn(v2, v3);
            }
        }

        // W2[hc] ready + Hh complete + GEMM1 done (Wa free for next prefetch)
        cp_wait0();
        __syncthreads();

        // prefetch W1[hc+1] -> Wa (flies during GEMM2)
        if (hc < 3) {
            const __half* src = g_fc1w_h + (size_t)(hc + 1) * 128 * DIM;
            #pragma unroll
            for (int it = 0; it < 8; it++) {
                int idx = tid + 256 * it;
                int r = idx >> 4;
                int col = (idx & 15) << 3;
                cp16(WaA + (r * YPH + col) * 2, src + r * DIM + col);
            }
            cp_commit();
        }

        // GEMM2: acc2 += H @ W2c^T
        wgemm_l<2, 8, 8>(Hh, YPH, Wb, YPH, acc2, rb, nb, lane);
    }

    __syncthreads();
    #pragma unroll
    for (int n = 0; n < 8; n++) {
        int col = nb + n * 8 + 2 * i;
        float b0f = fc2b[col];
        float b1f = fc2b[col + 1];
        #pragma unroll
        for (int m = 0; m < 2; m++) {
            int row = rb + m * 16 + g;
            h2[row * APAD + col]           = acc2[m][n][0] + b0f;
            h2[row * APAD + col + 1]       = acc2[m][n][1] + b1f;
            h2[(row + 8) * APAD + col]     = acc2[m][n][2] + b0f;
            h2[(row + 8) * APAD + col + 1] = acc2[m][n][3] + b1f;
        }
    }
    __syncthreads();

    {
        int row = tid >> 1;
        int cb = (tid & 1) * 64;
        float s = 0.f;
        #pragma unroll 8
        for (int c = 0; c < 64; c++) s += h2[row * APAD + cb + c];
        ps[tid] = s;
    }
    __syncthreads();
    if (tid < 128) muv[tid] = (ps[2 * tid] + ps[2 * tid + 1]) * (1.0f / DIM);
    __syncthreads();
    {
        int row = tid >> 1;
        int cb = (tid & 1) * 64;
        float m = muv[row];
        float v = 0.f;
        #pragma unroll 8
        for (int c = 0; c < 64; c++) {
            float d = h2[row * APAD + cb + c] - m;
            v += d * d;
        }
        ps[tid] = v;
    }
    __syncthreads();
    if (tid < 128) rsv[tid] = rsqrtf((ps[2 * tid] + ps[2 * tid + 1]) * (1.0f / DIM) + 1e-5f);
    __syncthreads();

    float* od = out + tok0 * DIM;
    #pragma unroll
    for (int it = 0; it < 16; it++) {
        int e4 = tid + 256 * it;
        int t = e4 >> 5;
        int c = (e4 & 31) << 2;
        float4 yv = *(const float4*)(ysrc + (size_t)t * DIM + c);
        float m = muv[t], r = rsv[t];
        float4 o;
        o.x = yv.x + (h2[t * APAD + c + 0] - m) * r * n2w[c + 0] + n2b[c + 0];
        o.y = yv.y + (h2[t * APAD + c + 1] - m) * r * n2w[c + 1] + n2b[c + 1];
        o.z = yv.z + (h2[t * APAD + c + 2] - m) * r * n2w[c + 2] + n2b[c + 2];
        o.w = yv.w + (h2[t * APAD + c + 3] - m) * r * n2w[c + 3] + n2b[c + 3];
        *(float4*)(od + (size_t)t * DIM + c) = o;
    }
}

extern "C" void kernel_launch(void* const* d_in, const int* in_sizes, int n_in,
                              void* d_out, int out_size) {
    const float* x      = (const float*)d_in[0];
    const float* qkv_w  = (const float*)d_in[1];
    const float* qkv_b  = (const float*)d_in[2];
    const float* proj_w = (const float*)d_in[3];
    const float* proj_b = (const float*)d_in[4];
    const float* rpe_w1 = (const float*)d_in[5];
    const float* rpe_b1 = (const float*)d_in[6];
    const float* rpe_w2 = (const float*)d_in[7];
    const float* n1w    = (const float*)d_in[8];
    const float* n1b    = (const float*)d_in[9];
    const float* fc1w   = (const float*)d_in[10];
    const float* fc1b   = (const float*)d_in[11];
    const float* fc2w   = (const float*)d_in[12];
    const float* fc2b   = (const float*)d_in[13];
    const float* n2w    = (const float*)d_in[14];
    const float* n2b    = (const float*)d_in[15];
    float* out = (float*)d_out;

    cudaFuncSetAttribute(attn_kernel, cudaFuncAttributeMaxDynamicSharedMemorySize, ATTN_SMEM_BYTES);
    cudaFuncSetAttribute(mlp_kernel,  cudaFuncAttributeMaxDynamicSharedMemorySize, MLP_SMEM_BYTES);

    prep_weights_kernel<<<192, 256>>>(qkv_w, proj_w, fc1w, fc2w);
    bias_table_kernel<<<225, 128>>>(rpe_w1, rpe_b1, rpe_w2);
    bias_scatter_kernel<<<64, 256>>>();
    attn_kernel<<<2048, 256, ATTN_SMEM_BYTES>>>(x, qkv_b, proj_b, n1w, n1b);
    mlp_kernel<<<1024, 256, MLP_SMEM_BYTES>>>(fc1b, fc2b, n2w, n2b, out);
}

// round 13
// speedup vs baseline: 1.8722x; 1.0348x over previous
#include <cuda_runtime.h>
#include <cuda_fp16.h>
#include <math.h>
#include <stdint.h>

#define WSZ 8
#define NHEAD 4
#define DIM 128
#define NTOK 64
#define HD 32
#define BATCH 32
#define HW 64
#define LSEQ 4096
#define RPE_HID 512
#define APAD 132
#define YPH 136    // fp16 smem pitch (halves)
#define PPH 72     // Vt fp16 pitch (halves)

__device__ float g_bias[NHEAD * NTOK * NTOK];
__device__ float g_ttab[225 * NHEAD];
__device__ float g_ybuf[(size_t)BATCH * LSEQ * DIM];
__device__ __half g_qkvw_h[3 * DIM * DIM];
__device__ __half g_projw_h[DIM * DIM];
__device__ __half g_fc1w_h[512 * DIM];
__device__ __half g_fc2w_h[DIM * 512];

// ---------------- fp16 MMA + ldmatrix helpers ----------------
__device__ __forceinline__ void mma_f16(float* c, const uint32_t* a, uint32_t b0, uint32_t b1) {
    asm volatile(
        "mma.sync.aligned.m16n8k16.row.col.f32.f16.f16.f32 "
        "{%0,%1,%2,%3}, {%4,%5,%6,%7}, {%8,%9}, {%0,%1,%2,%3};"
        : "+f"(c[0]), "+f"(c[1]), "+f"(c[2]), "+f"(c[3])
        : "r"(a[0]), "r"(a[1]), "r"(a[2]), "r"(a[3]), "r"(b0), "r"(b1));
}

__device__ __forceinline__ void ldsm_x4(uint32_t& r0, uint32_t& r1, uint32_t& r2, uint32_t& r3,
                                        uint32_t addr) {
    asm volatile("ldmatrix.sync.aligned.m8n8.x4.shared.b16 {%0,%1,%2,%3}, [%4];"
                 : "=r"(r0), "=r"(r1), "=r"(r2), "=r"(r3) : "r"(addr));
}

template<int MT, int NT, int KS>
__device__ __forceinline__ void wgemm_l(const __half* __restrict__ A, int lda,
                                        const __half* __restrict__ B, int ldb,
                                        float (&acc)[MT][NT][4], int rbase, int nbase, int lane)
{
    int lr = lane & 15;
    int lk = (lane >> 4) << 3;
    uint32_t ab[MT], bb[NT / 2];
    #pragma unroll
    for (int m = 0; m < MT; m++)
        ab[m] = (uint32_t)__cvta_generic_to_shared(A + (rbase + m * 16 + lr) * lda + lk);
    #pragma unroll
    for (int nn = 0; nn < NT / 2; nn++)
        bb[nn] = (uint32_t)__cvta_generic_to_shared(B + (nbase + nn * 16 + lr) * ldb + lk);
    #pragma unroll
    for (int ks = 0; ks < KS; ks++) {
        uint32_t a[MT][4];
        #pragma unroll
        for (int m = 0; m < MT; m++)
            ldsm_x4(a[m][0], a[m][1], a[m][2], a[m][3], ab[m] + ks * 32);
        #pragma unroll
        for (int nn = 0; nn < NT / 2; nn++) {
            uint32_t b0, b1, b2, b3;
            ldsm_x4(b0, b1, b2, b3, bb[nn] + ks * 32);
            #pragma unroll
            for (int m = 0; m < MT; m++) {
                mma_f16(acc[m][2 * nn],     a[m], b0, b2);
                mma_f16(acc[m][2 * nn + 1], a[m], b1, b3);
            }
        }
    }
}

// ---------------- cp.async helpers ----------------
__device__ __forceinline__ void cp16(uint32_t dst, const void* src) {
    asm volatile("cp.async.ca.shared.global [%0], [%1], 16;" :: "r"(dst), "l"(src));
}
__device__ __forceinline__ void cp_commit() { asm volatile("cp.async.commit_group;"); }
__device__ __forceinline__ void cp_wait0()  { asm volatile("cp.async.wait_group 0;"); }

// ---------------- weight prep ----------------
__global__ void prep_weights_kernel(const float* __restrict__ qkvw, const float* __restrict__ projw,
                                    const float* __restrict__ fc1w, const float* __restrict__ fc2w) {
    int e4 = blockIdx.x * 256 + threadIdx.x;   // 49152
    const float* src;
    __half* dst;
    int off;
    if (e4 < 12288)      { src = qkvw;  dst = g_qkvw_h;  off = e4; }
    else if (e4 < 16384) { src = projw; dst = g_projw_h; off = e4 - 12288; }
    else if (e4 < 32768) { src = fc1w;  dst = g_fc1w_h;  off = e4 - 16384; }
    else                 { src = fc2w;  dst = g_fc2w_h;  off = e4 - 32768; }
    float4 v = *(const float4*)(src + off * 4);
    *(__half2*)(dst + off * 4)     = __floats2half2_rn(v.x, v.y);
    *(__half2*)(dst + off * 4 + 2) = __floats2half2_rn(v.z, v.w);
}

// ---------------- RPE bias ----------------
__global__ void bias_table_kernel(const float* __restrict__ w1, const float* __restrict__ b1,
                                  const float* __restrict__ w2) {
    __shared__ float4 red[128];
    int p = blockIdx.x;
    int tid = threadIdx.x;
    int i = p / 15, j = p % 15;
    float v0 = (float)(i - 7) / 7.0f * 8.0f;
    float v1 = (float)(j - 7) / 7.0f * 8.0f;
    float inv_l8 = 1.0f / log2f(8.0f);
    float s0 = (v0 > 0.f) ? 1.f : ((v0 < 0.f) ? -1.f : 0.f);
    float s1 = (v1 > 0.f) ? 1.f : ((v1 < 0.f) ? -1.f : 0.f);
    float x0 = s0 * log2f(fabsf(v0) + 1.0f) * inv_l8;
    float x1 = s1 * log2f(fabsf(v1) + 1.0f) * inv_l8;
    float a0 = 0.f, a1 = 0.f, a2 = 0.f, a3 = 0.f;
    #pragma unroll
    for (int r = 0; r < 4; r++) {
        int h = tid + 128 * r;
        float hid = x0 * w1[2 * h] + x1 * w1[2 * h + 1] + b1[h];
        hid = fmaxf(hid, 0.f);
        a0 += hid * w2[0 * RPE_HID + h];
        a1 += hid * w2[1 * RPE_HID + h];
        a2 += hid * w2[2 * RPE_HID + h];
        a3 += hid * w2[3 * RPE_HID + h];
    }
    red[tid] = make_float4(a0, a1, a2, a3);
    __syncthreads();
    for (int s = 64; s > 0; s >>= 1) {
        if (tid < s) {
            float4 o = red[tid + s];
            red[tid].x += o.x; red[tid].y += o.y; red[tid].z += o.z; red[tid].w += o.w;
        }
        __syncthreads();
    }
    if (tid == 0) {
        g_ttab[p * 4 + 0] = red[0].x; g_ttab[p * 4 + 1] = red[0].y;
        g_ttab[p * 4 + 2] = red[0].z; g_ttab[p * 4 + 3] = red[0].w;
    }
}

__global__ void bias_scatter_kernel() {
    int e = blockIdx.x * 256 + threadIdx.x;
    int h = e >> 12;
    int rem = e & 4095;
    int i = rem >> 6, j = rem & 63;
    int yi = i >> 3, xi = i & 7, yj = j >> 3, xj = j & 7;
    int idx = (yi - yj + 7) * 15 + (xi - xj + 7);
    g_bias[e] = g_ttab[idx * 4 + h];
}

// ---------------- Kernel 2: attention + LN1 + residual (proj_w prefetch hidden under scores/PV) ----------------
#define AT_XW 0
#define AT_WB 17408
#define AT_QB 52224
#define AT_KB 69632
#define AT_VT 87040
#define AT_PS 105472
#define AT_RG 106496
#define AT_MU 106752
#define AT_RSTD 107008
#define ATTN_SMEM_BYTES 107264

__global__ __launch_bounds__(256, 2) void attn_kernel(
    const float* __restrict__ x, const float* __restrict__ qkv_b,
    const float* __restrict__ proj_b,
    const float* __restrict__ n1w, const float* __restrict__ n1b)
{
    extern __shared__ char smc[];
    __half* xw = (__half*)(smc + AT_XW);
    __half* ow = xw;
    __half* wb = (__half*)(smc + AT_WB);
    __half* qb = (__half*)(smc + AT_QB);
    __half* kb = (__half*)(smc + AT_KB);
    __half* vt = (__half*)(smc + AT_VT);
    float* ps = (float*)(smc + AT_PS);
    int* regid = (int*)(smc + AT_RG);
    float* mu = (float*)(smc + AT_MU);
    float* rstd = (float*)(smc + AT_RSTD);
    float* projf = (float*)(smc + AT_QB);   // overlay, pitch APAD

    uint32_t wbA = (uint32_t)__cvta_generic_to_shared(wb);

    int tid = threadIdx.x;
    int wid = tid >> 5;
    int lane = tid & 31;
    int g = lane >> 2;
    int i = lane & 3;

    int bx = blockIdx.x;
    int bimg = bx >> 6;
    int wh = (bx >> 3) & 7, ww = bx & 7;
    const float* xbase = x + (size_t)bimg * (LSEQ * DIM);

    // prefetch QKV chunk 0 -> wb
    #pragma unroll
    for (int it = 0; it < 8; it++) {
        int idx = tid + 256 * it;
        int r = idx >> 4;
        int col = (idx & 15) << 3;
        cp16(wbA + (r * YPH + col) * 2, g_qkvw_h + r * DIM + col);
    }
    cp_commit();

    // ---- load window (rolled -4) -> fp16 ----
    #pragma unroll
    for (int it = 0; it < 8; it++) {
        int e4 = tid + 256 * it;
        int t = e4 >> 5;
        int c = (e4 & 31) << 2;
        int ti = t >> 3, tj = t & 7;
        int hh = (wh * 8 + ti + 4) & 63;
        int wwp = (ww * 8 + tj + 4) & 63;
        float4 v = *(const float4*)(xbase + (size_t)((hh << 6) + wwp) * DIM + c);
        *(__half2*)(xw + t * YPH + c)     = __floats2half2_rn(v.x, v.y);
        *(__half2*)(xw + t * YPH + c + 2) = __floats2half2_rn(v.z, v.w);
    }
    if (tid < 64) {
        int ti = tid >> 3, tj = tid & 7;
        int ah = wh * 8 + ti, aw = ww * 8 + tj;
        int rh = ah < 56 ? 0 : (ah < 60 ? 1 : 2);
        int rw = aw < 56 ? 0 : (aw < 60 ? 1 : 2);
        regid[tid] = rh * 3 + rw;
    }

    const float scale = 0.17677669529663687f;

    // ---- QKV: 3 GEMMs 64x128 k=128, 8 warps 2Mx4N ----
    for (int cidx = 0; cidx < 3; cidx++) {
        cp_wait0();
        __syncthreads();

        float acc[2][4][4];
        #pragma unroll
        for (int m = 0; m < 2; m++)
            #pragma unroll
            for (int n = 0; n < 4; n++)
                #pragma unroll
                for (int q = 0; q < 4; q++) acc[m][n][q] = 0.f;
        int rbase = (wid >> 2) * 32;
        int nbase = (wid & 3) * 32;
        wgemm_l<2, 4, 8>(xw, YPH, wb, YPH, acc, rbase, nbase, lane);
        __syncthreads();   // GEMM reads of wb complete before next prefetch overwrites

        // prefetch next weights (qkv chunk cidx+1, or proj after last chunk)
        {
            const __half* nsrc = (cidx < 2) ? (g_qkvw_h + (cidx + 1) * DIM * DIM) : g_projw_h;
            #pragma unroll
            for (int it = 0; it < 8; it++) {
                int idx = tid + 256 * it;
                int r = idx >> 4;
                int col = (idx & 15) << 3;
                cp16(wbA + (r * YPH + col) * 2, nsrc + r * DIM + col);
            }
            cp_commit();
        }

        #pragma unroll
        for (int n = 0; n < 4; n++) {
            int col = nbase + n * 8 + 2 * i;
            float b0f = qkv_b[cidx * DIM + col];
            float b1f = qkv_b[cidx * DIM + col + 1];
            #pragma unroll
            for (int m = 0; m < 2; m++) {
                int row = rbase + m * 16 + g;
                float v0 = acc[m][n][0] + b0f;
                float v1 = acc[m][n][1] + b1f;
                float v2 = acc[m][n][2] + b0f;
                float v3 = acc[m][n][3] + b1f;
                if (cidx == 0) {
                    *(__half2*)(qb + row * YPH + col)       = __floats2half2_rn(v0 * scale, v1 * scale);
                    *(__half2*)(qb + (row + 8) * YPH + col) = __floats2half2_rn(v2 * scale, v3 * scale);
                } else if (cidx == 1) {
                    *(__half2*)(kb + row * YPH + col)       = __floats2half2_rn(v0, v1);
                    *(__half2*)(kb + (row + 8) * YPH + col) = __floats2half2_rn(v2, v3);
                } else {
                    vt[col * PPH + row]           = __float2half_rn(v0);
                    vt[(col + 1) * PPH + row]     = __float2half_rn(v1);
                    vt[col * PPH + row + 8]       = __float2half_rn(v2);
                    vt[(col + 1) * PPH + row + 8] = __float2half_rn(v3);
                }
            }
        }
        __syncthreads();   // epilogue outputs (qb/kb/vt) visible
    }

    // ---- scores + register softmax + register P (proj_w cp.async in flight) ----
    int h = wid >> 1;
    int hoff = h * HD;
    int rbase_h = (wid & 1) * 32;
    uint32_t pr[2][2][8];
    float rsinv[2][2];
    {
        float s[2][8][4];
        #pragma unroll
        for (int m = 0; m < 2; m++)
            #pragma unroll
            for (int n = 0; n < 8; n++)
                #pragma unroll
                for (int q = 0; q < 4; q++) s[m][n][q] = 0.f;
        wgemm_l<2, 8, 2>(qb + hoff, YPH, kb + hoff, YPH, s, rbase_h, 0, lane);

        const float* gb = g_bias + h * 4096;
        int cmask[8][2];
        #pragma unroll
        for (int n = 0; n < 8; n++) {
            cmask[n][0] = regid[n * 8 + 2 * i];
            cmask[n][1] = regid[n * 8 + 2 * i + 1];
        }
        #pragma unroll
        for (int m = 0; m < 2; m++) {
            #pragma unroll
            for (int ss = 0; ss < 2; ss++) {
                int row = rbase_h + m * 16 + 8 * ss + g;
                int rreg = regid[row];
                const float* gbr = gb + row * 64;
                float v[16];
                float mx = -1e30f;
                #pragma unroll
                for (int n = 0; n < 8; n++) {
                    int col = n * 8 + 2 * i;
                    float a0 = s[m][n][2 * ss]     + gbr[col]     + ((rreg != cmask[n][0]) ? -100.f : 0.f);
                    float a1 = s[m][n][2 * ss + 1] + gbr[col + 1] + ((rreg != cmask[n][1]) ? -100.f : 0.f);
                    v[2 * n] = a0; v[2 * n + 1] = a1;
                    mx = fmaxf(mx, fmaxf(a0, a1));
                }
                mx = fmaxf(mx, __shfl_xor_sync(0xFFFFFFFF, mx, 1));
                mx = fmaxf(mx, __shfl_xor_sync(0xFFFFFFFF, mx, 2));
                float sum = 0.f;
                #pragma unroll
                for (int n = 0; n < 8; n++) {
                    float e0 = __expf(v[2 * n] - mx);
                    float e1 = __expf(v[2 * n + 1] - mx);
                    sum += e0 + e1;
                    __half2 hp = __floats2half2_rn(e0, e1);
                    pr[m][ss][n] = *(uint32_t*)&hp;
                }
                sum += __shfl_xor_sync(0xFFFFFFFF, sum, 1);
                sum += __shfl_xor_sync(0xFFFFFFFF, sum, 2);
                rsinv[m][ss] = 1.0f / sum;
            }
        }
    }

    // ---- PV from register P ----
    {
        float o[2][4][4];
        #pragma unroll
        for (int m = 0; m < 2; m++)
            #pragma unroll
            for (int n = 0; n < 4; n++)
                #pragma unroll
                for (int q = 0; q < 4; q++) o[m][n][q] = 0.f;
        const __half* Vb = vt + hoff * PPH;
        int lr = lane & 15;
        int lk = (lane >> 4) << 3;
        uint32_t bb[2];
        #pragma unroll
        for (int nn = 0; nn < 2; nn++)
            bb[nn] = (uint32_t)__cvta_generic_to_shared(Vb + (nn * 16 + lr) * PPH + lk);
        #pragma unroll
        for (int ks = 0; ks < 4; ks++) {
            uint32_t a[2][4];
            #pragma unroll
            for (int m = 0; m < 2; m++) {
                a[m][0] = pr[m][0][2 * ks];
                a[m][1] = pr[m][1][2 * ks];
                a[m][2] = pr[m][0][2 * ks + 1];
                a[m][3] = pr[m][1][2 * ks + 1];
            }
            #pragma unroll
            for (int nn = 0; nn < 2; nn++) {
                uint32_t b0, b1, b2, b3;
                ldsm_x4(b0, b1, b2, b3, bb[nn] + ks * 32);
                #pragma unroll
                for (int m = 0; m < 2; m++) {
                    mma_f16(o[m][2 * nn],     a[m], b0, b2);
                    mma_f16(o[m][2 * nn + 1], a[m], b1, b3);
                }
            }
        }
        #pragma unroll
        for (int m = 0; m < 2; m++) {
            int row = rbase_h + m * 16 + g;
            float rs0 = rsinv[m][0];
            float rs1 = rsinv[m][1];
            #pragma unroll
            for (int n = 0; n < 4; n++) {
                int col = hoff + n * 8 + 2 * i;
                *(__half2*)(ow + row * YPH + col)       = __floats2half2_rn(o[m][n][0] * rs0, o[m][n][1] * rs0);
                *(__half2*)(ow + (row + 8) * YPH + col) = __floats2half2_rn(o[m][n][2] * rs1, o[m][n][3] * rs1);
            }
        }
    }
    cp_wait0();        // proj_w landed (issued before scores)
    __syncthreads();

    // ---- proj GEMM 64x128 k=128 -> fp32 projf ----
    {
        float acc[2][4][4];
        #pragma unroll
        for (int m = 0; m < 2; m++)
            #pragma unroll
            for (int n = 0; n < 4; n++)
                #pragma unroll
                for (int q = 0; q < 4; q++) acc[m][n][q] = 0.f;
        int rbase = (wid >> 2) * 32;
        int nbase = (wid & 3) * 32;
        wgemm_l<2, 4, 8>(ow, YPH, wb, YPH, acc, rbase, nbase, lane);
        #pragma unroll
        for (int n = 0; n < 4; n++) {
            int col = nbase + n * 8 + 2 * i;
            float b0f = proj_b[col];
            float b1f = proj_b[col + 1];
            #pragma unroll
            for (int m = 0; m < 2; m++) {
                int row = rbase + m * 16 + g;
                projf[row * APAD + col]           = acc[m][n][0] + b0f;
                projf[row * APAD + col + 1]       = acc[m][n][1] + b1f;
                projf[(row + 8) * APAD + col]     = acc[m][n][2] + b0f;
                projf[(row + 8) * APAD + col + 1] = acc[m][n][3] + b1f;
            }
        }
    }
    __syncthreads();

    // ---- LN1 stats: 4 threads/row ----
    {
        int row = tid >> 2;
        int cb = (tid & 3) * 32;
        float s = 0.f;
        #pragma unroll 8
        for (int c = 0; c < 32; c++) s += projf[row * APAD + cb + c];
        ps[tid] = s;
    }
    __syncthreads();
    if (tid < 64) {
        float s = ps[4 * tid] + ps[4 * tid + 1] + ps[4 * tid + 2] + ps[4 * tid + 3];
        mu[tid] = s * (1.0f / DIM);
    }
    __syncthreads();
    {
        int row = tid >> 2;
        int cb = (tid & 3) * 32;
        float m = mu[row];
        float v = 0.f;
        #pragma unroll 8
        for (int c = 0; c < 32; c++) {
            float d = projf[row * APAD + cb + c] - m;
            v += d * d;
        }
        ps[tid] = v;
    }
    __syncthreads();
    if (tid < 64) {
        float v = ps[4 * tid] + ps[4 * tid + 1] + ps[4 * tid + 2] + ps[4 * tid + 3];
        rstd[tid] = rsqrtf(v * (1.0f / DIM) + 1e-5f);
    }
    __syncthreads();

    // ---- y = x + LN(proj) ----
    float* yb = g_ybuf + (size_t)bimg * (LSEQ * DIM);
    #pragma unroll
    for (int it = 0; it < 8; it++) {
        int e4 = tid + 256 * it;
        int t = e4 >> 5;
        int c = (e4 & 31) << 2;
        int ti = t >> 3, tj = t & 7;
        int hh = (wh * 8 + ti + 4) & 63;
        int wwp = (ww * 8 + tj + 4) & 63;
        size_t goff = (size_t)((hh << 6) + wwp) * DIM + c;
        float4 xv = *(const float4*)(xbase + goff);
        float m = mu[t], r = rstd[t];
        float4 o;
        o.x = xv.x + (projf[t * APAD + c + 0] - m) * r * n1w[c + 0] + n1b[c + 0];
        o.y = xv.y + (projf[t * APAD + c + 1] - m) * r * n1w[c + 1] + n1b[c + 1];
        o.z = xv.z + (projf[t * APAD + c + 2] - m) * r * n1w[c + 2] + n1b[c + 2];
        o.w = xv.w + (projf[t * APAD + c + 3] - m) * r * n1w[c + 3] + n1b[c + 3];
        *(float4*)(yb + goff) = o;
    }
}

// ---------------- Kernel 3: MLP + LN2 + residual (512 threads, 4 warps/SMSP, cp.async) ----------------
// smem bytes: Yh @0 (34816) | Wa @34816 (34816) | Wb @69632 (34816) | Hh @104448 (34816) |
//             stats @139264 (ps 512f=2048 + mu 128f + rs 128f)
//             h2 fp32 overlay [128][132] @0 (67584 < 69632).
#define MLP_SMEM_BYTES 142336

__global__ __launch_bounds__(512, 1) void mlp_kernel(
    const float* __restrict__ fc1b, const float* __restrict__ fc2b,
    const float* __restrict__ n2w, const float* __restrict__ n2b,
    float* __restrict__ out)
{
    extern __shared__ char smc[];
    __half* Yh = (__half*)smc;
    __half* Wa = (__half*)(smc + 34816);
    __half* Wb = (__half*)(smc + 69632);
    __half* Hh = (__half*)(smc + 104448);
    float* ps  = (float*)(smc + 139264);
    float* muv = ps + 512;
    float* rsv = muv + 128;
    float* h2  = (float*)smc;

    uint32_t WaA = (uint32_t)__cvta_generic_to_shared(Wa);
    uint32_t WbA = (uint32_t)__cvta_generic_to_shared(Wb);

    int tid = threadIdx.x;
    int wid = tid >> 5;
    int lane = tid & 31;
    int g = lane >> 2;
    int i = lane & 3;
    int rb = (wid >> 2) * 32;     // 4 M-warps
    int nb = (wid & 3) * 32;      // 4 N-warps

    size_t tok0 = (size_t)blockIdx.x * 128;
    const float* ysrc = g_ybuf + tok0 * DIM;

    // prefetch W1 chunk 0 -> Wa
    #pragma unroll
    for (int it = 0; it < 4; it++) {
        int idx = tid + 512 * it;
        int r = idx >> 4;
        int col = (idx & 15) << 3;
        cp16(WaA + (r * YPH + col) * 2, g_fc1w_h + r * DIM + col);
    }
    cp_commit();

    // load + convert Y
    #pragma unroll
    for (int it = 0; it < 8; it++) {
        int e4 = tid + 512 * it;
        int t = e4 >> 5;
        int c = (e4 & 31) << 2;
        float4 v = *(const float4*)(ysrc + (size_t)t * DIM + c);
        *(__half2*)(Yh + t * YPH + c)     = __floats2half2_rn(v.x, v.y);
        *(__half2*)(Yh + t * YPH + c + 2) = __floats2half2_rn(v.z, v.w);
    }

    float acc2[2][4][4];
    #pragma unroll
    for (int m = 0; m < 2; m++)
        #pragma unroll
        for (int n = 0; n < 4; n++)
            #pragma unroll
            for (int q = 0; q < 4; q++) acc2[m][n][q] = 0.f;

    const float is2 = 0.70710678118654752f;

    for (int hc = 0; hc < 4; hc++) {
        cp_wait0();
        __syncthreads();

        // prefetch W2[hc] -> Wb (flies during GEMM1)
        #pragma unroll
        for (int it = 0; it < 4; it++) {
            int idx = tid + 512 * it;
            int r = idx >> 4;
            int col = (idx & 15) << 3;
            cp16(WbA + (r * YPH + col) * 2, g_fc2w_h + (size_t)r * 512 + hc * 128 + col);
        }
        cp_commit();

        // GEMM1: H = gelu(Y @ W1c^T + b1)
        float acc1[2][4][4];
        #pragma unroll
        for (int m = 0; m < 2; m++)
            #pragma unroll
            for (int n = 0; n < 4; n++)
                #pragma unroll
                for (int q = 0; q < 4; q++) acc1[m][n][q] = 0.f;
        wgemm_l<2, 4, 8>(Yh, YPH, Wa, YPH, acc1, rb, nb, lane);

        #pragma unroll
        for (int n = 0; n < 4; n++) {
            int col = nb + n * 8 + 2 * i;
            float b0f = fc1b[hc * 128 + col];
            float b1f = fc1b[hc * 128 + col + 1];
            #pragma unroll
            for (int m = 0; m < 2; m++) {
                int row = rb + m * 16 + g;
                float v0 = acc1[m][n][0] + b0f;
                float v1 = acc1[m][n][1] + b1f;
                float v2 = acc1[m][n][2] + b0f;
                float v3 = acc1[m][n][3] + b1f;
                v0 = 0.5f * v0 * (1.0f + erff(v0 * is2));
                v1 = 0.5f * v1 * (1.0f + erff(v1 * is2));
                v2 = 0.5f * v2 * (1.0f + erff(v2 * is2));
                v3 = 0.5f * v3 * (1.0f + erff(v3 * is2));
                *(__half2*)(Hh + row * YPH + col)       = __floats2half2_rn(v0, v1);
                *(__half2*)(Hh + (row + 8) * YPH + col) = __floats2half2_rn(v2, v3);
            }
        }

        cp_wait0();
        __syncthreads();

        // prefetch W1[hc+1] -> Wa (flies during GEMM2)
        if (hc < 3) {
            const __half* src = g_fc1w_h + (size_t)(hc + 1) * 128 * DIM;
            #pragma unroll
            for (int it = 0; it < 4; it++) {
                int idx = tid + 512 * it;
                int r = idx >> 4;
                int col = (idx & 15) << 3;
                cp16(WaA + (r * YPH + col) * 2, src + r * DIM + col);
            }
            cp_commit();
        }

        // GEMM2: acc2 += H @ W2c^T
        wgemm_l<2, 4, 8>(Hh, YPH, Wb, YPH, acc2, rb, nb, lane);
    }

    __syncthreads();
    #pragma unroll
    for (int n = 0; n < 4; n++) {
        int col = nb + n * 8 + 2 * i;
        float b0f = fc2b[col];
        float b1f = fc2b[col + 1];
        #pragma unroll
        for (int m = 0; m < 2; m++) {
            int row = rb + m * 16 + g;
            h2[row * APAD + col]           = acc2[m][n][0] + b0f;
            h2[row * APAD + col + 1]       = acc2[m][n][1] + b1f;
            h2[(row + 8) * APAD + col]     = acc2[m][n][2] + b0f;
            h2[(row + 8) * APAD + col + 1] = acc2[m][n][3] + b1f;
        }
    }
    __syncthreads();

    // LN2 stats: 4 threads/row
    {
        int row = tid >> 2;
        int cb = (tid & 3) * 32;
        float s = 0.f;
        #pragma unroll 8
        for (int c = 0; c < 32; c++) s += h2[row * APAD + cb + c];
        ps[tid] = s;
    }
    __syncthreads();
    if (tid < 128) {
        float s = ps[4 * tid] + ps[4 * tid + 1] + ps[4 * tid + 2] + ps[4 * tid + 3];
        muv[tid] = s * (1.0f / DIM);
    }
    __syncthreads();
    {
        int row = tid >> 2;
        int cb = (tid & 3) * 32;
        float m = muv[row];
        float v = 0.f;
        #pragma unroll 8
        for (int c = 0; c < 32; c++) {
            float d = h2[row * APAD + cb + c] - m;
            v += d * d;
        }
        ps[tid] = v;
    }
    __syncthreads();
    if (tid < 128) {
        float v = ps[4 * tid] + ps[4 * tid + 1] + ps[4 * tid + 2] + ps[4 * tid + 3];
        rsv[tid] = rsqrtf(v * (1.0f / DIM) + 1e-5f);
    }
    __syncthreads();

    float* od = out + tok0 * DIM;
    #pragma unroll
    for (int it = 0; it < 8; it++) {
        int e4 = tid + 512 * it;
        int t = e4 >> 5;
        int c = (e4 & 31) << 2;
        float4 yv = *(const float4*)(ysrc + (size_t)t * DIM + c);
        float m = muv[t], r = rsv[t];
        float4 o;
        o.x = yv.x + (h2[t * APAD + c + 0] - m) * r * n2w[c + 0] + n2b[c + 0];
        o.y = yv.y + (h2[t * APAD + c + 1] - m) * r * n2w[c + 1] + n2b[c + 1];
        o.z = yv.z + (h2[t * APAD + c + 2] - m) * r * n2w[c + 2] + n2b[c + 2];
        o.w = yv.w + (h2[t * APAD + c + 3] - m) * r * n2w[c + 3] + n2b[c + 3];
        *(float4*)(od + (size_t)t * DIM + c) = o;
    }
}

extern "C" void kernel_launch(void* const* d_in, const int* in_sizes, int n_in,
                              void* d_out, int out_size) {
    const float* x      = (const float*)d_in[0];
    const float* qkv_w  = (const float*)d_in[1];
    const float* qkv_b  = (const float*)d_in[2];
    const float* proj_w = (const float*)d_in[3];
    const float* proj_b = (const float*)d_in[4];
    const float* rpe_w1 = (const float*)d_in[5];
    const float* rpe_b1 = (const float*)d_in[6];
    const float* rpe_w2 = (const float*)d_in[7];
    const float* n1w    = (const float*)d_in[8];
    const float* n1b    = (const float*)d_in[9];
    const float* fc1w   = (const float*)d_in[10];
    const float* fc1b   = (const float*)d_in[11];
    const float* fc2w   = (const float*)d_in[12];
    const float* fc2b   = (const float*)d_in[13];
    const float* n2w    = (const float*)d_in[14];
    const float* n2b    = (const float*)d_in[15];
    float* out = (float*)d_out;

    cudaFuncSetAttribute(attn_kernel, cudaFuncAttributeMaxDynamicSharedMemorySize, ATTN_SMEM_BYTES);
    cudaFuncSetAttribute(mlp_kernel,  cudaFuncAttributeMaxDynamicSharedMemorySize, MLP_SMEM_BYTES);

    prep_weights_kernel<<<192, 256>>>(qkv_w, proj_w, fc1w, fc2w);
    bias_table_kernel<<<225, 128>>>(rpe_w1, rpe_b1, rpe_w2);
    bias_scatter_kernel<<<64, 256>>>();
    attn_kernel<<<2048, 256, ATTN_SMEM_BYTES>>>(x, qkv_b, proj_b, n1w, n1b);
    mlp_kernel<<<1024, 512, MLP_SMEM_BYTES>>>(fc1b, fc2b, n2w, n2b, out);
}